// round 1
// baseline (speedup 1.0000x reference)
#include <cuda_runtime.h>
#include <math.h>

// ---------------- problem constants ----------------
#define S_LEN 2048
#define HID   3584
#define NH    28
#define NKV   4
#define HD    128
#define NQD   (NH*HD)    // 3584
#define NKD   (NKV*HD)   // 512
#define GRP   (NH/NKV)   // 7

// ---------------- scratch (device globals; no allocs allowed) ----------------
__device__ float g_q[S_LEN * NQD];
__device__ float g_k[S_LEN * NKD];
__device__ float g_v[S_LEN * NKD];
__device__ float g_ctx[S_LEN * NQD];

// ---------------- GEMM: C[M,N] = A[M,K] @ W[K,N] + bias ----------------
// 64x64 tile, BK=16, 256 threads, 4x4 microtile per thread.
#define BM 64
#define BN 64
#define BK 16

__global__ __launch_bounds__(256)
void gemm_bias_kernel(const float* __restrict__ A, const float* __restrict__ W,
                      const float* __restrict__ bias, float* __restrict__ C,
                      int M, int N, int K) {
    __shared__ float As[BK][BM];
    __shared__ float Ws[BK][BN];

    const int tid = threadIdx.x;
    const int tx = tid & 15;        // 0..15
    const int ty = tid >> 4;        // 0..15
    const int rowBase = blockIdx.y * BM;
    const int colBase = blockIdx.x * BN;

    // A load: thread -> (m = tid/4, k4 = (tid%4)*4)
    const int a_m = tid >> 2;
    const int a_k = (tid & 3) << 2;
    // W load: thread -> (k = tid/16, n4 = (tid%16)*4)
    const int w_k = tid >> 4;
    const int w_n = (tid & 15) << 2;

    float acc[4][4];
#pragma unroll
    for (int i = 0; i < 4; i++)
#pragma unroll
        for (int j = 0; j < 4; j++) acc[i][j] = 0.f;

    for (int kb = 0; kb < K; kb += BK) {
        float4 av = *(const float4*)(A + (size_t)(rowBase + a_m) * K + kb + a_k);
        As[a_k + 0][a_m] = av.x;
        As[a_k + 1][a_m] = av.y;
        As[a_k + 2][a_m] = av.z;
        As[a_k + 3][a_m] = av.w;
        float4 wv = *(const float4*)(W + (size_t)(kb + w_k) * N + colBase + w_n);
        *(float4*)&Ws[w_k][w_n] = wv;
        __syncthreads();

#pragma unroll
        for (int kk = 0; kk < BK; kk++) {
            float4 a = *(const float4*)&As[kk][ty << 2];
            float4 w = *(const float4*)&Ws[kk][tx << 2];
            acc[0][0] += a.x * w.x; acc[0][1] += a.x * w.y; acc[0][2] += a.x * w.z; acc[0][3] += a.x * w.w;
            acc[1][0] += a.y * w.x; acc[1][1] += a.y * w.y; acc[1][2] += a.y * w.z; acc[1][3] += a.y * w.w;
            acc[2][0] += a.z * w.x; acc[2][1] += a.z * w.y; acc[2][2] += a.z * w.z; acc[2][3] += a.z * w.w;
            acc[3][0] += a.w * w.x; acc[3][1] += a.w * w.y; acc[3][2] += a.w * w.z; acc[3][3] += a.w * w.w;
        }
        __syncthreads();
    }

#pragma unroll
    for (int i = 0; i < 4; i++) {
        int row = rowBase + (ty << 2) + i;
#pragma unroll
        for (int j = 0; j < 4; j++) {
            int col = colBase + (tx << 2) + j;
            float b = bias ? bias[col] : 0.f;
            C[(size_t)row * N + col] = acc[i][j] + b;
        }
    }
}

// ---------------- mROPE (in-place on q and k) ----------------
// cos/sin: [3][S][HD]. section map: d%64 in [0,16)->0, [16,40)->1, [40,64)->2
__global__ void rope_kernel(float* __restrict__ q, float* __restrict__ k,
                            const float* __restrict__ cosp, const float* __restrict__ sinp) {
    const int s = blockIdx.x;      // 0..2047
    const int d = threadIdx.x;     // 0..63 (pair index)
    const int d2 = d + 64;
    const int sec = (d < 16) ? 0 : ((d < 40) ? 1 : 2);
    const int SH = S_LEN * HD;

    const float c1 = cosp[sec * SH + s * HD + d];
    const float s1 = sinp[sec * SH + s * HD + d];
    const float c2 = cosp[sec * SH + s * HD + d2];
    const float s2 = sinp[sec * SH + s * HD + d2];

#pragma unroll 1
    for (int hh = 0; hh < NH + NKV; hh++) {
        float* base = (hh < NH) ? (q + (size_t)s * NQD + hh * HD)
                                : (k + (size_t)s * NKD + (hh - NH) * HD);
        float x1 = base[d];
        float x2 = base[d2];
        base[d]  = x1 * c1 - x2 * s1;
        base[d2] = x2 * c2 + x1 * s2;
    }
}

// ---------------- attention: flash-style, fp32 ----------------
// grid = (S/64, NH). block = 256 (8 warps x 8 q-rows each).
// smem: Qs[64][128] | Kt[128][65] (transposed, padded) | Vs[64][128]
#define AT_BM 64
#define AT_BN 64
#define ATTN_SMEM_FLOATS (AT_BM*HD + HD*65 + AT_BN*HD)

__global__ __launch_bounds__(256, 2)
void attn_kernel(const float* __restrict__ q, const float* __restrict__ k,
                 const float* __restrict__ v, float* __restrict__ ctx) {
    extern __shared__ float sm[];
    float* Qs = sm;                       // [64][128]
    float* Kt = Qs + AT_BM * HD;          // [128][65]
    float* Vs = Kt + HD * 65;             // [64][128]

    const int h = blockIdx.y;             // 0..27
    const int kvh = h / GRP;
    const int r0 = blockIdx.x * AT_BM;
    const int tid = threadIdx.x;
    const int warp = tid >> 5;
    const int lane = tid & 31;
    const int rowb = warp * 8;            // this warp's first row within the tile

    // load Q tile (coalesced)
    for (int idx = tid; idx < AT_BM * HD; idx += 256) {
        int r = idx >> 7, d = idx & 127;
        Qs[idx] = q[(size_t)(r0 + r) * NQD + h * HD + d];
    }

    float m[8], l[8], o[8][4];
#pragma unroll
    for (int r = 0; r < 8; r++) {
        m[r] = -INFINITY; l[r] = 0.f;
        o[r][0] = o[r][1] = o[r][2] = o[r][3] = 0.f;
    }

    const float scale = 0.08838834764831845f;  // 1/sqrt(128)

    for (int kt = 0; kt < S_LEN; kt += AT_BN) {
        __syncthreads();   // protect Kt/Vs/Qs across iterations (and Q load on iter 0)
        // load K transposed: Kt[d][key], padded stride 65
        for (int idx = tid; idx < AT_BN * HD; idx += 256) {
            int key = idx >> 7, d = idx & 127;
            Kt[d * 65 + key] = k[(size_t)(kt + key) * NKD + kvh * HD + d];
        }
        // load V: Vs[key][d]
        for (int idx = tid; idx < AT_BN * HD; idx += 256) {
            Vs[idx] = v[(size_t)(kt + (idx >> 7)) * NKD + kvh * HD + (idx & 127)];
        }
        __syncthreads();

        // scores: lane handles keys (lane, lane+32) for this warp's 8 rows
        float s0[8], s1[8];
#pragma unroll
        for (int r = 0; r < 8; r++) { s0[r] = 0.f; s1[r] = 0.f; }

        for (int d = 0; d < HD; d++) {
            float k0 = Kt[d * 65 + lane];
            float k1 = Kt[d * 65 + lane + 32];
#pragma unroll
            for (int r = 0; r < 8; r++) {
                float qv = Qs[(rowb + r) * HD + d];
                s0[r] += qv * k0;
                s1[r] += qv * k1;
            }
        }

        // online softmax update
#pragma unroll
        for (int r = 0; r < 8; r++) {
            float a = s0[r] * scale;
            float b = s1[r] * scale;
            float mx = fmaxf(a, b);
#pragma unroll
            for (int off = 16; off; off >>= 1)
                mx = fmaxf(mx, __shfl_xor_sync(0xffffffffu, mx, off));
            float newm = fmaxf(m[r], mx);
            float corr = __expf(m[r] - newm);
            float p0 = __expf(a - newm);
            float p1 = __expf(b - newm);
            float ps = p0 + p1;
#pragma unroll
            for (int off = 16; off; off >>= 1)
                ps += __shfl_xor_sync(0xffffffffu, ps, off);
            l[r] = l[r] * corr + ps;
            m[r] = newm;
            o[r][0] *= corr; o[r][1] *= corr; o[r][2] *= corr; o[r][3] *= corr;
            s0[r] = p0; s1[r] = p1;   // reuse as probabilities
        }

        // PV: lane owns dims [lane*4, lane*4+4)
        for (int key = 0; key < 32; key++) {
            float4 v0 = *(const float4*)&Vs[key * HD + (lane << 2)];
            float4 v1 = *(const float4*)&Vs[(key + 32) * HD + (lane << 2)];
#pragma unroll
            for (int r = 0; r < 8; r++) {
                float p0 = __shfl_sync(0xffffffffu, s0[r], key);
                float p1 = __shfl_sync(0xffffffffu, s1[r], key);
                o[r][0] += p0 * v0.x + p1 * v1.x;
                o[r][1] += p0 * v0.y + p1 * v1.y;
                o[r][2] += p0 * v0.z + p1 * v1.z;
                o[r][3] += p0 * v0.w + p1 * v1.w;
            }
        }
    }

    // write context: ctx[row][h*HD + lane*4 + i]
#pragma unroll
    for (int r = 0; r < 8; r++) {
        float inv = 1.f / l[r];
        size_t base = (size_t)(r0 + rowb + r) * NQD + h * HD + (lane << 2);
        ctx[base + 0] = o[r][0] * inv;
        ctx[base + 1] = o[r][1] * inv;
        ctx[base + 2] = o[r][2] * inv;
        ctx[base + 3] = o[r][3] * inv;
    }
}

// ---------------- launch ----------------
extern "C" void kernel_launch(void* const* d_in, const int* in_sizes, int n_in,
                              void* d_out, int out_size) {
    const float* hs   = (const float*)d_in[0];
    const float* cosp = (const float*)d_in[1];
    const float* sinp = (const float*)d_in[2];
    const float* Wq   = (const float*)d_in[3];
    const float* bq   = (const float*)d_in[4];
    const float* Wk   = (const float*)d_in[5];
    const float* bk   = (const float*)d_in[6];
    const float* Wv   = (const float*)d_in[7];
    const float* bv   = (const float*)d_in[8];
    const float* Wo   = (const float*)d_in[9];
    float* out = (float*)d_out;

    float *q_p, *k_p, *v_p, *ctx_p;
    cudaGetSymbolAddress((void**)&q_p,   g_q);
    cudaGetSymbolAddress((void**)&k_p,   g_k);
    cudaGetSymbolAddress((void**)&v_p,   g_v);
    cudaGetSymbolAddress((void**)&ctx_p, g_ctx);

    const int attn_smem = ATTN_SMEM_FLOATS * (int)sizeof(float);
    cudaFuncSetAttribute(attn_kernel, cudaFuncAttributeMaxDynamicSharedMemorySize, attn_smem);

    // 1) QKV projections
    {
        dim3 grid(NQD / BN, S_LEN / BM);
        gemm_bias_kernel<<<grid, 256>>>(hs, Wq, bq, q_p, S_LEN, NQD, HID);
    }
    {
        dim3 grid(NKD / BN, S_LEN / BM);
        gemm_bias_kernel<<<grid, 256>>>(hs, Wk, bk, k_p, S_LEN, NKD, HID);
        gemm_bias_kernel<<<grid, 256>>>(hs, Wv, bv, v_p, S_LEN, NKD, HID);
    }

    // 2) mROPE on q, k (in place)
    rope_kernel<<<S_LEN, 64>>>(q_p, k_p, cosp, sinp);

    // 3) attention -> ctx
    {
        dim3 grid(S_LEN / AT_BM, NH);
        attn_kernel<<<grid, 256, attn_smem>>>(q_p, k_p, v_p, ctx_p);
    }

    // 4) output projection: out = ctx @ Wo
    {
        dim3 grid(HID / BN, S_LEN / BM);
        gemm_bias_kernel<<<grid, 256>>>(ctx_p, Wo, nullptr, out, S_LEN, HID, NQD);
    }
}

// round 3
// speedup vs baseline: 1.6711x; 1.6711x over previous
#include <cuda_runtime.h>
#include <cuda_bf16.h>
#include <math.h>
#include <stdint.h>

// ---------------- problem constants ----------------
#define S_LEN 2048
#define HID   3584
#define NH    28
#define NKV   4
#define HD    128
#define NQD   (NH*HD)    // 3584
#define NKD   (NKV*HD)   // 512
#define GRP   (NH/NKV)   // 7

// ---------------- scratch (device globals; no allocs allowed) ----------------
__device__ float g_q[S_LEN * NQD];
__device__ float g_k[S_LEN * NKD];
__device__ float g_v[S_LEN * NKD];
__device__ float g_ctx[S_LEN * NQD];

// bf16 hi/lo splits (16B-aligned for cp.async / vector access)
__device__ __align__(16) __nv_bfloat16 g_hsh[S_LEN * HID],  g_hsl[S_LEN * HID];
__device__ __align__(16) __nv_bfloat16 g_ctxh[S_LEN * NQD], g_ctxl[S_LEN * NQD];
// transposed weights [N, K]
__device__ __align__(16) __nv_bfloat16 g_wqh[(size_t)NQD * HID], g_wql[(size_t)NQD * HID];
__device__ __align__(16) __nv_bfloat16 g_wkh[(size_t)NKD * HID], g_wkl[(size_t)NKD * HID];
__device__ __align__(16) __nv_bfloat16 g_wvh[(size_t)NKD * HID], g_wvl[(size_t)NKD * HID];
__device__ __align__(16) __nv_bfloat16 g_woh[(size_t)HID * NQD], g_wol[(size_t)HID * NQD];

// ---------------- helpers ----------------
__device__ __forceinline__ uint32_t smem_u32(const void* p) {
    uint32_t a;
    asm("{ .reg .u64 t; cvta.to.shared.u64 t, %1; cvt.u32.u64 %0, t; }" : "=r"(a) : "l"(p));
    return a;
}

__device__ __forceinline__ void cp_async16(uint32_t dst, const void* src) {
    asm volatile("cp.async.cg.shared.global [%0], [%1], 16;" :: "r"(dst), "l"(src) : "memory");
}

__device__ __forceinline__ void ldm_x4(uint32_t* r, uint32_t addr) {
    asm volatile("ldmatrix.sync.aligned.m8n8.x4.shared.b16 {%0,%1,%2,%3}, [%4];"
                 : "=r"(r[0]), "=r"(r[1]), "=r"(r[2]), "=r"(r[3]) : "r"(addr));
}

__device__ __forceinline__ void ldm_x2(uint32_t* r, uint32_t addr) {
    asm volatile("ldmatrix.sync.aligned.m8n8.x2.shared.b16 {%0,%1}, [%2];"
                 : "=r"(r[0]), "=r"(r[1]) : "r"(addr));
}

__device__ __forceinline__ void mma_bf16(float* c, const uint32_t* a, const uint32_t* b) {
    asm volatile(
        "mma.sync.aligned.m16n8k16.row.col.f32.bf16.bf16.f32 "
        "{%0,%1,%2,%3}, {%4,%5,%6,%7}, {%8,%9}, {%0,%1,%2,%3};"
        : "+f"(c[0]), "+f"(c[1]), "+f"(c[2]), "+f"(c[3])
        : "r"(a[0]), "r"(a[1]), "r"(a[2]), "r"(a[3]), "r"(b[0]), "r"(b[1]));
}

// ---------------- split kernels ----------------
__global__ void split_kernel(const float4* __restrict__ X, __nv_bfloat162* __restrict__ H,
                             __nv_bfloat162* __restrict__ L, int n4) {
    int i = blockIdx.x * 256 + threadIdx.x;
    if (i >= n4) return;
    float4 x = X[i];
    __nv_bfloat16 h0 = __float2bfloat16(x.x), h1 = __float2bfloat16(x.y);
    __nv_bfloat16 h2 = __float2bfloat16(x.z), h3 = __float2bfloat16(x.w);
    H[2*i]   = __halves2bfloat162(h0, h1);
    H[2*i+1] = __halves2bfloat162(h2, h3);
    L[2*i]   = __halves2bfloat162(__float2bfloat16(x.x - __bfloat162float(h0)),
                                  __float2bfloat16(x.y - __bfloat162float(h1)));
    L[2*i+1] = __halves2bfloat162(__float2bfloat16(x.z - __bfloat162float(h2)),
                                  __float2bfloat16(x.w - __bfloat162float(h3)));
}

// W [K, N] row-major -> Th/Tl [N, K]
__global__ void tsplit_kernel(const float* __restrict__ W, __nv_bfloat16* __restrict__ Th,
                              __nv_bfloat16* __restrict__ Tl, int K, int N) {
    __shared__ float t[32][33];
    int n0 = blockIdx.x * 32, k0 = blockIdx.y * 32;
    int tx = threadIdx.x, ty = threadIdx.y;   // 32 x 8
#pragma unroll
    for (int i = 0; i < 4; i++) {
        int k = k0 + ty + i * 8;
        t[ty + i * 8][tx] = W[(size_t)k * N + n0 + tx];
    }
    __syncthreads();
#pragma unroll
    for (int i = 0; i < 4; i++) {
        int n = n0 + ty + i * 8;
        float v = t[tx][ty + i * 8];
        __nv_bfloat16 h = __float2bfloat16(v);
        Th[(size_t)n * K + k0 + tx] = h;
        Tl[(size_t)n * K + k0 + tx] = __float2bfloat16(v - __bfloat162float(h));
    }
}

// ---------------- mma.sync GEMM ----------------
// C[M,Ntot](fp32) = Ah/Al[M,K] x (Bh/Bl[Ntot,K])^T + bias
// CTA tile 128x128, BK=32, 8 warps (2m x 4n), each warp 64x32.
// smem tile: [128][40] bf16 per operand (pad 32->40, 80B rows, conflict-free ldmatrix)
#define GBK 32
#define ROWP 40
#define STG_TILE 10240                 // 128*40*2 bytes per operand tile
#define STG_BYTES (4*STG_TILE)         // 40KB per stage
#define GEMM_SMEM (2*STG_BYTES)        // 80KB

__global__ __launch_bounds__(256)
void gemm_mma(const __nv_bfloat16* __restrict__ Ah, const __nv_bfloat16* __restrict__ Al,
              const __nv_bfloat16* __restrict__ Bh, const __nv_bfloat16* __restrict__ Bl,
              const float* __restrict__ bias, float* __restrict__ C, int K, int Ntot) {
    extern __shared__ char smem[];
    const uint32_t sb = smem_u32(smem);
    const int tid = threadIdx.x;
    const int lane = tid & 31;
    const int warp = tid >> 5;
    const int wm = (warp >> 2) * 64;    // warp m offset in CTA tile
    const int wn = (warp & 3) * 32;     // warp n offset
    const int row0 = blockIdx.y * 128;
    const int col0 = blockIdx.x * 128;
    const int NI = K / GBK;

    float acc[4][4][4];
#pragma unroll
    for (int mt = 0; mt < 4; mt++)
#pragma unroll
        for (int nt = 0; nt < 4; nt++)
#pragma unroll
            for (int i = 0; i < 4; i++) acc[mt][nt][i] = 0.f;

    // ---- async load of one stage ----
    auto issue_load = [&](int stage, int kb) {
        uint32_t sbase = sb + stage * STG_BYTES;
#pragma unroll
        for (int tile = 0; tile < 4; tile++) {
            const __nv_bfloat16* src =
                (tile == 0) ? Ah : (tile == 1) ? Al : (tile == 2) ? Bh : Bl;
            int gbase = (tile < 2) ? row0 : col0;
#pragma unroll
            for (int j = 0; j < 2; j++) {
                int s = j * 256 + tid;          // 0..511
                int row = s >> 2;               // 0..127
                int c = (s & 3) << 3;           // 0,8,16,24 (bf16)
                const void* g = src + (size_t)(gbase + row) * K + kb + c;
                uint32_t dst = sbase + tile * STG_TILE + (row * ROWP + c) * 2;
                cp_async16(dst, g);
            }
        }
        asm volatile("cp.async.commit_group;" ::: "memory");
    };

    issue_load(0, 0);

    for (int i = 0; i < NI; i++) {
        if (i + 1 < NI) {
            issue_load((i + 1) & 1, (i + 1) * GBK);
            asm volatile("cp.async.wait_group 1;" ::: "memory");
        } else {
            asm volatile("cp.async.wait_group 0;" ::: "memory");
        }
        __syncthreads();

        const uint32_t sa = sb + (i & 1) * STG_BYTES;
#pragma unroll
        for (int ks = 0; ks < 2; ks++) {
            uint32_t bh[4][2], bl[4][2];
#pragma unroll
            for (int nt = 0; nt < 4; nt++) {
                uint32_t addr = sa + 2 * STG_TILE +
                    ((wn + nt * 8 + (lane & 7)) * ROWP + ks * 16 + (((lane >> 3) & 1) << 3)) * 2;
                ldm_x2(bh[nt], addr);
                ldm_x2(bl[nt], addr + STG_TILE);
            }
#pragma unroll
            for (int mt = 0; mt < 4; mt++) {
                uint32_t ah[4], al[4];
                uint32_t addr = sa +
                    ((wm + mt * 16 + (lane & 15)) * ROWP + ks * 16 + ((lane >> 4) << 3)) * 2;
                ldm_x4(ah, addr);
                ldm_x4(al, addr + STG_TILE);
#pragma unroll
                for (int nt = 0; nt < 4; nt++) {
                    mma_bf16(acc[mt][nt], ah, bh[nt]);
                    mma_bf16(acc[mt][nt], ah, bl[nt]);
                    mma_bf16(acc[mt][nt], al, bh[nt]);
                }
            }
        }
        __syncthreads();
    }

    // ---- epilogue ----
#pragma unroll
    for (int mt = 0; mt < 4; mt++) {
#pragma unroll
        for (int nt = 0; nt < 4; nt++) {
            int r = row0 + wm + mt * 16 + (lane >> 2);
            int cidx = col0 + wn + nt * 8 + ((lane & 3) << 1);
            float b0 = 0.f, b1 = 0.f;
            if (bias) { b0 = bias[cidx]; b1 = bias[cidx + 1]; }
            float2* p0 = (float2*)(C + (size_t)r * Ntot + cidx);
            float2* p1 = (float2*)(C + (size_t)(r + 8) * Ntot + cidx);
            *p0 = make_float2(acc[mt][nt][0] + b0, acc[mt][nt][1] + b1);
            *p1 = make_float2(acc[mt][nt][2] + b0, acc[mt][nt][3] + b1);
        }
    }
}

// ---------------- mROPE (in-place on q and k) ----------------
__global__ void rope_kernel(float* __restrict__ q, float* __restrict__ k,
                            const float* __restrict__ cosp, const float* __restrict__ sinp) {
    const int s = blockIdx.x;
    const int d = threadIdx.x;     // 0..63
    const int d2 = d + 64;
    const int sec = (d < 16) ? 0 : ((d < 40) ? 1 : 2);
    const int SH = S_LEN * HD;

    const float c1 = cosp[sec * SH + s * HD + d];
    const float s1 = sinp[sec * SH + s * HD + d];
    const float c2 = cosp[sec * SH + s * HD + d2];
    const float s2 = sinp[sec * SH + s * HD + d2];

#pragma unroll 1
    for (int hh = 0; hh < NH + NKV; hh++) {
        float* base = (hh < NH) ? (q + (size_t)s * NQD + hh * HD)
                                : (k + (size_t)s * NKD + (hh - NH) * HD);
        float x1 = base[d];
        float x2 = base[d2];
        base[d]  = x1 * c1 - x2 * s1;
        base[d2] = x2 * c2 + x1 * s2;
    }
}

// ---------------- attention: flash-style, fp32 (unchanged from R1) ----------------
#define AT_BM 64
#define AT_BN 64
#define ATTN_SMEM_FLOATS (AT_BM*HD + HD*65 + AT_BN*HD)

__global__ __launch_bounds__(256, 2)
void attn_kernel(const float* __restrict__ q, const float* __restrict__ k,
                 const float* __restrict__ v, float* __restrict__ ctx) {
    extern __shared__ float sm[];
    float* Qs = sm;
    float* Kt = Qs + AT_BM * HD;
    float* Vs = Kt + HD * 65;

    const int h = blockIdx.y;
    const int kvh = h / GRP;
    const int r0 = blockIdx.x * AT_BM;
    const int tid = threadIdx.x;
    const int warp = tid >> 5;
    const int lane = tid & 31;
    const int rowb = warp * 8;

    for (int idx = tid; idx < AT_BM * HD; idx += 256) {
        int r = idx >> 7, d = idx & 127;
        Qs[idx] = q[(size_t)(r0 + r) * NQD + h * HD + d];
    }

    float m[8], l[8], o[8][4];
#pragma unroll
    for (int r = 0; r < 8; r++) {
        m[r] = -INFINITY; l[r] = 0.f;
        o[r][0] = o[r][1] = o[r][2] = o[r][3] = 0.f;
    }

    const float scale = 0.08838834764831845f;

    for (int kt = 0; kt < S_LEN; kt += AT_BN) {
        __syncthreads();
        for (int idx = tid; idx < AT_BN * HD; idx += 256) {
            int key = idx >> 7, d = idx & 127;
            Kt[d * 65 + key] = k[(size_t)(kt + key) * NKD + kvh * HD + d];
        }
        for (int idx = tid; idx < AT_BN * HD; idx += 256) {
            Vs[idx] = v[(size_t)(kt + (idx >> 7)) * NKD + kvh * HD + (idx & 127)];
        }
        __syncthreads();

        float s0[8], s1[8];
#pragma unroll
        for (int r = 0; r < 8; r++) { s0[r] = 0.f; s1[r] = 0.f; }

        for (int d = 0; d < HD; d++) {
            float k0 = Kt[d * 65 + lane];
            float k1 = Kt[d * 65 + lane + 32];
#pragma unroll
            for (int r = 0; r < 8; r++) {
                float qv = Qs[(rowb + r) * HD + d];
                s0[r] += qv * k0;
                s1[r] += qv * k1;
            }
        }

#pragma unroll
        for (int r = 0; r < 8; r++) {
            float a = s0[r] * scale;
            float b = s1[r] * scale;
            float mx = fmaxf(a, b);
#pragma unroll
            for (int off = 16; off; off >>= 1)
                mx = fmaxf(mx, __shfl_xor_sync(0xffffffffu, mx, off));
            float newm = fmaxf(m[r], mx);
            float corr = __expf(m[r] - newm);
            float p0 = __expf(a - newm);
            float p1 = __expf(b - newm);
            float ps = p0 + p1;
#pragma unroll
            for (int off = 16; off; off >>= 1)
                ps += __shfl_xor_sync(0xffffffffu, ps, off);
            l[r] = l[r] * corr + ps;
            m[r] = newm;
            o[r][0] *= corr; o[r][1] *= corr; o[r][2] *= corr; o[r][3] *= corr;
            s0[r] = p0; s1[r] = p1;
        }

        for (int key = 0; key < 32; key++) {
            float4 v0 = *(const float4*)&Vs[key * HD + (lane << 2)];
            float4 v1 = *(const float4*)&Vs[(key + 32) * HD + (lane << 2)];
#pragma unroll
            for (int r = 0; r < 8; r++) {
                float p0 = __shfl_sync(0xffffffffu, s0[r], key);
                float p1 = __shfl_sync(0xffffffffu, s1[r], key);
                o[r][0] += p0 * v0.x + p1 * v1.x;
                o[r][1] += p0 * v0.y + p1 * v1.y;
                o[r][2] += p0 * v0.z + p1 * v1.z;
                o[r][3] += p0 * v0.w + p1 * v1.w;
            }
        }
    }

#pragma unroll
    for (int r = 0; r < 8; r++) {
        float inv = 1.f / l[r];
        size_t base = (size_t)(r0 + rowb + r) * NQD + h * HD + (lane << 2);
        ctx[base + 0] = o[r][0] * inv;
        ctx[base + 1] = o[r][1] * inv;
        ctx[base + 2] = o[r][2] * inv;
        ctx[base + 3] = o[r][3] * inv;
    }
}

// ---------------- launch ----------------
extern "C" void kernel_launch(void* const* d_in, const int* in_sizes, int n_in,
                              void* d_out, int out_size) {
    const float* hs   = (const float*)d_in[0];
    const float* cosp = (const float*)d_in[1];
    const float* sinp = (const float*)d_in[2];
    const float* Wq   = (const float*)d_in[3];
    const float* bq   = (const float*)d_in[4];
    const float* Wk   = (const float*)d_in[5];
    const float* bk   = (const float*)d_in[6];
    const float* Wv   = (const float*)d_in[7];
    const float* bv   = (const float*)d_in[8];
    const float* Wo   = (const float*)d_in[9];
    float* out = (float*)d_out;

    float *q_p, *k_p, *v_p, *ctx_p;
    cudaGetSymbolAddress((void**)&q_p,   g_q);
    cudaGetSymbolAddress((void**)&k_p,   g_k);
    cudaGetSymbolAddress((void**)&v_p,   g_v);
    cudaGetSymbolAddress((void**)&ctx_p, g_ctx);

    __nv_bfloat16 *hsh, *hsl, *ctxh, *ctxl, *wqh, *wql, *wkh, *wkl, *wvh, *wvl, *woh, *wol;
    cudaGetSymbolAddress((void**)&hsh,  g_hsh);  cudaGetSymbolAddress((void**)&hsl,  g_hsl);
    cudaGetSymbolAddress((void**)&ctxh, g_ctxh); cudaGetSymbolAddress((void**)&ctxl, g_ctxl);
    cudaGetSymbolAddress((void**)&wqh,  g_wqh);  cudaGetSymbolAddress((void**)&wql,  g_wql);
    cudaGetSymbolAddress((void**)&wkh,  g_wkh);  cudaGetSymbolAddress((void**)&wkl,  g_wkl);
    cudaGetSymbolAddress((void**)&wvh,  g_wvh);  cudaGetSymbolAddress((void**)&wvl,  g_wvl);
    cudaGetSymbolAddress((void**)&woh,  g_woh);  cudaGetSymbolAddress((void**)&wol,  g_wol);

    cudaFuncSetAttribute(gemm_mma, cudaFuncAttributeMaxDynamicSharedMemorySize, GEMM_SMEM);
    const int attn_smem = ATTN_SMEM_FLOATS * (int)sizeof(float);
    cudaFuncSetAttribute(attn_kernel, cudaFuncAttributeMaxDynamicSharedMemorySize, attn_smem);

    // 1) splits / transposes
    {
        int n4 = S_LEN * HID / 4;
        split_kernel<<<(n4 + 255) / 256, 256>>>((const float4*)hs, (__nv_bfloat162*)hsh, (__nv_bfloat162*)hsl, n4);
    }
    {
        dim3 blk(32, 8);
        tsplit_kernel<<<dim3(NQD / 32, HID / 32), blk>>>(Wq, wqh, wql, HID, NQD);
        tsplit_kernel<<<dim3(NKD / 32, HID / 32), blk>>>(Wk, wkh, wkl, HID, NKD);
        tsplit_kernel<<<dim3(NKD / 32, HID / 32), blk>>>(Wv, wvh, wvl, HID, NKD);
        tsplit_kernel<<<dim3(HID / 32, NQD / 32), blk>>>(Wo, woh, wol, NQD, HID);
    }

    // 2) QKV projections (mma.sync bf16 split)
    gemm_mma<<<dim3(NQD / 128, S_LEN / 128), 256, GEMM_SMEM>>>(hsh, hsl, wqh, wql, bq, q_p, HID, NQD);
    gemm_mma<<<dim3(NKD / 128, S_LEN / 128), 256, GEMM_SMEM>>>(hsh, hsl, wkh, wkl, bk, k_p, HID, NKD);
    gemm_mma<<<dim3(NKD / 128, S_LEN / 128), 256, GEMM_SMEM>>>(hsh, hsl, wvh, wvl, bv, v_p, HID, NKD);

    // 3) mROPE
    rope_kernel<<<S_LEN, 64>>>(q_p, k_p, cosp, sinp);

    // 4) attention -> ctx
    {
        dim3 grid(S_LEN / AT_BM, NH);
        attn_kernel<<<grid, 256, attn_smem>>>(q_p, k_p, v_p, ctx_p);
    }

    // 5) split ctx, output projection
    {
        int n4 = S_LEN * NQD / 4;
        split_kernel<<<(n4 + 255) / 256, 256>>>((const float4*)ctx_p, (__nv_bfloat162*)ctxh, (__nv_bfloat162*)ctxl, n4);
    }
    gemm_mma<<<dim3(HID / 128, S_LEN / 128), 256, GEMM_SMEM>>>(ctxh, ctxl, woh, wol, nullptr, out, NQD, HID);
}

// round 4
// speedup vs baseline: 3.0359x; 1.8168x over previous
#include <cuda_runtime.h>
#include <cuda_bf16.h>
#include <math.h>
#include <stdint.h>

// ---------------- problem constants ----------------
#define S_LEN 2048
#define HID   3584
#define NH    28
#define NKV   4
#define HD    128
#define NQD   (NH*HD)    // 3584
#define NKD   (NKV*HD)   // 512
#define GRP   (NH/NKV)   // 7

// ---------------- scratch (device globals; no allocs allowed) ----------------
__device__ float g_q[S_LEN * NQD];
__device__ float g_k[S_LEN * NKD];
__device__ float g_v[S_LEN * NKD];

// bf16 hi/lo splits (16B-aligned for cp.async / vector access)
__device__ __align__(16) __nv_bfloat16 g_hsh[S_LEN * HID],  g_hsl[S_LEN * HID];
__device__ __align__(16) __nv_bfloat16 g_ctxh[S_LEN * NQD], g_ctxl[S_LEN * NQD];
__device__ __align__(16) __nv_bfloat16 g_qh[S_LEN * NQD],   g_ql[S_LEN * NQD];
__device__ __align__(16) __nv_bfloat16 g_kh[S_LEN * NKD],   g_kl[S_LEN * NKD];
__device__ __align__(16) __nv_bfloat16 g_vh[S_LEN * NKD],   g_vl[S_LEN * NKD];
// transposed weights [N, K]
__device__ __align__(16) __nv_bfloat16 g_wqh[(size_t)NQD * HID], g_wql[(size_t)NQD * HID];
__device__ __align__(16) __nv_bfloat16 g_wkh[(size_t)NKD * HID], g_wkl[(size_t)NKD * HID];
__device__ __align__(16) __nv_bfloat16 g_wvh[(size_t)NKD * HID], g_wvl[(size_t)NKD * HID];
__device__ __align__(16) __nv_bfloat16 g_woh[(size_t)HID * NQD], g_wol[(size_t)HID * NQD];

// ---------------- helpers ----------------
__device__ __forceinline__ uint32_t smem_u32(const void* p) {
    uint32_t a;
    asm("{ .reg .u64 t; cvta.to.shared.u64 t, %1; cvt.u32.u64 %0, t; }" : "=r"(a) : "l"(p));
    return a;
}

__device__ __forceinline__ void cp_async16(uint32_t dst, const void* src) {
    asm volatile("cp.async.cg.shared.global [%0], [%1], 16;" :: "r"(dst), "l"(src) : "memory");
}

__device__ __forceinline__ void ldm_x4(uint32_t* r, uint32_t addr) {
    asm volatile("ldmatrix.sync.aligned.m8n8.x4.shared.b16 {%0,%1,%2,%3}, [%4];"
                 : "=r"(r[0]), "=r"(r[1]), "=r"(r[2]), "=r"(r[3]) : "r"(addr));
}

__device__ __forceinline__ void ldm_x2(uint32_t* r, uint32_t addr) {
    asm volatile("ldmatrix.sync.aligned.m8n8.x2.shared.b16 {%0,%1}, [%2];"
                 : "=r"(r[0]), "=r"(r[1]) : "r"(addr));
}

__device__ __forceinline__ void ldm_x2_t(uint32_t* r, uint32_t addr) {
    asm volatile("ldmatrix.sync.aligned.m8n8.x2.trans.shared.b16 {%0,%1}, [%2];"
                 : "=r"(r[0]), "=r"(r[1]) : "r"(addr));
}

__device__ __forceinline__ void mma_bf16(float* c, const uint32_t* a, const uint32_t* b) {
    asm volatile(
        "mma.sync.aligned.m16n8k16.row.col.f32.bf16.bf16.f32 "
        "{%0,%1,%2,%3}, {%4,%5,%6,%7}, {%8,%9}, {%0,%1,%2,%3};"
        : "+f"(c[0]), "+f"(c[1]), "+f"(c[2]), "+f"(c[3])
        : "r"(a[0]), "r"(a[1]), "r"(a[2]), "r"(a[3]), "r"(b[0]), "r"(b[1]));
}

// pack two f32 -> bf16x2 (lo in low half, hi in high half)
__device__ __forceinline__ uint32_t pack_bf2(float lo, float hi) {
    uint32_t r;
    asm("cvt.rn.bf16x2.f32 %0, %1, %2;" : "=r"(r) : "f"(hi), "f"(lo));
    return r;
}

// ---------------- split kernels ----------------
__global__ void split_kernel(const float4* __restrict__ X, __nv_bfloat162* __restrict__ H,
                             __nv_bfloat162* __restrict__ L, int n4) {
    int i = blockIdx.x * 256 + threadIdx.x;
    if (i >= n4) return;
    float4 x = X[i];
    __nv_bfloat16 h0 = __float2bfloat16(x.x), h1 = __float2bfloat16(x.y);
    __nv_bfloat16 h2 = __float2bfloat16(x.z), h3 = __float2bfloat16(x.w);
    H[2*i]   = __halves2bfloat162(h0, h1);
    H[2*i+1] = __halves2bfloat162(h2, h3);
    L[2*i]   = __halves2bfloat162(__float2bfloat16(x.x - __bfloat162float(h0)),
                                  __float2bfloat16(x.y - __bfloat162float(h1)));
    L[2*i+1] = __halves2bfloat162(__float2bfloat16(x.z - __bfloat162float(h2)),
                                  __float2bfloat16(x.w - __bfloat162float(h3)));
}

__global__ void split_scale_kernel(const float4* __restrict__ X, __nv_bfloat162* __restrict__ H,
                                   __nv_bfloat162* __restrict__ L, float sc, int n4) {
    int i = blockIdx.x * 256 + threadIdx.x;
    if (i >= n4) return;
    float4 x = X[i];
    x.x *= sc; x.y *= sc; x.z *= sc; x.w *= sc;
    __nv_bfloat16 h0 = __float2bfloat16(x.x), h1 = __float2bfloat16(x.y);
    __nv_bfloat16 h2 = __float2bfloat16(x.z), h3 = __float2bfloat16(x.w);
    H[2*i]   = __halves2bfloat162(h0, h1);
    H[2*i+1] = __halves2bfloat162(h2, h3);
    L[2*i]   = __halves2bfloat162(__float2bfloat16(x.x - __bfloat162float(h0)),
                                  __float2bfloat16(x.y - __bfloat162float(h1)));
    L[2*i+1] = __halves2bfloat162(__float2bfloat16(x.z - __bfloat162float(h2)),
                                  __float2bfloat16(x.w - __bfloat162float(h3)));
}

// W [K, N] row-major -> Th/Tl [N, K]
__global__ void tsplit_kernel(const float* __restrict__ W, __nv_bfloat16* __restrict__ Th,
                              __nv_bfloat16* __restrict__ Tl, int K, int N) {
    __shared__ float t[32][33];
    int n0 = blockIdx.x * 32, k0 = blockIdx.y * 32;
    int tx = threadIdx.x, ty = threadIdx.y;   // 32 x 8
#pragma unroll
    for (int i = 0; i < 4; i++) {
        int k = k0 + ty + i * 8;
        t[ty + i * 8][tx] = W[(size_t)k * N + n0 + tx];
    }
    __syncthreads();
#pragma unroll
    for (int i = 0; i < 4; i++) {
        int n = n0 + ty + i * 8;
        float v = t[tx][ty + i * 8];
        __nv_bfloat16 h = __float2bfloat16(v);
        Th[(size_t)n * K + k0 + tx] = h;
        Tl[(size_t)n * K + k0 + tx] = __float2bfloat16(v - __bfloat162float(h));
    }
}

// ---------------- mma.sync GEMM (unchanged from R3) ----------------
#define GBK 32
#define ROWP 40
#define STG_TILE 10240
#define STG_BYTES (4*STG_TILE)
#define GEMM_SMEM (2*STG_BYTES)

__global__ __launch_bounds__(256)
void gemm_mma(const __nv_bfloat16* __restrict__ Ah, const __nv_bfloat16* __restrict__ Al,
              const __nv_bfloat16* __restrict__ Bh, const __nv_bfloat16* __restrict__ Bl,
              const float* __restrict__ bias, float* __restrict__ C, int K, int Ntot) {
    extern __shared__ char smem[];
    const uint32_t sb = smem_u32(smem);
    const int tid = threadIdx.x;
    const int lane = tid & 31;
    const int warp = tid >> 5;
    const int wm = (warp >> 2) * 64;
    const int wn = (warp & 3) * 32;
    const int row0 = blockIdx.y * 128;
    const int col0 = blockIdx.x * 128;
    const int NI = K / GBK;

    float acc[4][4][4];
#pragma unroll
    for (int mt = 0; mt < 4; mt++)
#pragma unroll
        for (int nt = 0; nt < 4; nt++)
#pragma unroll
            for (int i = 0; i < 4; i++) acc[mt][nt][i] = 0.f;

    auto issue_load = [&](int stage, int kb) {
        uint32_t sbase = sb + stage * STG_BYTES;
#pragma unroll
        for (int tile = 0; tile < 4; tile++) {
            const __nv_bfloat16* src =
                (tile == 0) ? Ah : (tile == 1) ? Al : (tile == 2) ? Bh : Bl;
            int gbase = (tile < 2) ? row0 : col0;
#pragma unroll
            for (int j = 0; j < 2; j++) {
                int s = j * 256 + tid;
                int row = s >> 2;
                int c = (s & 3) << 3;
                const void* g = src + (size_t)(gbase + row) * K + kb + c;
                uint32_t dst = sbase + tile * STG_TILE + (row * ROWP + c) * 2;
                cp_async16(dst, g);
            }
        }
        asm volatile("cp.async.commit_group;" ::: "memory");
    };

    issue_load(0, 0);

    for (int i = 0; i < NI; i++) {
        if (i + 1 < NI) {
            issue_load((i + 1) & 1, (i + 1) * GBK);
            asm volatile("cp.async.wait_group 1;" ::: "memory");
        } else {
            asm volatile("cp.async.wait_group 0;" ::: "memory");
        }
        __syncthreads();

        const uint32_t sa = sb + (i & 1) * STG_BYTES;
#pragma unroll
        for (int ks = 0; ks < 2; ks++) {
            uint32_t bh[4][2], bl[4][2];
#pragma unroll
            for (int nt = 0; nt < 4; nt++) {
                uint32_t addr = sa + 2 * STG_TILE +
                    ((wn + nt * 8 + (lane & 7)) * ROWP + ks * 16 + (((lane >> 3) & 1) << 3)) * 2;
                ldm_x2(bh[nt], addr);
                ldm_x2(bl[nt], addr + STG_TILE);
            }
#pragma unroll
            for (int mt = 0; mt < 4; mt++) {
                uint32_t ah[4], al[4];
                uint32_t addr = sa +
                    ((wm + mt * 16 + (lane & 15)) * ROWP + ks * 16 + ((lane >> 4) << 3)) * 2;
                ldm_x4(ah, addr);
                ldm_x4(al, addr + STG_TILE);
#pragma unroll
                for (int nt = 0; nt < 4; nt++) {
                    mma_bf16(acc[mt][nt], ah, bh[nt]);
                    mma_bf16(acc[mt][nt], ah, bl[nt]);
                    mma_bf16(acc[mt][nt], al, bh[nt]);
                }
            }
        }
        __syncthreads();
    }

#pragma unroll
    for (int mt = 0; mt < 4; mt++) {
#pragma unroll
        for (int nt = 0; nt < 4; nt++) {
            int r = row0 + wm + mt * 16 + (lane >> 2);
            int cidx = col0 + wn + nt * 8 + ((lane & 3) << 1);
            float b0 = 0.f, b1 = 0.f;
            if (bias) { b0 = bias[cidx]; b1 = bias[cidx + 1]; }
            float2* p0 = (float2*)(C + (size_t)r * Ntot + cidx);
            float2* p1 = (float2*)(C + (size_t)(r + 8) * Ntot + cidx);
            *p0 = make_float2(acc[mt][nt][0] + b0, acc[mt][nt][1] + b1);
            *p1 = make_float2(acc[mt][nt][2] + b0, acc[mt][nt][3] + b1);
        }
    }
}

// ---------------- mROPE (in-place on q and k) ----------------
__global__ void rope_kernel(float* __restrict__ q, float* __restrict__ k,
                            const float* __restrict__ cosp, const float* __restrict__ sinp) {
    const int s = blockIdx.x;
    const int d = threadIdx.x;     // 0..63
    const int d2 = d + 64;
    const int sec = (d < 16) ? 0 : ((d < 40) ? 1 : 2);
    const int SH = S_LEN * HD;

    const float c1 = cosp[sec * SH + s * HD + d];
    const float s1 = sinp[sec * SH + s * HD + d];
    const float c2 = cosp[sec * SH + s * HD + d2];
    const float s2 = sinp[sec * SH + s * HD + d2];

#pragma unroll 1
    for (int hh = 0; hh < NH + NKV; hh++) {
        float* base = (hh < NH) ? (q + (size_t)s * NQD + hh * HD)
                                : (k + (size_t)s * NKD + (hh - NH) * HD);
        float x1 = base[d];
        float x2 = base[d2];
        base[d]  = x1 * c1 - x2 * s1;
        base[d2] = x2 * c2 + x1 * s2;
    }
}

// ---------------- attention: mma.sync flash, bf16 hi/lo split ----------------
// CTA = (head, 64 q-rows), 4 warps x 16 rows, BN=64 keys per iter.
#define ATP 136                      // padded row length (bf16 elems): 272B, conflict-free
#define AT_ROWB (ATP*2)              // 272 bytes per row
#define AT_TILE (64*AT_ROWB)         // 17408 B per 64x128 tile
#define AQ_H 0
#define AQ_L (AQ_H + AT_TILE)
#define AK_H (AQ_L + AT_TILE)
#define AK_L (AK_H + AT_TILE)
#define AV_H (AK_L + AT_TILE)
#define AV_L (AV_H + AT_TILE)
#define ATTN_SMEM (6*AT_TILE)        // 104448 B

__global__ __launch_bounds__(128)
void attn_mma(const __nv_bfloat16* __restrict__ qh, const __nv_bfloat16* __restrict__ ql,
              const __nv_bfloat16* __restrict__ kh, const __nv_bfloat16* __restrict__ kl,
              const __nv_bfloat16* __restrict__ vh, const __nv_bfloat16* __restrict__ vl,
              __nv_bfloat16* __restrict__ ctxh, __nv_bfloat16* __restrict__ ctxl) {
    extern __shared__ char smem[];
    const uint32_t sb = smem_u32(smem);
    const int tid = threadIdx.x;
    const int lane = tid & 31;
    const int warp = tid >> 5;
    const int h = blockIdx.y;
    const int kvh = h / GRP;
    const int r0 = blockIdx.x * 64;

    // ---- prolog: Q tile (64 x 128) hi/lo -> smem ----
#pragma unroll
    for (int j = 0; j < 8; j++) {
        int idx = j * 128 + tid;          // 0..1023
        int row = idx >> 4, c = idx & 15; // 16 chunks of 8 bf16 per row
        size_t g = (size_t)(r0 + row) * NQD + h * HD + c * 8;
        uint32_t so = row * AT_ROWB + c * 16;
        cp_async16(sb + AQ_H + so, qh + g);
        cp_async16(sb + AQ_L + so, ql + g);
    }
    asm volatile("cp.async.commit_group;" ::: "memory");
    asm volatile("cp.async.wait_group 0;" ::: "memory");
    __syncthreads();

    // ---- Q fragments -> registers (warp owns rows [warp*16, warp*16+16)) ----
    uint32_t qfh[8][4], qfl[8][4];
#pragma unroll
    for (int kf = 0; kf < 8; kf++) {
        uint32_t off = ((warp * 16 + (lane & 15)) * ATP + kf * 16 + ((lane >> 4) << 3)) * 2;
        ldm_x4(qfh[kf], sb + AQ_H + off);
        ldm_x4(qfl[kf], sb + AQ_L + off);
    }

    float o[16][4];
#pragma unroll
    for (int nt = 0; nt < 16; nt++)
#pragma unroll
        for (int i = 0; i < 4; i++) o[nt][i] = 0.f;
    float m0 = -INFINITY, m1 = -INFINITY, l0 = 0.f, l1 = 0.f;

    for (int kt = 0; kt < S_LEN; kt += 64) {
        __syncthreads();   // all warps done reading previous K/V (and Q frags on iter 0)
        // ---- load K,V tiles hi/lo ----
#pragma unroll
        for (int j = 0; j < 8; j++) {
            int idx = j * 128 + tid;
            int row = idx >> 4, c = idx & 15;
            size_t g = (size_t)(kt + row) * NKD + kvh * HD + c * 8;
            uint32_t so = row * AT_ROWB + c * 16;
            cp_async16(sb + AK_H + so, kh + g);
            cp_async16(sb + AK_L + so, kl + g);
            cp_async16(sb + AV_H + so, vh + g);
            cp_async16(sb + AV_L + so, vl + g);
        }
        asm volatile("cp.async.commit_group;" ::: "memory");
        asm volatile("cp.async.wait_group 0;" ::: "memory");
        __syncthreads();

        // ---- S = Q K^T (3-term split), scale pre-folded into Q ----
        float s[8][4];
#pragma unroll
        for (int nt = 0; nt < 8; nt++)
#pragma unroll
            for (int i = 0; i < 4; i++) s[nt][i] = 0.f;

#pragma unroll
        for (int kf = 0; kf < 8; kf++) {
#pragma unroll
            for (int nt = 0; nt < 8; nt++) {
                uint32_t bh[2], bl[2];
                uint32_t off = ((nt * 8 + (lane & 7)) * ATP + kf * 16 + (((lane >> 3) & 1) << 3)) * 2;
                ldm_x2(bh, sb + AK_H + off);
                ldm_x2(bl, sb + AK_L + off);
                mma_bf16(s[nt], qfh[kf], bh);
                mma_bf16(s[nt], qfh[kf], bl);
                mma_bf16(s[nt], qfl[kf], bh);
            }
        }

        // ---- online softmax (rows: r_lo = lane>>2, r_hi = r_lo+8 within warp tile) ----
        float mx0 = -INFINITY, mx1 = -INFINITY;
#pragma unroll
        for (int nt = 0; nt < 8; nt++) {
            mx0 = fmaxf(mx0, fmaxf(s[nt][0], s[nt][1]));
            mx1 = fmaxf(mx1, fmaxf(s[nt][2], s[nt][3]));
        }
        mx0 = fmaxf(mx0, __shfl_xor_sync(0xffffffffu, mx0, 1));
        mx0 = fmaxf(mx0, __shfl_xor_sync(0xffffffffu, mx0, 2));
        mx1 = fmaxf(mx1, __shfl_xor_sync(0xffffffffu, mx1, 1));
        mx1 = fmaxf(mx1, __shfl_xor_sync(0xffffffffu, mx1, 2));

        float nm0 = fmaxf(m0, mx0), nm1 = fmaxf(m1, mx1);
        float c0 = __expf(m0 - nm0), c1 = __expf(m1 - nm1);
        m0 = nm0; m1 = nm1;

        float sum0 = 0.f, sum1 = 0.f;
#pragma unroll
        for (int nt = 0; nt < 8; nt++) {
            s[nt][0] = __expf(s[nt][0] - nm0);
            s[nt][1] = __expf(s[nt][1] - nm0);
            s[nt][2] = __expf(s[nt][2] - nm1);
            s[nt][3] = __expf(s[nt][3] - nm1);
            sum0 += s[nt][0] + s[nt][1];
            sum1 += s[nt][2] + s[nt][3];
        }
        sum0 += __shfl_xor_sync(0xffffffffu, sum0, 1);
        sum0 += __shfl_xor_sync(0xffffffffu, sum0, 2);
        sum1 += __shfl_xor_sync(0xffffffffu, sum1, 1);
        sum1 += __shfl_xor_sync(0xffffffffu, sum1, 2);
        l0 = l0 * c0 + sum0;
        l1 = l1 * c1 + sum1;

#pragma unroll
        for (int nt = 0; nt < 16; nt++) {
            o[nt][0] *= c0; o[nt][1] *= c0;
            o[nt][2] *= c1; o[nt][3] *= c1;
        }

        // ---- O += P V (3-term split). P C-frags -> A-frags in registers ----
#pragma unroll
        for (int kf = 0; kf < 4; kf++) {
            uint32_t ah[4], al[4];
#pragma unroll
            for (int half = 0; half < 2; half++) {
                int nt = 2 * kf + half;
                uint32_t p01 = pack_bf2(s[nt][0], s[nt][1]);
                uint32_t p23 = pack_bf2(s[nt][2], s[nt][3]);
                // residuals via bit-expansion of the packed hi values
                float h0 = __uint_as_float(p01 << 16);
                float h1 = __uint_as_float(p01 & 0xffff0000u);
                float h2 = __uint_as_float(p23 << 16);
                float h3 = __uint_as_float(p23 & 0xffff0000u);
                uint32_t q01 = pack_bf2(s[nt][0] - h0, s[nt][1] - h1);
                uint32_t q23 = pack_bf2(s[nt][2] - h2, s[nt][3] - h3);
                ah[2 * half]     = p01;   // (row r,   k low8)  for half=0; k high8 for half=1
                ah[2 * half + 1] = p23;   // (row r+8)
                al[2 * half]     = q01;
                al[2 * half + 1] = q23;
            }
            // note: frag order must be {(r,klo),(r+8,klo),(r,khi),(r+8,khi)} — matches loop above
#pragma unroll
            for (int nt = 0; nt < 16; nt++) {
                uint32_t bh[2], bl[2];
                uint32_t off = ((kf * 16 + (lane & 15)) * ATP + nt * 8) * 2;
                ldm_x2_t(bh, sb + AV_H + off);
                ldm_x2_t(bl, sb + AV_L + off);
                mma_bf16(o[nt], ah, bh);
                mma_bf16(o[nt], ah, bl);
                mma_bf16(o[nt], al, bh);
            }
        }
    }

    // ---- epilogue: write ctx hi/lo bf16 ----
    float inv0 = 1.f / l0, inv1 = 1.f / l1;
    int r_lo = r0 + warp * 16 + (lane >> 2);
    int r_hi = r_lo + 8;
#pragma unroll
    for (int nt = 0; nt < 16; nt++) {
        int col = h * HD + nt * 8 + ((lane & 3) << 1);
        {
            float x0 = o[nt][0] * inv0, x1 = o[nt][1] * inv0;
            uint32_t ph = pack_bf2(x0, x1);
            float h0 = __uint_as_float(ph << 16);
            float h1 = __uint_as_float(ph & 0xffff0000u);
            uint32_t pl = pack_bf2(x0 - h0, x1 - h1);
            *(uint32_t*)(ctxh + (size_t)r_lo * NQD + col) = ph;
            *(uint32_t*)(ctxl + (size_t)r_lo * NQD + col) = pl;
        }
        {
            float x0 = o[nt][2] * inv1, x1 = o[nt][3] * inv1;
            uint32_t ph = pack_bf2(x0, x1);
            float h0 = __uint_as_float(ph << 16);
            float h1 = __uint_as_float(ph & 0xffff0000u);
            uint32_t pl = pack_bf2(x0 - h0, x1 - h1);
            *(uint32_t*)(ctxh + (size_t)r_hi * NQD + col) = ph;
            *(uint32_t*)(ctxl + (size_t)r_hi * NQD + col) = pl;
        }
    }
}

// ---------------- launch ----------------
extern "C" void kernel_launch(void* const* d_in, const int* in_sizes, int n_in,
                              void* d_out, int out_size) {
    const float* hs   = (const float*)d_in[0];
    const float* cosp = (const float*)d_in[1];
    const float* sinp = (const float*)d_in[2];
    const float* Wq   = (const float*)d_in[3];
    const float* bq   = (const float*)d_in[4];
    const float* Wk   = (const float*)d_in[5];
    const float* bk   = (const float*)d_in[6];
    const float* Wv   = (const float*)d_in[7];
    const float* bv   = (const float*)d_in[8];
    const float* Wo   = (const float*)d_in[9];
    float* out = (float*)d_out;

    float *q_p, *k_p, *v_p;
    cudaGetSymbolAddress((void**)&q_p, g_q);
    cudaGetSymbolAddress((void**)&k_p, g_k);
    cudaGetSymbolAddress((void**)&v_p, g_v);

    __nv_bfloat16 *hsh, *hsl, *ctxh, *ctxl, *wqh, *wql, *wkh, *wkl, *wvh, *wvl, *woh, *wol;
    __nv_bfloat16 *qh, *qls, *khp, *klp, *vhp, *vlp;
    cudaGetSymbolAddress((void**)&hsh,  g_hsh);  cudaGetSymbolAddress((void**)&hsl,  g_hsl);
    cudaGetSymbolAddress((void**)&ctxh, g_ctxh); cudaGetSymbolAddress((void**)&ctxl, g_ctxl);
    cudaGetSymbolAddress((void**)&wqh,  g_wqh);  cudaGetSymbolAddress((void**)&wql,  g_wql);
    cudaGetSymbolAddress((void**)&wkh,  g_wkh);  cudaGetSymbolAddress((void**)&wkl,  g_wkl);
    cudaGetSymbolAddress((void**)&wvh,  g_wvh);  cudaGetSymbolAddress((void**)&wvl,  g_wvl);
    cudaGetSymbolAddress((void**)&woh,  g_woh);  cudaGetSymbolAddress((void**)&wol,  g_wol);
    cudaGetSymbolAddress((void**)&qh,   g_qh);   cudaGetSymbolAddress((void**)&qls,  g_ql);
    cudaGetSymbolAddress((void**)&khp,  g_kh);   cudaGetSymbolAddress((void**)&klp,  g_kl);
    cudaGetSymbolAddress((void**)&vhp,  g_vh);   cudaGetSymbolAddress((void**)&vlp,  g_vl);

    cudaFuncSetAttribute(gemm_mma, cudaFuncAttributeMaxDynamicSharedMemorySize, GEMM_SMEM);
    cudaFuncSetAttribute(attn_mma, cudaFuncAttributeMaxDynamicSharedMemorySize, ATTN_SMEM);

    // 1) splits / transposes
    {
        int n4 = S_LEN * HID / 4;
        split_kernel<<<(n4 + 255) / 256, 256>>>((const float4*)hs, (__nv_bfloat162*)hsh, (__nv_bfloat162*)hsl, n4);
    }
    {
        dim3 blk(32, 8);
        tsplit_kernel<<<dim3(NQD / 32, HID / 32), blk>>>(Wq, wqh, wql, HID, NQD);
        tsplit_kernel<<<dim3(NKD / 32, HID / 32), blk>>>(Wk, wkh, wkl, HID, NKD);
        tsplit_kernel<<<dim3(NKD / 32, HID / 32), blk>>>(Wv, wvh, wvl, HID, NKD);
        tsplit_kernel<<<dim3(HID / 32, NQD / 32), blk>>>(Wo, woh, wol, NQD, HID);
    }

    // 2) QKV projections
    gemm_mma<<<dim3(NQD / 128, S_LEN / 128), 256, GEMM_SMEM>>>(hsh, hsl, wqh, wql, bq, q_p, HID, NQD);
    gemm_mma<<<dim3(NKD / 128, S_LEN / 128), 256, GEMM_SMEM>>>(hsh, hsl, wkh, wkl, bk, k_p, HID, NKD);
    gemm_mma<<<dim3(NKD / 128, S_LEN / 128), 256, GEMM_SMEM>>>(hsh, hsl, wvh, wvl, bv, v_p, HID, NKD);

    // 3) mROPE
    rope_kernel<<<S_LEN, 64>>>(q_p, k_p, cosp, sinp);

    // 4) split q (scaled), k, v into bf16 hi/lo
    {
        const float scale = 0.08838834764831845f;   // 1/sqrt(128)
        int n4q = S_LEN * NQD / 4;
        split_scale_kernel<<<(n4q + 255) / 256, 256>>>((const float4*)q_p, (__nv_bfloat162*)qh, (__nv_bfloat162*)qls, scale, n4q);
        int n4k = S_LEN * NKD / 4;
        split_kernel<<<(n4k + 255) / 256, 256>>>((const float4*)k_p, (__nv_bfloat162*)khp, (__nv_bfloat162*)klp, n4k);
        split_kernel<<<(n4k + 255) / 256, 256>>>((const float4*)v_p, (__nv_bfloat162*)vhp, (__nv_bfloat162*)vlp, n4k);
    }

    // 5) attention -> ctx (hi/lo bf16 directly)
    {
        dim3 grid(S_LEN / 64, NH);
        attn_mma<<<grid, 128, ATTN_SMEM>>>(qh, qls, khp, klp, vhp, vlp, ctxh, ctxl);
    }

    // 6) output projection
    gemm_mma<<<dim3(HID / 128, S_LEN / 128), 256, GEMM_SMEM>>>(ctxh, ctxl, woh, wol, nullptr, out, NQD, HID);
}

// round 5
// speedup vs baseline: 3.2506x; 1.0707x over previous
#include <cuda_runtime.h>
#include <cuda_bf16.h>
#include <math.h>
#include <stdint.h>

// ---------------- problem constants ----------------
#define S_LEN 2048
#define HID   3584
#define NH    28
#define NKV   4
#define HD    128
#define NQD   (NH*HD)    // 3584
#define NKD   (NKV*HD)   // 512
#define GRP   (NH/NKV)   // 7
#define NQKV  (NQD + 2*NKD)  // 4608

// ---------------- scratch (device globals; no allocs allowed) ----------------
__device__ float g_qkv[(size_t)S_LEN * NQKV];
__device__ float g_bias[NQKV];

// bf16 hi/lo splits (16B-aligned for cp.async / vector access)
__device__ __align__(16) __nv_bfloat16 g_hsh[S_LEN * HID],  g_hsl[S_LEN * HID];
__device__ __align__(16) __nv_bfloat16 g_ctxh[S_LEN * NQD], g_ctxl[S_LEN * NQD];
__device__ __align__(16) __nv_bfloat16 g_qh[S_LEN * NQD],   g_ql[S_LEN * NQD];
__device__ __align__(16) __nv_bfloat16 g_kh[S_LEN * NKD],   g_kl[S_LEN * NKD];
__device__ __align__(16) __nv_bfloat16 g_vh[S_LEN * NKD],   g_vl[S_LEN * NKD];
// transposed weights [N, K]; QKV concatenated along N
__device__ __align__(16) __nv_bfloat16 g_wh[(size_t)NQKV * HID], g_wl[(size_t)NQKV * HID];
__device__ __align__(16) __nv_bfloat16 g_woh[(size_t)HID * NQD], g_wol[(size_t)HID * NQD];

// ---------------- helpers ----------------
__device__ __forceinline__ uint32_t smem_u32(const void* p) {
    uint32_t a;
    asm("{ .reg .u64 t; cvta.to.shared.u64 t, %1; cvt.u32.u64 %0, t; }" : "=r"(a) : "l"(p));
    return a;
}

__device__ __forceinline__ void cp_async16(uint32_t dst, const void* src) {
    asm volatile("cp.async.cg.shared.global [%0], [%1], 16;" :: "r"(dst), "l"(src) : "memory");
}

__device__ __forceinline__ void ldm_x4(uint32_t* r, uint32_t addr) {
    asm volatile("ldmatrix.sync.aligned.m8n8.x4.shared.b16 {%0,%1,%2,%3}, [%4];"
                 : "=r"(r[0]), "=r"(r[1]), "=r"(r[2]), "=r"(r[3]) : "r"(addr));
}

__device__ __forceinline__ void ldm_x2(uint32_t* r, uint32_t addr) {
    asm volatile("ldmatrix.sync.aligned.m8n8.x2.shared.b16 {%0,%1}, [%2];"
                 : "=r"(r[0]), "=r"(r[1]) : "r"(addr));
}

__device__ __forceinline__ void ldm_x2_t(uint32_t* r, uint32_t addr) {
    asm volatile("ldmatrix.sync.aligned.m8n8.x2.trans.shared.b16 {%0,%1}, [%2];"
                 : "=r"(r[0]), "=r"(r[1]) : "r"(addr));
}

__device__ __forceinline__ void mma_bf16(float* c, const uint32_t* a, const uint32_t* b) {
    asm volatile(
        "mma.sync.aligned.m16n8k16.row.col.f32.bf16.bf16.f32 "
        "{%0,%1,%2,%3}, {%4,%5,%6,%7}, {%8,%9}, {%0,%1,%2,%3};"
        : "+f"(c[0]), "+f"(c[1]), "+f"(c[2]), "+f"(c[3])
        : "r"(a[0]), "r"(a[1]), "r"(a[2]), "r"(a[3]), "r"(b[0]), "r"(b[1]));
}

__device__ __forceinline__ uint32_t pack_bf2(float lo, float hi) {
    uint32_t r;
    asm("cvt.rn.bf16x2.f32 %0, %1, %2;" : "=r"(r) : "f"(hi), "f"(lo));
    return r;
}

__device__ __forceinline__ void wsplit(__nv_bfloat16* H, __nv_bfloat16* L, size_t idx, float x) {
    __nv_bfloat16 h = __float2bfloat16(x);
    H[idx] = h;
    L[idx] = __float2bfloat16(x - __bfloat162float(h));
}

// ---------------- split kernels ----------------
__global__ void split_kernel(const float4* __restrict__ X, __nv_bfloat162* __restrict__ H,
                             __nv_bfloat162* __restrict__ L, int n4) {
    int i = blockIdx.x * 256 + threadIdx.x;
    if (i >= n4) return;
    float4 x = X[i];
    __nv_bfloat16 h0 = __float2bfloat16(x.x), h1 = __float2bfloat16(x.y);
    __nv_bfloat16 h2 = __float2bfloat16(x.z), h3 = __float2bfloat16(x.w);
    H[2*i]   = __halves2bfloat162(h0, h1);
    H[2*i+1] = __halves2bfloat162(h2, h3);
    L[2*i]   = __halves2bfloat162(__float2bfloat16(x.x - __bfloat162float(h0)),
                                  __float2bfloat16(x.y - __bfloat162float(h1)));
    L[2*i+1] = __halves2bfloat162(__float2bfloat16(x.z - __bfloat162float(h2)),
                                  __float2bfloat16(x.w - __bfloat162float(h3)));
}

// W [K, N] row-major -> Th/Tl [N, K]
__global__ void tsplit_kernel(const float* __restrict__ W, __nv_bfloat16* __restrict__ Th,
                              __nv_bfloat16* __restrict__ Tl, int K, int N) {
    __shared__ float t[32][33];
    int n0 = blockIdx.x * 32, k0 = blockIdx.y * 32;
    int tx = threadIdx.x, ty = threadIdx.y;   // 32 x 8
#pragma unroll
    for (int i = 0; i < 4; i++) {
        int k = k0 + ty + i * 8;
        t[ty + i * 8][tx] = W[(size_t)k * N + n0 + tx];
    }
    __syncthreads();
#pragma unroll
    for (int i = 0; i < 4; i++) {
        int n = n0 + ty + i * 8;
        float v = t[tx][ty + i * 8];
        __nv_bfloat16 h = __float2bfloat16(v);
        Th[(size_t)n * K + k0 + tx] = h;
        Tl[(size_t)n * K + k0 + tx] = __float2bfloat16(v - __bfloat162float(h));
    }
}

__global__ void concat_bias_kernel(const float* __restrict__ bq, const float* __restrict__ bk,
                                   const float* __restrict__ bv, float* __restrict__ b) {
    int i = blockIdx.x * 256 + threadIdx.x;
    if (i < NQD) b[i] = bq[i];
    else if (i < NQD + NKD) b[i] = bk[i - NQD];
    else if (i < NQKV) b[i] = bv[i - NQD - NKD];
}

// ---------------- mma.sync GEMM (proven R3) ----------------
#define GBK 32
#define ROWP 40
#define STG_TILE 10240
#define STG_BYTES (4*STG_TILE)
#define GEMM_SMEM (2*STG_BYTES)

__global__ __launch_bounds__(256)
void gemm_mma(const __nv_bfloat16* __restrict__ Ah, const __nv_bfloat16* __restrict__ Al,
              const __nv_bfloat16* __restrict__ Bh, const __nv_bfloat16* __restrict__ Bl,
              const float* __restrict__ bias, float* __restrict__ C, int K, int Ntot) {
    extern __shared__ char smem[];
    const uint32_t sb = smem_u32(smem);
    const int tid = threadIdx.x;
    const int lane = tid & 31;
    const int warp = tid >> 5;
    const int wm = (warp >> 2) * 64;
    const int wn = (warp & 3) * 32;
    const int row0 = blockIdx.y * 128;
    const int col0 = blockIdx.x * 128;
    const int NI = K / GBK;

    float acc[4][4][4];
#pragma unroll
    for (int mt = 0; mt < 4; mt++)
#pragma unroll
        for (int nt = 0; nt < 4; nt++)
#pragma unroll
            for (int i = 0; i < 4; i++) acc[mt][nt][i] = 0.f;

    auto issue_load = [&](int stage, int kb) {
        uint32_t sbase = sb + stage * STG_BYTES;
#pragma unroll
        for (int tile = 0; tile < 4; tile++) {
            const __nv_bfloat16* src =
                (tile == 0) ? Ah : (tile == 1) ? Al : (tile == 2) ? Bh : Bl;
            int gbase = (tile < 2) ? row0 : col0;
#pragma unroll
            for (int j = 0; j < 2; j++) {
                int s = j * 256 + tid;
                int row = s >> 2;
                int c = (s & 3) << 3;
                const void* g = src + (size_t)(gbase + row) * K + kb + c;
                uint32_t dst = sbase + tile * STG_TILE + (row * ROWP + c) * 2;
                cp_async16(dst, g);
            }
        }
        asm volatile("cp.async.commit_group;" ::: "memory");
    };

    issue_load(0, 0);

    for (int i = 0; i < NI; i++) {
        if (i + 1 < NI) {
            issue_load((i + 1) & 1, (i + 1) * GBK);
            asm volatile("cp.async.wait_group 1;" ::: "memory");
        } else {
            asm volatile("cp.async.wait_group 0;" ::: "memory");
        }
        __syncthreads();

        const uint32_t sa = sb + (i & 1) * STG_BYTES;
#pragma unroll
        for (int ks = 0; ks < 2; ks++) {
            uint32_t bh[4][2], bl[4][2];
#pragma unroll
            for (int nt = 0; nt < 4; nt++) {
                uint32_t addr = sa + 2 * STG_TILE +
                    ((wn + nt * 8 + (lane & 7)) * ROWP + ks * 16 + (((lane >> 3) & 1) << 3)) * 2;
                ldm_x2(bh[nt], addr);
                ldm_x2(bl[nt], addr + STG_TILE);
            }
#pragma unroll
            for (int mt = 0; mt < 4; mt++) {
                uint32_t ah[4], al[4];
                uint32_t addr = sa +
                    ((wm + mt * 16 + (lane & 15)) * ROWP + ks * 16 + ((lane >> 4) << 3)) * 2;
                ldm_x4(ah, addr);
                ldm_x4(al, addr + STG_TILE);
#pragma unroll
                for (int nt = 0; nt < 4; nt++) {
                    mma_bf16(acc[mt][nt], ah, bh[nt]);
                    mma_bf16(acc[mt][nt], ah, bl[nt]);
                    mma_bf16(acc[mt][nt], al, bh[nt]);
                }
            }
        }
        __syncthreads();
    }

#pragma unroll
    for (int mt = 0; mt < 4; mt++) {
#pragma unroll
        for (int nt = 0; nt < 4; nt++) {
            int r = row0 + wm + mt * 16 + (lane >> 2);
            int cidx = col0 + wn + nt * 8 + ((lane & 3) << 1);
            float b0 = 0.f, b1 = 0.f;
            if (bias) { b0 = bias[cidx]; b1 = bias[cidx + 1]; }
            float2* p0 = (float2*)(C + (size_t)r * Ntot + cidx);
            float2* p1 = (float2*)(C + (size_t)(r + 8) * Ntot + cidx);
            *p0 = make_float2(acc[mt][nt][0] + b0, acc[mt][nt][1] + b1);
            *p1 = make_float2(acc[mt][nt][2] + b0, acc[mt][nt][3] + b1);
        }
    }
}

// ---------------- fused mROPE + hi/lo split ----------------
// reads qkv [S][4608], writes qh/ql (scaled), kh/kl, vh/vl
__global__ __launch_bounds__(256)
void rope_split_kernel(const float* __restrict__ qkv,
                       const float* __restrict__ cosp, const float* __restrict__ sinp,
                       __nv_bfloat16* __restrict__ qh, __nv_bfloat16* __restrict__ ql,
                       __nv_bfloat16* __restrict__ kh, __nv_bfloat16* __restrict__ kl,
                       __nv_bfloat16* __restrict__ vh, __nv_bfloat16* __restrict__ vl) {
    const int s = blockIdx.x;
    const int tid = threadIdx.x;
    const int d = tid & 63;
    const int grp = tid >> 6;             // 0..3
    const int d2 = d + 64;
    const int sec = (d < 16) ? 0 : ((d < 40) ? 1 : 2);
    const int SH = S_LEN * HD;
    const float scale = 0.08838834764831845f;   // 1/sqrt(128)

    const float c1 = cosp[sec * SH + s * HD + d];
    const float s1 = sinp[sec * SH + s * HD + d];
    const float c2 = cosp[sec * SH + s * HD + d2];
    const float s2 = sinp[sec * SH + s * HD + d2];

    const float* row = qkv + (size_t)s * NQKV;

#pragma unroll 1
    for (int it = 0; it < 9; it++) {
        int hh = it * 4 + grp;    // 0..35
        if (hh < NH) {
            const float* base = row + hh * HD;
            float x1 = base[d], x2 = base[d2];
            float y1 = (x1 * c1 - x2 * s1) * scale;
            float y2 = (x2 * c2 + x1 * s2) * scale;
            size_t o = (size_t)s * NQD + hh * HD;
            wsplit(qh, ql, o + d, y1);
            wsplit(qh, ql, o + d2, y2);
        } else if (hh < NH + NKV) {
            int kvi = hh - NH;
            const float* base = row + NQD + kvi * HD;
            float x1 = base[d], x2 = base[d2];
            float y1 = x1 * c1 - x2 * s1;
            float y2 = x2 * c2 + x1 * s2;
            size_t o = (size_t)s * NKD + kvi * HD;
            wsplit(kh, kl, o + d, y1);
            wsplit(kh, kl, o + d2, y2);
        } else {
            int kvi = hh - NH - NKV;
            const float* base = row + NQD + NKD + kvi * HD;
            size_t o = (size_t)s * NKD + kvi * HD;
            wsplit(vh, vl, o + d, base[d]);
            wsplit(vh, vl, o + d2, base[d2]);
        }
    }
}

// ---------------- attention: mma.sync flash, 128 q-rows/CTA, pipelined KV ----------------
#define ATP 136
#define AT_ROWB (ATP*2)              // 272 B/row
#define AQ_TILE (128*AT_ROWB)        // 34816
#define KV_TILE (32*AT_ROWB)         // 8704
#define KV_STG  (4*KV_TILE)          // 34816 (Kh,Kl,Vh,Vl)
#define AQ_H 0
#define AQ_L AQ_TILE
#define AKV  (2*AQ_TILE)
#define ATTN_SMEM (AKV + 2*KV_STG)   // 139264 B

__global__ __launch_bounds__(256)
void attn_mma(const __nv_bfloat16* __restrict__ qh, const __nv_bfloat16* __restrict__ ql,
              const __nv_bfloat16* __restrict__ kh, const __nv_bfloat16* __restrict__ kl,
              const __nv_bfloat16* __restrict__ vh, const __nv_bfloat16* __restrict__ vl,
              __nv_bfloat16* __restrict__ ctxh, __nv_bfloat16* __restrict__ ctxl) {
    extern __shared__ char smem[];
    const uint32_t sb = smem_u32(smem);
    const int tid = threadIdx.x;
    const int lane = tid & 31;
    const int warp = tid >> 5;           // 0..7
    const int h = blockIdx.y;
    const int kvh = h / GRP;
    const int r0 = blockIdx.x * 128;

    // ---- Q tile (128 x 128) hi/lo ----
#pragma unroll
    for (int j = 0; j < 8; j++) {
        int idx = j * 256 + tid;          // 0..2047
        int row = idx >> 4, c = idx & 15;
        size_t g = (size_t)(r0 + row) * NQD + h * HD + c * 8;
        uint32_t so = row * AT_ROWB + c * 16;
        cp_async16(sb + AQ_H + so, qh + g);
        cp_async16(sb + AQ_L + so, ql + g);
    }
    asm volatile("cp.async.commit_group;" ::: "memory");

    auto issue_kv = [&](int stage, int kt) {
        uint32_t base = sb + AKV + stage * KV_STG;
#pragma unroll
        for (int j = 0; j < 2; j++) {
            int idx = j * 256 + tid;      // 0..511
            int row = idx >> 4, c = idx & 15;
            size_t g = (size_t)(kt + row) * NKD + kvh * HD + c * 8;
            uint32_t so = row * AT_ROWB + c * 16;
            cp_async16(base + 0 * KV_TILE + so, kh + g);
            cp_async16(base + 1 * KV_TILE + so, kl + g);
            cp_async16(base + 2 * KV_TILE + so, vh + g);
            cp_async16(base + 3 * KV_TILE + so, vl + g);
        }
        asm volatile("cp.async.commit_group;" ::: "memory");
    };

    issue_kv(0, 0);
    asm volatile("cp.async.wait_group 1;" ::: "memory");   // Q done (kv0 may pend)
    __syncthreads();

    // ---- Q fragments (warp owns rows [warp*16, warp*16+16)) ----
    uint32_t qfh[8][4], qfl[8][4];
#pragma unroll
    for (int kf = 0; kf < 8; kf++) {
        uint32_t off = ((warp * 16 + (lane & 15)) * ATP + kf * 16 + ((lane >> 4) << 3)) * 2;
        ldm_x4(qfh[kf], sb + AQ_H + off);
        ldm_x4(qfl[kf], sb + AQ_L + off);
    }

    float o[16][4];
#pragma unroll
    for (int nt = 0; nt < 16; nt++)
#pragma unroll
        for (int i = 0; i < 4; i++) o[nt][i] = 0.f;
    float m0 = -INFINITY, m1 = -INFINITY, l0 = 0.f, l1 = 0.f;

    const int NI = S_LEN / 32;            // 64

    for (int it = 0; it < NI; it++) {
        if (it + 1 < NI) {
            issue_kv((it + 1) & 1, (it + 1) * 32);
            asm volatile("cp.async.wait_group 1;" ::: "memory");
        } else {
            asm volatile("cp.async.wait_group 0;" ::: "memory");
        }
        __syncthreads();

        const uint32_t sk = sb + AKV + (it & 1) * KV_STG;

        // ---- S = Q K^T (3-term split) ----
        float s[4][4];
#pragma unroll
        for (int nt = 0; nt < 4; nt++)
#pragma unroll
            for (int i = 0; i < 4; i++) s[nt][i] = 0.f;

#pragma unroll
        for (int kf = 0; kf < 8; kf++) {
#pragma unroll
            for (int nt = 0; nt < 4; nt++) {
                uint32_t bh[2], bl[2];
                uint32_t off = ((nt * 8 + (lane & 7)) * ATP + kf * 16 + (((lane >> 3) & 1) << 3)) * 2;
                ldm_x2(bh, sk + 0 * KV_TILE + off);
                ldm_x2(bl, sk + 1 * KV_TILE + off);
                mma_bf16(s[nt], qfh[kf], bh);
                mma_bf16(s[nt], qfh[kf], bl);
                mma_bf16(s[nt], qfl[kf], bh);
            }
        }

        // ---- online softmax ----
        float mx0 = -INFINITY, mx1 = -INFINITY;
#pragma unroll
        for (int nt = 0; nt < 4; nt++) {
            mx0 = fmaxf(mx0, fmaxf(s[nt][0], s[nt][1]));
            mx1 = fmaxf(mx1, fmaxf(s[nt][2], s[nt][3]));
        }
        mx0 = fmaxf(mx0, __shfl_xor_sync(0xffffffffu, mx0, 1));
        mx0 = fmaxf(mx0, __shfl_xor_sync(0xffffffffu, mx0, 2));
        mx1 = fmaxf(mx1, __shfl_xor_sync(0xffffffffu, mx1, 1));
        mx1 = fmaxf(mx1, __shfl_xor_sync(0xffffffffu, mx1, 2));

        float nm0 = fmaxf(m0, mx0), nm1 = fmaxf(m1, mx1);
        float c0 = __expf(m0 - nm0), c1 = __expf(m1 - nm1);
        m0 = nm0; m1 = nm1;

        float sum0 = 0.f, sum1 = 0.f;
#pragma unroll
        for (int nt = 0; nt < 4; nt++) {
            s[nt][0] = __expf(s[nt][0] - nm0);
            s[nt][1] = __expf(s[nt][1] - nm0);
            s[nt][2] = __expf(s[nt][2] - nm1);
            s[nt][3] = __expf(s[nt][3] - nm1);
            sum0 += s[nt][0] + s[nt][1];
            sum1 += s[nt][2] + s[nt][3];
        }
        sum0 += __shfl_xor_sync(0xffffffffu, sum0, 1);
        sum0 += __shfl_xor_sync(0xffffffffu, sum0, 2);
        sum1 += __shfl_xor_sync(0xffffffffu, sum1, 1);
        sum1 += __shfl_xor_sync(0xffffffffu, sum1, 2);
        l0 = l0 * c0 + sum0;
        l1 = l1 * c1 + sum1;

#pragma unroll
        for (int nt = 0; nt < 16; nt++) {
            o[nt][0] *= c0; o[nt][1] *= c0;
            o[nt][2] *= c1; o[nt][3] *= c1;
        }

        // ---- O += P V (3-term split) ----
#pragma unroll
        for (int kf = 0; kf < 2; kf++) {
            uint32_t ah[4], al[4];
#pragma unroll
            for (int half = 0; half < 2; half++) {
                int nt = 2 * kf + half;
                uint32_t p01 = pack_bf2(s[nt][0], s[nt][1]);
                uint32_t p23 = pack_bf2(s[nt][2], s[nt][3]);
                float h0 = __uint_as_float(p01 << 16);
                float h1 = __uint_as_float(p01 & 0xffff0000u);
                float h2 = __uint_as_float(p23 << 16);
                float h3 = __uint_as_float(p23 & 0xffff0000u);
                uint32_t q01 = pack_bf2(s[nt][0] - h0, s[nt][1] - h1);
                uint32_t q23 = pack_bf2(s[nt][2] - h2, s[nt][3] - h3);
                ah[2 * half]     = p01;
                ah[2 * half + 1] = p23;
                al[2 * half]     = q01;
                al[2 * half + 1] = q23;
            }
#pragma unroll
            for (int nt = 0; nt < 16; nt++) {
                uint32_t bh[2], bl[2];
                uint32_t off = ((kf * 16 + (lane & 15)) * ATP + nt * 8) * 2;
                ldm_x2_t(bh, sk + 2 * KV_TILE + off);
                ldm_x2_t(bl, sk + 3 * KV_TILE + off);
                mma_bf16(o[nt], ah, bh);
                mma_bf16(o[nt], ah, bl);
                mma_bf16(o[nt], al, bh);
            }
        }
        __syncthreads();
    }

    // ---- epilogue: ctx hi/lo bf16 ----
    float inv0 = 1.f / l0, inv1 = 1.f / l1;
    int r_lo = r0 + warp * 16 + (lane >> 2);
    int r_hi = r_lo + 8;
#pragma unroll
    for (int nt = 0; nt < 16; nt++) {
        int col = h * HD + nt * 8 + ((lane & 3) << 1);
        {
            float x0 = o[nt][0] * inv0, x1 = o[nt][1] * inv0;
            uint32_t ph = pack_bf2(x0, x1);
            float h0 = __uint_as_float(ph << 16);
            float h1 = __uint_as_float(ph & 0xffff0000u);
            uint32_t pl = pack_bf2(x0 - h0, x1 - h1);
            *(uint32_t*)(ctxh + (size_t)r_lo * NQD + col) = ph;
            *(uint32_t*)(ctxl + (size_t)r_lo * NQD + col) = pl;
        }
        {
            float x0 = o[nt][2] * inv1, x1 = o[nt][3] * inv1;
            uint32_t ph = pack_bf2(x0, x1);
            float h0 = __uint_as_float(ph << 16);
            float h1 = __uint_as_float(ph & 0xffff0000u);
            uint32_t pl = pack_bf2(x0 - h0, x1 - h1);
            *(uint32_t*)(ctxh + (size_t)r_hi * NQD + col) = ph;
            *(uint32_t*)(ctxl + (size_t)r_hi * NQD + col) = pl;
        }
    }
}

// ---------------- launch ----------------
extern "C" void kernel_launch(void* const* d_in, const int* in_sizes, int n_in,
                              void* d_out, int out_size) {
    const float* hs   = (const float*)d_in[0];
    const float* cosp = (const float*)d_in[1];
    const float* sinp = (const float*)d_in[2];
    const float* Wq   = (const float*)d_in[3];
    const float* bq   = (const float*)d_in[4];
    const float* Wk   = (const float*)d_in[5];
    const float* bk   = (const float*)d_in[6];
    const float* Wv   = (const float*)d_in[7];
    const float* bv   = (const float*)d_in[8];
    const float* Wo   = (const float*)d_in[9];
    float* out = (float*)d_out;

    float *qkv_p, *bias_p;
    cudaGetSymbolAddress((void**)&qkv_p,  g_qkv);
    cudaGetSymbolAddress((void**)&bias_p, g_bias);

    __nv_bfloat16 *hsh, *hsl, *ctxh, *ctxl, *wh, *wl, *woh, *wol;
    __nv_bfloat16 *qh, *ql, *kh, *kl, *vh, *vl;
    cudaGetSymbolAddress((void**)&hsh,  g_hsh);  cudaGetSymbolAddress((void**)&hsl,  g_hsl);
    cudaGetSymbolAddress((void**)&ctxh, g_ctxh); cudaGetSymbolAddress((void**)&ctxl, g_ctxl);
    cudaGetSymbolAddress((void**)&wh,   g_wh);   cudaGetSymbolAddress((void**)&wl,   g_wl);
    cudaGetSymbolAddress((void**)&woh,  g_woh);  cudaGetSymbolAddress((void**)&wol,  g_wol);
    cudaGetSymbolAddress((void**)&qh,   g_qh);   cudaGetSymbolAddress((void**)&ql,   g_ql);
    cudaGetSymbolAddress((void**)&kh,   g_kh);   cudaGetSymbolAddress((void**)&kl,   g_kl);
    cudaGetSymbolAddress((void**)&vh,   g_vh);   cudaGetSymbolAddress((void**)&vl,   g_vl);

    cudaFuncSetAttribute(gemm_mma, cudaFuncAttributeMaxDynamicSharedMemorySize, GEMM_SMEM);
    cudaFuncSetAttribute(attn_mma, cudaFuncAttributeMaxDynamicSharedMemorySize, ATTN_SMEM);

    // 1) input split + weight transposes/splits (QKV concatenated) + bias concat
    {
        int n4 = S_LEN * HID / 4;
        split_kernel<<<(n4 + 255) / 256, 256>>>((const float4*)hs, (__nv_bfloat162*)hsh, (__nv_bfloat162*)hsl, n4);
    }
    {
        dim3 blk(32, 8);
        tsplit_kernel<<<dim3(NQD / 32, HID / 32), blk>>>(Wq, wh, wl, HID, NQD);
        tsplit_kernel<<<dim3(NKD / 32, HID / 32), blk>>>(Wk, wh + (size_t)NQD * HID, wl + (size_t)NQD * HID, HID, NKD);
        tsplit_kernel<<<dim3(NKD / 32, HID / 32), blk>>>(Wv, wh + (size_t)(NQD + NKD) * HID, wl + (size_t)(NQD + NKD) * HID, HID, NKD);
        tsplit_kernel<<<dim3(HID / 32, NQD / 32), blk>>>(Wo, woh, wol, NQD, HID);
        concat_bias_kernel<<<(NQKV + 255) / 256, 256>>>(bq, bk, bv, bias_p);
    }

    // 2) fused QKV projection
    gemm_mma<<<dim3(NQKV / 128, S_LEN / 128), 256, GEMM_SMEM>>>(hsh, hsl, wh, wl, bias_p, qkv_p, HID, NQKV);

    // 3) fused mROPE + hi/lo split (scale folded into q)
    rope_split_kernel<<<S_LEN, 256>>>(qkv_p, cosp, sinp, qh, ql, kh, kl, vh, vl);

    // 4) attention -> ctx (hi/lo bf16 directly)
    {
        dim3 grid(S_LEN / 128, NH);
        attn_mma<<<grid, 256, ATTN_SMEM>>>(qh, ql, kh, kl, vh, vl, ctxh, ctxl);
    }

    // 5) output projection
    gemm_mma<<<dim3(HID / 128, S_LEN / 128), 256, GEMM_SMEM>>>(ctxh, ctxl, woh, wol, nullptr, out, NQD, HID);
}

// round 7
// speedup vs baseline: 3.4235x; 1.0532x over previous
#include <cuda_runtime.h>
#include <cuda_bf16.h>
#include <math.h>
#include <stdint.h>

// ---------------- problem constants ----------------
#define S_LEN 2048
#define HID   3584
#define NH    28
#define NKV   4
#define HD    128
#define NQD   (NH*HD)    // 3584
#define NKD   (NKV*HD)   // 512
#define GRP   (NH/NKV)   // 7
#define NQKV  (NQD + 2*NKD)  // 4608

// ---------------- scratch (device globals; no allocs allowed) ----------------
__device__ float g_qkv[(size_t)S_LEN * NQKV];
__device__ float g_bias[NQKV];

// bf16 hi/lo splits (16B-aligned for cp.async / vector access)
__device__ __align__(16) __nv_bfloat16 g_hsh[S_LEN * HID],  g_hsl[S_LEN * HID];
__device__ __align__(16) __nv_bfloat16 g_ctxh[S_LEN * NQD], g_ctxl[S_LEN * NQD];
__device__ __align__(16) __nv_bfloat16 g_qh[S_LEN * NQD],   g_ql[S_LEN * NQD];
__device__ __align__(16) __nv_bfloat16 g_kh[S_LEN * NKD],   g_kl[S_LEN * NKD];
__device__ __align__(16) __nv_bfloat16 g_vh[S_LEN * NKD],   g_vl[S_LEN * NKD];
// transposed weights [N, K]; QKV concatenated along N
__device__ __align__(16) __nv_bfloat16 g_wh[(size_t)NQKV * HID], g_wl[(size_t)NQKV * HID];
__device__ __align__(16) __nv_bfloat16 g_woh[(size_t)HID * NQD], g_wol[(size_t)HID * NQD];

// ---------------- helpers ----------------
__device__ __forceinline__ uint32_t smem_u32(const void* p) {
    uint32_t a;
    asm("{ .reg .u64 t; cvta.to.shared.u64 t, %1; cvt.u32.u64 %0, t; }" : "=r"(a) : "l"(p));
    return a;
}

__device__ __forceinline__ void cp_async16(uint32_t dst, const void* src) {
    asm volatile("cp.async.cg.shared.global [%0], [%1], 16;" :: "r"(dst), "l"(src) : "memory");
}

__device__ __forceinline__ void ldm_x4(uint32_t* r, uint32_t addr) {
    asm volatile("ldmatrix.sync.aligned.m8n8.x4.shared.b16 {%0,%1,%2,%3}, [%4];"
                 : "=r"(r[0]), "=r"(r[1]), "=r"(r[2]), "=r"(r[3]) : "r"(addr));
}

__device__ __forceinline__ void ldm_x2(uint32_t* r, uint32_t addr) {
    asm volatile("ldmatrix.sync.aligned.m8n8.x2.shared.b16 {%0,%1}, [%2];"
                 : "=r"(r[0]), "=r"(r[1]) : "r"(addr));
}

__device__ __forceinline__ void ldm_x2_t(uint32_t* r, uint32_t addr) {
    asm volatile("ldmatrix.sync.aligned.m8n8.x2.trans.shared.b16 {%0,%1}, [%2];"
                 : "=r"(r[0]), "=r"(r[1]) : "r"(addr));
}

__device__ __forceinline__ void mma_bf16(float* c, const uint32_t* a, const uint32_t* b) {
    asm volatile(
        "mma.sync.aligned.m16n8k16.row.col.f32.bf16.bf16.f32 "
        "{%0,%1,%2,%3}, {%4,%5,%6,%7}, {%8,%9}, {%0,%1,%2,%3};"
        : "+f"(c[0]), "+f"(c[1]), "+f"(c[2]), "+f"(c[3])
        : "r"(a[0]), "r"(a[1]), "r"(a[2]), "r"(a[3]), "r"(b[0]), "r"(b[1]));
}

__device__ __forceinline__ uint32_t pack_bf2(float lo, float hi) {
    uint32_t r;
    asm("cvt.rn.bf16x2.f32 %0, %1, %2;" : "=r"(r) : "f"(hi), "f"(lo));
    return r;
}

__device__ __forceinline__ void wsplit(__nv_bfloat16* H, __nv_bfloat16* L, size_t idx, float x) {
    __nv_bfloat16 h = __float2bfloat16(x);
    H[idx] = h;
    L[idx] = __float2bfloat16(x - __bfloat162float(h));
}

// ---------------- split kernels ----------------
__global__ void split_kernel(const float4* __restrict__ X, __nv_bfloat162* __restrict__ H,
                             __nv_bfloat162* __restrict__ L, int n4) {
    int i = blockIdx.x * 256 + threadIdx.x;
    if (i >= n4) return;
    float4 x = X[i];
    __nv_bfloat16 h0 = __float2bfloat16(x.x), h1 = __float2bfloat16(x.y);
    __nv_bfloat16 h2 = __float2bfloat16(x.z), h3 = __float2bfloat16(x.w);
    H[2*i]   = __halves2bfloat162(h0, h1);
    H[2*i+1] = __halves2bfloat162(h2, h3);
    L[2*i]   = __halves2bfloat162(__float2bfloat16(x.x - __bfloat162float(h0)),
                                  __float2bfloat16(x.y - __bfloat162float(h1)));
    L[2*i+1] = __halves2bfloat162(__float2bfloat16(x.z - __bfloat162float(h2)),
                                  __float2bfloat16(x.w - __bfloat162float(h3)));
}

// W [K, N] row-major -> Th/Tl [N, K]
__global__ void tsplit_kernel(const float* __restrict__ W, __nv_bfloat16* __restrict__ Th,
                              __nv_bfloat16* __restrict__ Tl, int K, int N) {
    __shared__ float t[32][33];
    int n0 = blockIdx.x * 32, k0 = blockIdx.y * 32;
    int tx = threadIdx.x, ty = threadIdx.y;   // 32 x 8
#pragma unroll
    for (int i = 0; i < 4; i++) {
        int k = k0 + ty + i * 8;
        t[ty + i * 8][tx] = W[(size_t)k * N + n0 + tx];
    }
    __syncthreads();
#pragma unroll
    for (int i = 0; i < 4; i++) {
        int n = n0 + ty + i * 8;
        float v = t[tx][ty + i * 8];
        __nv_bfloat16 h = __float2bfloat16(v);
        Th[(size_t)n * K + k0 + tx] = h;
        Tl[(size_t)n * K + k0 + tx] = __float2bfloat16(v - __bfloat162float(h));
    }
}

__global__ void concat_bias_kernel(const float* __restrict__ bq, const float* __restrict__ bk,
                                   const float* __restrict__ bv, float* __restrict__ b) {
    int i = blockIdx.x * 256 + threadIdx.x;
    if (i < NQD) b[i] = bq[i];
    else if (i < NQD + NKD) b[i] = bk[i - NQD];
    else if (i < NQKV) b[i] = bv[i - NQD - NKD];
}

// ---------------- mma.sync GEMM ----------------
// CTA tile 128x128, BK=32, 8 warps (2m x 4n). 2 CTAs/SM via launch bounds.
// ROWP=40 keeps row stride 80B -> every (row, c*8) chunk 16B-aligned for cp.async.
#define GBK 32
#define ROWP 40
#define STG_TILE (128*ROWP*2)          // 10240 B per operand tile
#define STG_BYTES (4*STG_TILE)         // 40960 B per stage
#define GEMM_SMEM (2*STG_BYTES)        // 81920 B

__global__ __launch_bounds__(256, 2)
void gemm_mma(const __nv_bfloat16* __restrict__ Ah, const __nv_bfloat16* __restrict__ Al,
              const __nv_bfloat16* __restrict__ Bh, const __nv_bfloat16* __restrict__ Bl,
              const float* __restrict__ bias, float* __restrict__ C, int K, int Ntot) {
    extern __shared__ char smem[];
    const uint32_t sb = smem_u32(smem);
    const int tid = threadIdx.x;
    const int lane = tid & 31;
    const int warp = tid >> 5;
    const int wm = (warp >> 2) * 64;
    const int wn = (warp & 3) * 32;
    const int row0 = blockIdx.y * 128;
    const int col0 = blockIdx.x * 128;
    const int NI = K / GBK;

    float acc[4][4][4];
#pragma unroll
    for (int mt = 0; mt < 4; mt++)
#pragma unroll
        for (int nt = 0; nt < 4; nt++)
#pragma unroll
            for (int i = 0; i < 4; i++) acc[mt][nt][i] = 0.f;

    auto issue_load = [&](int stage, int kb) {
        uint32_t sbase = sb + stage * STG_BYTES;
#pragma unroll
        for (int tile = 0; tile < 4; tile++) {
            const __nv_bfloat16* src =
                (tile == 0) ? Ah : (tile == 1) ? Al : (tile == 2) ? Bh : Bl;
            int gbase = (tile < 2) ? row0 : col0;
#pragma unroll
            for (int j = 0; j < 2; j++) {
                int s = j * 256 + tid;
                int row = s >> 2;
                int c = (s & 3) << 3;
                const void* g = src + (size_t)(gbase + row) * K + kb + c;
                uint32_t dst = sbase + tile * STG_TILE + (row * ROWP + c) * 2;
                cp_async16(dst, g);
            }
        }
        asm volatile("cp.async.commit_group;" ::: "memory");
    };

    issue_load(0, 0);

    for (int i = 0; i < NI; i++) {
        if (i + 1 < NI) {
            issue_load((i + 1) & 1, (i + 1) * GBK);
            asm volatile("cp.async.wait_group 1;" ::: "memory");
        } else {
            asm volatile("cp.async.wait_group 0;" ::: "memory");
        }
        __syncthreads();

        const uint32_t sa = sb + (i & 1) * STG_BYTES;
#pragma unroll
        for (int ks = 0; ks < 2; ks++) {
            uint32_t bh[4][2], bl[4][2];
#pragma unroll
            for (int nt = 0; nt < 4; nt++) {
                uint32_t addr = sa + 2 * STG_TILE +
                    ((wn + nt * 8 + (lane & 7)) * ROWP + ks * 16 + (((lane >> 3) & 1) << 3)) * 2;
                ldm_x2(bh[nt], addr);
                ldm_x2(bl[nt], addr + STG_TILE);
            }
#pragma unroll
            for (int mt = 0; mt < 4; mt++) {
                uint32_t ah[4], al[4];
                uint32_t addr = sa +
                    ((wm + mt * 16 + (lane & 15)) * ROWP + ks * 16 + ((lane >> 4) << 3)) * 2;
                ldm_x4(ah, addr);
                ldm_x4(al, addr + STG_TILE);
#pragma unroll
                for (int nt = 0; nt < 4; nt++) {
                    mma_bf16(acc[mt][nt], ah, bh[nt]);
                    mma_bf16(acc[mt][nt], ah, bl[nt]);
                    mma_bf16(acc[mt][nt], al, bh[nt]);
                }
            }
        }
        __syncthreads();
    }

#pragma unroll
    for (int mt = 0; mt < 4; mt++) {
#pragma unroll
        for (int nt = 0; nt < 4; nt++) {
            int r = row0 + wm + mt * 16 + (lane >> 2);
            int cidx = col0 + wn + nt * 8 + ((lane & 3) << 1);
            float b0 = 0.f, b1 = 0.f;
            if (bias) { b0 = bias[cidx]; b1 = bias[cidx + 1]; }
            float2* p0 = (float2*)(C + (size_t)r * Ntot + cidx);
            float2* p1 = (float2*)(C + (size_t)(r + 8) * Ntot + cidx);
            *p0 = make_float2(acc[mt][nt][0] + b0, acc[mt][nt][1] + b1);
            *p1 = make_float2(acc[mt][nt][2] + b0, acc[mt][nt][3] + b1);
        }
    }
}

// ---------------- fused mROPE + hi/lo split ----------------
__global__ __launch_bounds__(256)
void rope_split_kernel(const float* __restrict__ qkv,
                       const float* __restrict__ cosp, const float* __restrict__ sinp,
                       __nv_bfloat16* __restrict__ qh, __nv_bfloat16* __restrict__ ql,
                       __nv_bfloat16* __restrict__ kh, __nv_bfloat16* __restrict__ kl,
                       __nv_bfloat16* __restrict__ vh, __nv_bfloat16* __restrict__ vl) {
    const int s = blockIdx.x;
    const int tid = threadIdx.x;
    const int d = tid & 63;
    const int grp = tid >> 6;             // 0..3
    const int d2 = d + 64;
    const int sec = (d < 16) ? 0 : ((d < 40) ? 1 : 2);
    const int SH = S_LEN * HD;
    const float scale = 0.08838834764831845f;   // 1/sqrt(128)

    const float c1 = cosp[sec * SH + s * HD + d];
    const float s1 = sinp[sec * SH + s * HD + d];
    const float c2 = cosp[sec * SH + s * HD + d2];
    const float s2 = sinp[sec * SH + s * HD + d2];

    const float* row = qkv + (size_t)s * NQKV;

#pragma unroll 1
    for (int it = 0; it < 9; it++) {
        int hh = it * 4 + grp;    // 0..35
        if (hh < NH) {
            const float* base = row + hh * HD;
            float x1 = base[d], x2 = base[d2];
            float y1 = (x1 * c1 - x2 * s1) * scale;
            float y2 = (x2 * c2 + x1 * s2) * scale;
            size_t o = (size_t)s * NQD + hh * HD;
            wsplit(qh, ql, o + d, y1);
            wsplit(qh, ql, o + d2, y2);
        } else if (hh < NH + NKV) {
            int kvi = hh - NH;
            const float* base = row + NQD + kvi * HD;
            float x1 = base[d], x2 = base[d2];
            float y1 = x1 * c1 - x2 * s1;
            float y2 = x2 * c2 + x1 * s2;
            size_t o = (size_t)s * NKD + kvi * HD;
            wsplit(kh, kl, o + d, y1);
            wsplit(kh, kl, o + d2, y2);
        } else {
            int kvi = hh - NH - NKV;
            const float* base = row + NQD + NKD + kvi * HD;
            size_t o = (size_t)s * NKD + kvi * HD;
            wsplit(vh, vl, o + d, base[d]);
            wsplit(vh, vl, o + d2, base[d2]);
        }
    }
}

// ---------------- attention: mma.sync flash, 128 q-rows/CTA, pipelined KV ----------------
#define ATP 136
#define AT_ROWB (ATP*2)              // 272 B/row
#define AQ_TILE (128*AT_ROWB)        // 34816
#define KV_TILE (32*AT_ROWB)         // 8704
#define KV_STG  (4*KV_TILE)          // 34816 (Kh,Kl,Vh,Vl)
#define AQ_H 0
#define AQ_L AQ_TILE
#define AKV  (2*AQ_TILE)
#define ATTN_SMEM (AKV + 2*KV_STG)   // 139264 B

__global__ __launch_bounds__(256)
void attn_mma(const __nv_bfloat16* __restrict__ qh, const __nv_bfloat16* __restrict__ ql,
              const __nv_bfloat16* __restrict__ kh, const __nv_bfloat16* __restrict__ kl,
              const __nv_bfloat16* __restrict__ vh, const __nv_bfloat16* __restrict__ vl,
              __nv_bfloat16* __restrict__ ctxh, __nv_bfloat16* __restrict__ ctxl) {
    extern __shared__ char smem[];
    const uint32_t sb = smem_u32(smem);
    const int tid = threadIdx.x;
    const int lane = tid & 31;
    const int warp = tid >> 5;           // 0..7
    const int h = blockIdx.y;
    const int kvh = h / GRP;
    const int r0 = blockIdx.x * 128;

    // ---- Q tile (128 x 128) hi/lo ----
#pragma unroll
    for (int j = 0; j < 8; j++) {
        int idx = j * 256 + tid;          // 0..2047
        int row = idx >> 4, c = idx & 15;
        size_t g = (size_t)(r0 + row) * NQD + h * HD + c * 8;
        uint32_t so = row * AT_ROWB + c * 16;
        cp_async16(sb + AQ_H + so, qh + g);
        cp_async16(sb + AQ_L + so, ql + g);
    }
    asm volatile("cp.async.commit_group;" ::: "memory");

    auto issue_kv = [&](int stage, int kt) {
        uint32_t base = sb + AKV + stage * KV_STG;
#pragma unroll
        for (int j = 0; j < 2; j++) {
            int idx = j * 256 + tid;      // 0..511
            int row = idx >> 4, c = idx & 15;
            size_t g = (size_t)(kt + row) * NKD + kvh * HD + c * 8;
            uint32_t so = row * AT_ROWB + c * 16;
            cp_async16(base + 0 * KV_TILE + so, kh + g);
            cp_async16(base + 1 * KV_TILE + so, kl + g);
            cp_async16(base + 2 * KV_TILE + so, vh + g);
            cp_async16(base + 3 * KV_TILE + so, vl + g);
        }
        asm volatile("cp.async.commit_group;" ::: "memory");
    };

    issue_kv(0, 0);
    asm volatile("cp.async.wait_group 1;" ::: "memory");   // Q done (kv0 may pend)
    __syncthreads();

    // ---- Q fragments (warp owns rows [warp*16, warp*16+16)) ----
    uint32_t qfh[8][4], qfl[8][4];
#pragma unroll
    for (int kf = 0; kf < 8; kf++) {
        uint32_t off = ((warp * 16 + (lane & 15)) * ATP + kf * 16 + ((lane >> 4) << 3)) * 2;
        ldm_x4(qfh[kf], sb + AQ_H + off);
        ldm_x4(qfl[kf], sb + AQ_L + off);
    }

    float o[16][4];
#pragma unroll
    for (int nt = 0; nt < 16; nt++)
#pragma unroll
        for (int i = 0; i < 4; i++) o[nt][i] = 0.f;
    float m0 = -INFINITY, m1 = -INFINITY, l0 = 0.f, l1 = 0.f;

    const int NI = S_LEN / 32;            // 64

    for (int it = 0; it < NI; it++) {
        if (it + 1 < NI) {
            issue_kv((it + 1) & 1, (it + 1) * 32);
            asm volatile("cp.async.wait_group 1;" ::: "memory");
        } else {
            asm volatile("cp.async.wait_group 0;" ::: "memory");
        }
        __syncthreads();

        const uint32_t sk = sb + AKV + (it & 1) * KV_STG;

        // ---- S = Q K^T (3-term split) ----
        float s[4][4];
#pragma unroll
        for (int nt = 0; nt < 4; nt++)
#pragma unroll
            for (int i = 0; i < 4; i++) s[nt][i] = 0.f;

#pragma unroll
        for (int kf = 0; kf < 8; kf++) {
#pragma unroll
            for (int nt = 0; nt < 4; nt++) {
                uint32_t bh[2], bl[2];
                uint32_t off = ((nt * 8 + (lane & 7)) * ATP + kf * 16 + (((lane >> 3) & 1) << 3)) * 2;
                ldm_x2(bh, sk + 0 * KV_TILE + off);
                ldm_x2(bl, sk + 1 * KV_TILE + off);
                mma_bf16(s[nt], qfh[kf], bh);
                mma_bf16(s[nt], qfh[kf], bl);
                mma_bf16(s[nt], qfl[kf], bh);
            }
        }

        // ---- online softmax ----
        float mx0 = -INFINITY, mx1 = -INFINITY;
#pragma unroll
        for (int nt = 0; nt < 4; nt++) {
            mx0 = fmaxf(mx0, fmaxf(s[nt][0], s[nt][1]));
            mx1 = fmaxf(mx1, fmaxf(s[nt][2], s[nt][3]));
        }
        mx0 = fmaxf(mx0, __shfl_xor_sync(0xffffffffu, mx0, 1));
        mx0 = fmaxf(mx0, __shfl_xor_sync(0xffffffffu, mx0, 2));
        mx1 = fmaxf(mx1, __shfl_xor_sync(0xffffffffu, mx1, 1));
        mx1 = fmaxf(mx1, __shfl_xor_sync(0xffffffffu, mx1, 2));

        float nm0 = fmaxf(m0, mx0), nm1 = fmaxf(m1, mx1);
        float c0 = __expf(m0 - nm0), c1 = __expf(m1 - nm1);
        m0 = nm0; m1 = nm1;

        float sum0 = 0.f, sum1 = 0.f;
#pragma unroll
        for (int nt = 0; nt < 4; nt++) {
            s[nt][0] = __expf(s[nt][0] - nm0);
            s[nt][1] = __expf(s[nt][1] - nm0);
            s[nt][2] = __expf(s[nt][2] - nm1);
            s[nt][3] = __expf(s[nt][3] - nm1);
            sum0 += s[nt][0] + s[nt][1];
            sum1 += s[nt][2] + s[nt][3];
        }
        sum0 += __shfl_xor_sync(0xffffffffu, sum0, 1);
        sum0 += __shfl_xor_sync(0xffffffffu, sum0, 2);
        sum1 += __shfl_xor_sync(0xffffffffu, sum1, 1);
        sum1 += __shfl_xor_sync(0xffffffffu, sum1, 2);
        l0 = l0 * c0 + sum0;
        l1 = l1 * c1 + sum1;

#pragma unroll
        for (int nt = 0; nt < 16; nt++) {
            o[nt][0] *= c0; o[nt][1] *= c0;
            o[nt][2] *= c1; o[nt][3] *= c1;
        }

        // ---- O += P V (3-term split) ----
#pragma unroll
        for (int kf = 0; kf < 2; kf++) {
            uint32_t ah[4], al[4];
#pragma unroll
            for (int half = 0; half < 2; half++) {
                int nt = 2 * kf + half;
                uint32_t p01 = pack_bf2(s[nt][0], s[nt][1]);
                uint32_t p23 = pack_bf2(s[nt][2], s[nt][3]);
                float h0 = __uint_as_float(p01 << 16);
                float h1 = __uint_as_float(p01 & 0xffff0000u);
                float h2 = __uint_as_float(p23 << 16);
                float h3 = __uint_as_float(p23 & 0xffff0000u);
                uint32_t q01 = pack_bf2(s[nt][0] - h0, s[nt][1] - h1);
                uint32_t q23 = pack_bf2(s[nt][2] - h2, s[nt][3] - h3);
                ah[2 * half]     = p01;
                ah[2 * half + 1] = p23;
                al[2 * half]     = q01;
                al[2 * half + 1] = q23;
            }
#pragma unroll
            for (int nt = 0; nt < 16; nt++) {
                uint32_t bh[2], bl[2];
                uint32_t off = ((kf * 16 + (lane & 15)) * ATP + nt * 8) * 2;
                ldm_x2_t(bh, sk + 2 * KV_TILE + off);
                ldm_x2_t(bl, sk + 3 * KV_TILE + off);
                mma_bf16(o[nt], ah, bh);
                mma_bf16(o[nt], ah, bl);
                mma_bf16(o[nt], al, bh);
            }
        }
        __syncthreads();
    }

    // ---- epilogue: ctx hi/lo bf16 ----
    float inv0 = 1.f / l0, inv1 = 1.f / l1;
    int r_lo = r0 + warp * 16 + (lane >> 2);
    int r_hi = r_lo + 8;
#pragma unroll
    for (int nt = 0; nt < 16; nt++) {
        int col = h * HD + nt * 8 + ((lane & 3) << 1);
        {
            float x0 = o[nt][0] * inv0, x1 = o[nt][1] * inv0;
            uint32_t ph = pack_bf2(x0, x1);
            float h0 = __uint_as_float(ph << 16);
            float h1 = __uint_as_float(ph & 0xffff0000u);
            uint32_t pl = pack_bf2(x0 - h0, x1 - h1);
            *(uint32_t*)(ctxh + (size_t)r_lo * NQD + col) = ph;
            *(uint32_t*)(ctxl + (size_t)r_lo * NQD + col) = pl;
        }
        {
            float x0 = o[nt][2] * inv1, x1 = o[nt][3] * inv1;
            uint32_t ph = pack_bf2(x0, x1);
            float h0 = __uint_as_float(ph << 16);
            float h1 = __uint_as_float(ph & 0xffff0000u);
            uint32_t pl = pack_bf2(x0 - h0, x1 - h1);
            *(uint32_t*)(ctxh + (size_t)r_hi * NQD + col) = ph;
            *(uint32_t*)(ctxl + (size_t)r_hi * NQD + col) = pl;
        }
    }
}

// ---------------- launch ----------------
extern "C" void kernel_launch(void* const* d_in, const int* in_sizes, int n_in,
                              void* d_out, int out_size) {
    const float* hs   = (const float*)d_in[0];
    const float* cosp = (const float*)d_in[1];
    const float* sinp = (const float*)d_in[2];
    const float* Wq   = (const float*)d_in[3];
    const float* bq   = (const float*)d_in[4];
    const float* Wk   = (const float*)d_in[5];
    const float* bk   = (const float*)d_in[6];
    const float* Wv   = (const float*)d_in[7];
    const float* bv   = (const float*)d_in[8];
    const float* Wo   = (const float*)d_in[9];
    float* out = (float*)d_out;

    float *qkv_p, *bias_p;
    cudaGetSymbolAddress((void**)&qkv_p,  g_qkv);
    cudaGetSymbolAddress((void**)&bias_p, g_bias);

    __nv_bfloat16 *hsh, *hsl, *ctxh, *ctxl, *wh, *wl, *woh, *wol;
    __nv_bfloat16 *qh, *ql, *kh, *kl, *vh, *vl;
    cudaGetSymbolAddress((void**)&hsh,  g_hsh);  cudaGetSymbolAddress((void**)&hsl,  g_hsl);
    cudaGetSymbolAddress((void**)&ctxh, g_ctxh); cudaGetSymbolAddress((void**)&ctxl, g_ctxl);
    cudaGetSymbolAddress((void**)&wh,   g_wh);   cudaGetSymbolAddress((void**)&wl,   g_wl);
    cudaGetSymbolAddress((void**)&woh,  g_woh);  cudaGetSymbolAddress((void**)&wol,  g_wol);
    cudaGetSymbolAddress((void**)&qh,   g_qh);   cudaGetSymbolAddress((void**)&ql,   g_ql);
    cudaGetSymbolAddress((void**)&kh,   g_kh);   cudaGetSymbolAddress((void**)&kl,   g_kl);
    cudaGetSymbolAddress((void**)&vh,   g_vh);   cudaGetSymbolAddress((void**)&vl,   g_vl);

    cudaFuncSetAttribute(gemm_mma, cudaFuncAttributeMaxDynamicSharedMemorySize, GEMM_SMEM);
    cudaFuncSetAttribute(attn_mma, cudaFuncAttributeMaxDynamicSharedMemorySize, ATTN_SMEM);

    // 1) input split + weight transposes/splits (QKV concatenated) + bias concat
    {
        int n4 = S_LEN * HID / 4;
        split_kernel<<<(n4 + 255) / 256, 256>>>((const float4*)hs, (__nv_bfloat162*)hsh, (__nv_bfloat162*)hsl, n4);
    }
    {
        dim3 blk(32, 8);
        tsplit_kernel<<<dim3(NQD / 32, HID / 32), blk>>>(Wq, wh, wl, HID, NQD);
        tsplit_kernel<<<dim3(NKD / 32, HID / 32), blk>>>(Wk, wh + (size_t)NQD * HID, wl + (size_t)NQD * HID, HID, NKD);
        tsplit_kernel<<<dim3(NKD / 32, HID / 32), blk>>>(Wv, wh + (size_t)(NQD + NKD) * HID, wl + (size_t)(NQD + NKD) * HID, HID, NKD);
        tsplit_kernel<<<dim3(HID / 32, NQD / 32), blk>>>(Wo, woh, wol, NQD, HID);
        concat_bias_kernel<<<(NQKV + 255) / 256, 256>>>(bq, bk, bv, bias_p);
    }

    // 2) fused QKV projection
    gemm_mma<<<dim3(NQKV / 128, S_LEN / 128), 256, GEMM_SMEM>>>(hsh, hsl, wh, wl, bias_p, qkv_p, HID, NQKV);

    // 3) fused mROPE + hi/lo split (scale folded into q)
    rope_split_kernel<<<S_LEN, 256>>>(qkv_p, cosp, sinp, qh, ql, kh, kl, vh, vl);

    // 4) attention -> ctx (hi/lo bf16 directly)
    {
        dim3 grid(S_LEN / 128, NH);
        attn_mma<<<grid, 256, ATTN_SMEM>>>(qh, ql, kh, kl, vh, vl, ctxh, ctxl);
    }

    // 5) output projection
    gemm_mma<<<dim3(HID / 128, S_LEN / 128), 256, GEMM_SMEM>>>(ctxh, ctxl, woh, wol, nullptr, out, NQD, HID);
}

// round 8
// speedup vs baseline: 3.5679x; 1.0422x over previous
#include <cuda_runtime.h>
#include <cuda_bf16.h>
#include <math.h>
#include <stdint.h>

// ---------------- problem constants ----------------
#define S_LEN 2048
#define HID   3584
#define NH    28
#define NKV   4
#define HD    128
#define NQD   (NH*HD)    // 3584
#define NKD   (NKV*HD)   // 512
#define GRP   (NH/NKV)   // 7
#define NQKV  (NQD + 2*NKD)  // 4608

// ---------------- scratch (device globals; no allocs allowed) ----------------
__device__ float g_qkv[(size_t)S_LEN * NQKV];
__device__ float g_bias[NQKV];

__device__ __align__(16) __nv_bfloat16 g_hsh[S_LEN * HID],  g_hsl[S_LEN * HID];
__device__ __align__(16) __nv_bfloat16 g_ctxh[S_LEN * NQD], g_ctxl[S_LEN * NQD];
__device__ __align__(16) __nv_bfloat16 g_qh[S_LEN * NQD],   g_ql[S_LEN * NQD];
__device__ __align__(16) __nv_bfloat16 g_kh[S_LEN * NKD],   g_kl[S_LEN * NKD];
__device__ __align__(16) __nv_bfloat16 g_vh[S_LEN * NKD],   g_vl[S_LEN * NKD];
__device__ __align__(16) __nv_bfloat16 g_wh[(size_t)NQKV * HID], g_wl[(size_t)NQKV * HID];
__device__ __align__(16) __nv_bfloat16 g_woh[(size_t)HID * NQD], g_wol[(size_t)HID * NQD];

// ---------------- helpers ----------------
__device__ __forceinline__ uint32_t smem_u32(const void* p) {
    uint32_t a;
    asm("{ .reg .u64 t; cvta.to.shared.u64 t, %1; cvt.u32.u64 %0, t; }" : "=r"(a) : "l"(p));
    return a;
}

__device__ __forceinline__ void cp_async16(uint32_t dst, const void* src) {
    asm volatile("cp.async.cg.shared.global [%0], [%1], 16;" :: "r"(dst), "l"(src) : "memory");
}

__device__ __forceinline__ void ldm_x4(uint32_t* r, uint32_t addr) {
    asm volatile("ldmatrix.sync.aligned.m8n8.x4.shared.b16 {%0,%1,%2,%3}, [%4];"
                 : "=r"(r[0]), "=r"(r[1]), "=r"(r[2]), "=r"(r[3]) : "r"(addr));
}

__device__ __forceinline__ void ldm_x4_t(uint32_t* r, uint32_t addr) {
    asm volatile("ldmatrix.sync.aligned.m8n8.x4.trans.shared.b16 {%0,%1,%2,%3}, [%4];"
                 : "=r"(r[0]), "=r"(r[1]), "=r"(r[2]), "=r"(r[3]) : "r"(addr));
}

__device__ __forceinline__ void mma_bf16(float* c, const uint32_t* a, const uint32_t* b) {
    asm volatile(
        "mma.sync.aligned.m16n8k16.row.col.f32.bf16.bf16.f32 "
        "{%0,%1,%2,%3}, {%4,%5,%6,%7}, {%8,%9}, {%0,%1,%2,%3};"
        : "+f"(c[0]), "+f"(c[1]), "+f"(c[2]), "+f"(c[3])
        : "r"(a[0]), "r"(a[1]), "r"(a[2]), "r"(a[3]), "r"(b[0]), "r"(b[1]));
}

__device__ __forceinline__ uint32_t pack_bf2(float lo, float hi) {
    uint32_t r;
    asm("cvt.rn.bf16x2.f32 %0, %1, %2;" : "=r"(r) : "f"(hi), "f"(lo));
    return r;
}

__device__ __forceinline__ void wsplit(__nv_bfloat16* H, __nv_bfloat16* L, size_t idx, float x) {
    __nv_bfloat16 h = __float2bfloat16(x);
    H[idx] = h;
    L[idx] = __float2bfloat16(x - __bfloat162float(h));
}

// ---------------- split kernels ----------------
__global__ void split_kernel(const float4* __restrict__ X, __nv_bfloat162* __restrict__ H,
                             __nv_bfloat162* __restrict__ L, int n4) {
    int i = blockIdx.x * 256 + threadIdx.x;
    if (i >= n4) return;
    float4 x = X[i];
    __nv_bfloat16 h0 = __float2bfloat16(x.x), h1 = __float2bfloat16(x.y);
    __nv_bfloat16 h2 = __float2bfloat16(x.z), h3 = __float2bfloat16(x.w);
    H[2*i]   = __halves2bfloat162(h0, h1);
    H[2*i+1] = __halves2bfloat162(h2, h3);
    L[2*i]   = __halves2bfloat162(__float2bfloat16(x.x - __bfloat162float(h0)),
                                  __float2bfloat16(x.y - __bfloat162float(h1)));
    L[2*i+1] = __halves2bfloat162(__float2bfloat16(x.z - __bfloat162float(h2)),
                                  __float2bfloat16(x.w - __bfloat162float(h3)));
}

// W [K, N] row-major -> Th/Tl [N, K]
__global__ void tsplit_kernel(const float* __restrict__ W, __nv_bfloat16* __restrict__ Th,
                              __nv_bfloat16* __restrict__ Tl, int K, int N) {
    __shared__ float t[32][33];
    int n0 = blockIdx.x * 32, k0 = blockIdx.y * 32;
    int tx = threadIdx.x, ty = threadIdx.y;   // 32 x 8
#pragma unroll
    for (int i = 0; i < 4; i++) {
        int k = k0 + ty + i * 8;
        t[ty + i * 8][tx] = W[(size_t)k * N + n0 + tx];
    }
    __syncthreads();
#pragma unroll
    for (int i = 0; i < 4; i++) {
        int n = n0 + ty + i * 8;
        float v = t[tx][ty + i * 8];
        __nv_bfloat16 h = __float2bfloat16(v);
        Th[(size_t)n * K + k0 + tx] = h;
        Tl[(size_t)n * K + k0 + tx] = __float2bfloat16(v - __bfloat162float(h));
    }
}

__global__ void concat_bias_kernel(const float* __restrict__ bq, const float* __restrict__ bk,
                                   const float* __restrict__ bv, float* __restrict__ b) {
    int i = blockIdx.x * 256 + threadIdx.x;
    if (i < NQD) b[i] = bq[i];
    else if (i < NQD + NKD) b[i] = bk[i - NQD];
    else if (i < NQKV) b[i] = bv[i - NQD - NKD];
}

// ---------------- mma.sync GEMM ----------------
#define GBK 32
#define ROWP 40
#define STG_TILE (128*ROWP*2)          // 10240 B per operand tile
#define STG_BYTES (4*STG_TILE)         // 40960 B per stage
#define GEMM_SMEM (2*STG_BYTES)        // 81920 B

__global__ __launch_bounds__(256, 2)
void gemm_mma(const __nv_bfloat16* __restrict__ Ah, const __nv_bfloat16* __restrict__ Al,
              const __nv_bfloat16* __restrict__ Bh, const __nv_bfloat16* __restrict__ Bl,
              const float* __restrict__ bias, float* __restrict__ C, int K, int Ntot) {
    extern __shared__ char smem[];
    const uint32_t sb = smem_u32(smem);
    const int tid = threadIdx.x;
    const int lane = tid & 31;
    const int warp = tid >> 5;
    const int wm = (warp >> 2) * 64;
    const int wn = (warp & 3) * 32;
    const int row0 = blockIdx.y * 128;
    const int col0 = blockIdx.x * 128;
    const int NI = K / GBK;

    float acc[4][4][4];
#pragma unroll
    for (int mt = 0; mt < 4; mt++)
#pragma unroll
        for (int nt = 0; nt < 4; nt++)
#pragma unroll
            for (int i = 0; i < 4; i++) acc[mt][nt][i] = 0.f;

    auto issue_load = [&](int stage, int kb) {
        uint32_t sbase = sb + stage * STG_BYTES;
#pragma unroll
        for (int tile = 0; tile < 4; tile++) {
            const __nv_bfloat16* src =
                (tile == 0) ? Ah : (tile == 1) ? Al : (tile == 2) ? Bh : Bl;
            int gbase = (tile < 2) ? row0 : col0;
#pragma unroll
            for (int j = 0; j < 2; j++) {
                int s = j * 256 + tid;
                int row = s >> 2;
                int c = (s & 3) << 3;
                const void* g = src + (size_t)(gbase + row) * K + kb + c;
                uint32_t dst = sbase + tile * STG_TILE + (row * ROWP + c) * 2;
                cp_async16(dst, g);
            }
        }
        asm volatile("cp.async.commit_group;" ::: "memory");
    };

    issue_load(0, 0);

    for (int i = 0; i < NI; i++) {
        if (i + 1 < NI) {
            issue_load((i + 1) & 1, (i + 1) * GBK);
            asm volatile("cp.async.wait_group 1;" ::: "memory");
        } else {
            asm volatile("cp.async.wait_group 0;" ::: "memory");
        }
        __syncthreads();

        const uint32_t sa = sb + (i & 1) * STG_BYTES;
#pragma unroll
        for (int ks = 0; ks < 2; ks++) {
            // B fragments: x4 ldmatrix fetches two n-tiles (both k-halves) at once.
            // lanes 0-7:  n-tile even, k-lo | 8-15: n-tile even, k-hi
            // lanes 16-23: n-tile odd, k-lo | 24-31: n-tile odd, k-hi
            uint32_t bh[4][2], bl[4][2];
#pragma unroll
            for (int np = 0; np < 2; np++) {
                uint32_t addr = sa + 2 * STG_TILE +
                    ((wn + np * 16 + ((lane >> 4) << 3) + (lane & 7)) * ROWP
                     + ks * 16 + (((lane >> 3) & 1) << 3)) * 2;
                ldm_x4(&bh[np * 2][0], addr);
                ldm_x4(&bl[np * 2][0], addr + STG_TILE);
            }
#pragma unroll
            for (int mt = 0; mt < 4; mt++) {
                uint32_t ah[4], al[4];
                uint32_t addr = sa +
                    ((wm + mt * 16 + (lane & 15)) * ROWP + ks * 16 + ((lane >> 4) << 3)) * 2;
                ldm_x4(ah, addr);
                ldm_x4(al, addr + STG_TILE);
#pragma unroll
                for (int nt = 0; nt < 4; nt++) {
                    mma_bf16(acc[mt][nt], ah, bh[nt]);
                    mma_bf16(acc[mt][nt], ah, bl[nt]);
                    mma_bf16(acc[mt][nt], al, bh[nt]);
                }
            }
        }
        __syncthreads();
    }

#pragma unroll
    for (int mt = 0; mt < 4; mt++) {
#pragma unroll
        for (int nt = 0; nt < 4; nt++) {
            int r = row0 + wm + mt * 16 + (lane >> 2);
            int cidx = col0 + wn + nt * 8 + ((lane & 3) << 1);
            float b0 = 0.f, b1 = 0.f;
            if (bias) { b0 = bias[cidx]; b1 = bias[cidx + 1]; }
            float2* p0 = (float2*)(C + (size_t)r * Ntot + cidx);
            float2* p1 = (float2*)(C + (size_t)(r + 8) * Ntot + cidx);
            *p0 = make_float2(acc[mt][nt][0] + b0, acc[mt][nt][1] + b1);
            *p1 = make_float2(acc[mt][nt][2] + b0, acc[mt][nt][3] + b1);
        }
    }
}

// ---------------- fused mROPE + hi/lo split ----------------
__global__ __launch_bounds__(256)
void rope_split_kernel(const float* __restrict__ qkv,
                       const float* __restrict__ cosp, const float* __restrict__ sinp,
                       __nv_bfloat16* __restrict__ qh, __nv_bfloat16* __restrict__ ql,
                       __nv_bfloat16* __restrict__ kh, __nv_bfloat16* __restrict__ kl,
                       __nv_bfloat16* __restrict__ vh, __nv_bfloat16* __restrict__ vl) {
    const int s = blockIdx.x;
    const int tid = threadIdx.x;
    const int d = tid & 63;
    const int grp = tid >> 6;             // 0..3
    const int d2 = d + 64;
    const int sec = (d < 16) ? 0 : ((d < 40) ? 1 : 2);
    const int SH = S_LEN * HD;
    const float scale = 0.08838834764831845f;   // 1/sqrt(128)

    const float c1 = cosp[sec * SH + s * HD + d];
    const float s1 = sinp[sec * SH + s * HD + d];
    const float c2 = cosp[sec * SH + s * HD + d2];
    const float s2 = sinp[sec * SH + s * HD + d2];

    const float* row = qkv + (size_t)s * NQKV;

#pragma unroll 1
    for (int it = 0; it < 9; it++) {
        int hh = it * 4 + grp;    // 0..35
        if (hh < NH) {
            const float* base = row + hh * HD;
            float x1 = base[d], x2 = base[d2];
            float y1 = (x1 * c1 - x2 * s1) * scale;
            float y2 = (x2 * c2 + x1 * s2) * scale;
            size_t o = (size_t)s * NQD + hh * HD;
            wsplit(qh, ql, o + d, y1);
            wsplit(qh, ql, o + d2, y2);
        } else if (hh < NH + NKV) {
            int kvi = hh - NH;
            const float* base = row + NQD + kvi * HD;
            float x1 = base[d], x2 = base[d2];
            float y1 = x1 * c1 - x2 * s1;
            float y2 = x2 * c2 + x1 * s2;
            size_t o = (size_t)s * NKD + kvi * HD;
            wsplit(kh, kl, o + d, y1);
            wsplit(kh, kl, o + d2, y2);
        } else {
            int kvi = hh - NH - NKV;
            const float* base = row + NQD + NKD + kvi * HD;
            size_t o = (size_t)s * NKD + kvi * HD;
            wsplit(vh, vl, o + d, base[d]);
            wsplit(vh, vl, o + d2, base[d2]);
        }
    }
}

// ---------------- attention: mma.sync flash, 128 q-rows/CTA, pipelined KV ----------------
#define ATP 136
#define AT_ROWB (ATP*2)              // 272 B/row
#define AQ_TILE (128*AT_ROWB)        // 34816
#define KV_TILE (32*AT_ROWB)         // 8704
#define KV_STG  (4*KV_TILE)          // 34816 (Kh,Kl,Vh,Vl)
#define AQ_H 0
#define AQ_L AQ_TILE
#define AKV  (2*AQ_TILE)
#define ATTN_SMEM (AKV + 2*KV_STG)   // 139264 B

__global__ __launch_bounds__(256)
void attn_mma(const __nv_bfloat16* __restrict__ qh, const __nv_bfloat16* __restrict__ ql,
              const __nv_bfloat16* __restrict__ kh, const __nv_bfloat16* __restrict__ kl,
              const __nv_bfloat16* __restrict__ vh, const __nv_bfloat16* __restrict__ vl,
              __nv_bfloat16* __restrict__ ctxh, __nv_bfloat16* __restrict__ ctxl) {
    extern __shared__ char smem[];
    const uint32_t sb = smem_u32(smem);
    const int tid = threadIdx.x;
    const int lane = tid & 31;
    const int warp = tid >> 5;           // 0..7
    const int h = blockIdx.y;
    const int kvh = h / GRP;
    const int r0 = blockIdx.x * 128;

    // ---- Q tile (128 x 128) hi/lo ----
#pragma unroll
    for (int j = 0; j < 8; j++) {
        int idx = j * 256 + tid;          // 0..2047
        int row = idx >> 4, c = idx & 15;
        size_t g = (size_t)(r0 + row) * NQD + h * HD + c * 8;
        uint32_t so = row * AT_ROWB + c * 16;
        cp_async16(sb + AQ_H + so, qh + g);
        cp_async16(sb + AQ_L + so, ql + g);
    }
    asm volatile("cp.async.commit_group;" ::: "memory");

    auto issue_kv = [&](int stage, int kt) {
        uint32_t base = sb + AKV + stage * KV_STG;
#pragma unroll
        for (int j = 0; j < 2; j++) {
            int idx = j * 256 + tid;      // 0..511
            int row = idx >> 4, c = idx & 15;
            size_t g = (size_t)(kt + row) * NKD + kvh * HD + c * 8;
            uint32_t so = row * AT_ROWB + c * 16;
            cp_async16(base + 0 * KV_TILE + so, kh + g);
            cp_async16(base + 1 * KV_TILE + so, kl + g);
            cp_async16(base + 2 * KV_TILE + so, vh + g);
            cp_async16(base + 3 * KV_TILE + so, vl + g);
        }
        asm volatile("cp.async.commit_group;" ::: "memory");
    };

    issue_kv(0, 0);
    asm volatile("cp.async.wait_group 1;" ::: "memory");   // Q done (kv0 may pend)
    __syncthreads();

    // ---- Q fragments (warp owns rows [warp*16, warp*16+16)) ----
    uint32_t qfh[8][4], qfl[8][4];
#pragma unroll
    for (int kf = 0; kf < 8; kf++) {
        uint32_t off = ((warp * 16 + (lane & 15)) * ATP + kf * 16 + ((lane >> 4) << 3)) * 2;
        ldm_x4(qfh[kf], sb + AQ_H + off);
        ldm_x4(qfl[kf], sb + AQ_L + off);
    }

    float o[16][4];
#pragma unroll
    for (int nt = 0; nt < 16; nt++)
#pragma unroll
        for (int i = 0; i < 4; i++) o[nt][i] = 0.f;
    float m0 = -INFINITY, m1 = -INFINITY, l0 = 0.f, l1 = 0.f;

    const int NI = S_LEN / 32;            // 64

    for (int it = 0; it < NI; it++) {
        if (it + 1 < NI) {
            issue_kv((it + 1) & 1, (it + 1) * 32);
            asm volatile("cp.async.wait_group 1;" ::: "memory");
        } else {
            asm volatile("cp.async.wait_group 0;" ::: "memory");
        }
        __syncthreads();

        const uint32_t sk = sb + AKV + (it & 1) * KV_STG;

        // ---- S = Q K^T (3-term split); K frags via x4 (two n-tiles per load) ----
        float s[4][4];
#pragma unroll
        for (int nt = 0; nt < 4; nt++)
#pragma unroll
            for (int i = 0; i < 4; i++) s[nt][i] = 0.f;

#pragma unroll
        for (int kf = 0; kf < 8; kf++) {
            uint32_t kbh[4][2], kbl[4][2];
#pragma unroll
            for (int np = 0; np < 2; np++) {
                uint32_t addr = sk +
                    ((np * 16 + ((lane >> 4) << 3) + (lane & 7)) * ATP
                     + kf * 16 + (((lane >> 3) & 1) << 3)) * 2;
                ldm_x4(&kbh[np * 2][0], addr);                 // K_h tile (offset 0)
                ldm_x4(&kbl[np * 2][0], addr + KV_TILE);       // K_l tile
            }
#pragma unroll
            for (int nt = 0; nt < 4; nt++) {
                mma_bf16(s[nt], qfh[kf], kbh[nt]);
                mma_bf16(s[nt], qfh[kf], kbl[nt]);
                mma_bf16(s[nt], qfl[kf], kbh[nt]);
            }
        }

        // ---- online softmax ----
        float mx0 = -INFINITY, mx1 = -INFINITY;
#pragma unroll
        for (int nt = 0; nt < 4; nt++) {
            mx0 = fmaxf(mx0, fmaxf(s[nt][0], s[nt][1]));
            mx1 = fmaxf(mx1, fmaxf(s[nt][2], s[nt][3]));
        }
        mx0 = fmaxf(mx0, __shfl_xor_sync(0xffffffffu, mx0, 1));
        mx0 = fmaxf(mx0, __shfl_xor_sync(0xffffffffu, mx0, 2));
        mx1 = fmaxf(mx1, __shfl_xor_sync(0xffffffffu, mx1, 1));
        mx1 = fmaxf(mx1, __shfl_xor_sync(0xffffffffu, mx1, 2));

        float nm0 = fmaxf(m0, mx0), nm1 = fmaxf(m1, mx1);
        float c0 = __expf(m0 - nm0), c1 = __expf(m1 - nm1);
        m0 = nm0; m1 = nm1;

        float sum0 = 0.f, sum1 = 0.f;
#pragma unroll
        for (int nt = 0; nt < 4; nt++) {
            s[nt][0] = __expf(s[nt][0] - nm0);
            s[nt][1] = __expf(s[nt][1] - nm0);
            s[nt][2] = __expf(s[nt][2] - nm1);
            s[nt][3] = __expf(s[nt][3] - nm1);
            sum0 += s[nt][0] + s[nt][1];
            sum1 += s[nt][2] + s[nt][3];
        }
        sum0 += __shfl_xor_sync(0xffffffffu, sum0, 1);
        sum0 += __shfl_xor_sync(0xffffffffu, sum0, 2);
        sum1 += __shfl_xor_sync(0xffffffffu, sum1, 1);
        sum1 += __shfl_xor_sync(0xffffffffu, sum1, 2);
        l0 = l0 * c0 + sum0;
        l1 = l1 * c1 + sum1;

#pragma unroll
        for (int nt = 0; nt < 16; nt++) {
            o[nt][0] *= c0; o[nt][1] *= c0;
            o[nt][2] *= c1; o[nt][3] *= c1;
        }

        // ---- O += P V (3-term split); V frags via x4.trans (two n-tiles per load) ----
#pragma unroll
        for (int kf = 0; kf < 2; kf++) {
            uint32_t ah[4], al[4];
#pragma unroll
            for (int half = 0; half < 2; half++) {
                int nt = 2 * kf + half;
                uint32_t p01 = pack_bf2(s[nt][0], s[nt][1]);
                uint32_t p23 = pack_bf2(s[nt][2], s[nt][3]);
                float h0 = __uint_as_float(p01 << 16);
                float h1 = __uint_as_float(p01 & 0xffff0000u);
                float h2 = __uint_as_float(p23 << 16);
                float h3 = __uint_as_float(p23 & 0xffff0000u);
                uint32_t q01 = pack_bf2(s[nt][0] - h0, s[nt][1] - h1);
                uint32_t q23 = pack_bf2(s[nt][2] - h2, s[nt][3] - h3);
                ah[2 * half]     = p01;
                ah[2 * half + 1] = p23;
                al[2 * half]     = q01;
                al[2 * half + 1] = q23;
            }
#pragma unroll
            for (int np = 0; np < 8; np++) {
                uint32_t vbh[4], vbl[4];
                uint32_t addr = sk + 2 * KV_TILE +
                    ((kf * 16 + (lane & 15)) * ATP + np * 16 + ((lane >> 4) << 3)) * 2;
                ldm_x4_t(vbh, addr);                 // V_h
                ldm_x4_t(vbl, addr + KV_TILE);       // V_l
                mma_bf16(o[2 * np],     ah, &vbh[0]);
                mma_bf16(o[2 * np],     ah, &vbl[0]);
                mma_bf16(o[2 * np],     al, &vbh[0]);
                mma_bf16(o[2 * np + 1], ah, &vbh[2]);
                mma_bf16(o[2 * np + 1], ah, &vbl[2]);
                mma_bf16(o[2 * np + 1], al, &vbh[2]);
            }
        }
        __syncthreads();
    }

    // ---- epilogue: ctx hi/lo bf16 ----
    float inv0 = 1.f / l0, inv1 = 1.f / l1;
    int r_lo = r0 + warp * 16 + (lane >> 2);
    int r_hi = r_lo + 8;
#pragma unroll
    for (int nt = 0; nt < 16; nt++) {
        int col = h * HD + nt * 8 + ((lane & 3) << 1);
        {
            float x0 = o[nt][0] * inv0, x1 = o[nt][1] * inv0;
            uint32_t ph = pack_bf2(x0, x1);
            float h0 = __uint_as_float(ph << 16);
            float h1 = __uint_as_float(ph & 0xffff0000u);
            uint32_t pl = pack_bf2(x0 - h0, x1 - h1);
            *(uint32_t*)(ctxh + (size_t)r_lo * NQD + col) = ph;
            *(uint32_t*)(ctxl + (size_t)r_lo * NQD + col) = pl;
        }
        {
            float x0 = o[nt][2] * inv1, x1 = o[nt][3] * inv1;
            uint32_t ph = pack_bf2(x0, x1);
            float h0 = __uint_as_float(ph << 16);
            float h1 = __uint_as_float(ph & 0xffff0000u);
            uint32_t pl = pack_bf2(x0 - h0, x1 - h1);
            *(uint32_t*)(ctxh + (size_t)r_hi * NQD + col) = ph;
            *(uint32_t*)(ctxl + (size_t)r_hi * NQD + col) = pl;
        }
    }
}

// ---------------- launch ----------------
extern "C" void kernel_launch(void* const* d_in, const int* in_sizes, int n_in,
                              void* d_out, int out_size) {
    const float* hs   = (const float*)d_in[0];
    const float* cosp = (const float*)d_in[1];
    const float* sinp = (const float*)d_in[2];
    const float* Wq   = (const float*)d_in[3];
    const float* bq   = (const float*)d_in[4];
    const float* Wk   = (const float*)d_in[5];
    const float* bk   = (const float*)d_in[6];
    const float* Wv   = (const float*)d_in[7];
    const float* bv   = (const float*)d_in[8];
    const float* Wo   = (const float*)d_in[9];
    float* out = (float*)d_out;

    float *qkv_p, *bias_p;
    cudaGetSymbolAddress((void**)&qkv_p,  g_qkv);
    cudaGetSymbolAddress((void**)&bias_p, g_bias);

    __nv_bfloat16 *hsh, *hsl, *ctxh, *ctxl, *wh, *wl, *woh, *wol;
    __nv_bfloat16 *qh, *ql, *kh, *kl, *vh, *vl;
    cudaGetSymbolAddress((void**)&hsh,  g_hsh);  cudaGetSymbolAddress((void**)&hsl,  g_hsl);
    cudaGetSymbolAddress((void**)&ctxh, g_ctxh); cudaGetSymbolAddress((void**)&ctxl, g_ctxl);
    cudaGetSymbolAddress((void**)&wh,   g_wh);   cudaGetSymbolAddress((void**)&wl,   g_wl);
    cudaGetSymbolAddress((void**)&woh,  g_woh);  cudaGetSymbolAddress((void**)&wol,  g_wol);
    cudaGetSymbolAddress((void**)&qh,   g_qh);   cudaGetSymbolAddress((void**)&ql,   g_ql);
    cudaGetSymbolAddress((void**)&kh,   g_kh);   cudaGetSymbolAddress((void**)&kl,   g_kl);
    cudaGetSymbolAddress((void**)&vh,   g_vh);   cudaGetSymbolAddress((void**)&vl,   g_vl);

    cudaFuncSetAttribute(gemm_mma, cudaFuncAttributeMaxDynamicSharedMemorySize, GEMM_SMEM);
    cudaFuncSetAttribute(attn_mma, cudaFuncAttributeMaxDynamicSharedMemorySize, ATTN_SMEM);

    // 1) input split + weight transposes/splits (QKV concatenated) + bias concat
    {
        int n4 = S_LEN * HID / 4;
        split_kernel<<<(n4 + 255) / 256, 256>>>((const float4*)hs, (__nv_bfloat162*)hsh, (__nv_bfloat162*)hsl, n4);
    }
    {
        dim3 blk(32, 8);
        tsplit_kernel<<<dim3(NQD / 32, HID / 32), blk>>>(Wq, wh, wl, HID, NQD);
        tsplit_kernel<<<dim3(NKD / 32, HID / 32), blk>>>(Wk, wh + (size_t)NQD * HID, wl + (size_t)NQD * HID, HID, NKD);
        tsplit_kernel<<<dim3(NKD / 32, HID / 32), blk>>>(Wv, wh + (size_t)(NQD + NKD) * HID, wl + (size_t)(NQD + NKD) * HID, HID, NKD);
        tsplit_kernel<<<dim3(HID / 32, NQD / 32), blk>>>(Wo, woh, wol, NQD, HID);
        concat_bias_kernel<<<(NQKV + 255) / 256, 256>>>(bq, bk, bv, bias_p);
    }

    // 2) fused QKV projection
    gemm_mma<<<dim3(NQKV / 128, S_LEN / 128), 256, GEMM_SMEM>>>(hsh, hsl, wh, wl, bias_p, qkv_p, HID, NQKV);

    // 3) fused mROPE + hi/lo split (scale folded into q)
    rope_split_kernel<<<S_LEN, 256>>>(qkv_p, cosp, sinp, qh, ql, kh, kl, vh, vl);

    // 4) attention -> ctx (hi/lo bf16 directly)
    {
        dim3 grid(S_LEN / 128, NH);
        attn_mma<<<grid, 256, ATTN_SMEM>>>(qh, ql, kh, kl, vh, vl, ctxh, ctxl);
    }

    // 5) output projection
    gemm_mma<<<dim3(HID / 128, S_LEN / 128), 256, GEMM_SMEM>>>(ctxh, ctxl, woh, wol, nullptr, out, NQD, HID);
}

// round 9
// speedup vs baseline: 3.9027x; 1.0938x over previous
#include <cuda_runtime.h>
#include <cuda_bf16.h>
#include <cuda_fp16.h>
#include <math.h>
#include <stdint.h>

// ---------------- problem constants ----------------
#define S_LEN 2048
#define HID   3584
#define NH    28
#define NKV   4
#define HD    128
#define NQD   (NH*HD)    // 3584
#define NKD   (NKV*HD)   // 512
#define GRP   (NH/NKV)   // 7
#define NQKV  (NQD + 2*NKD)  // 4608

// ---------------- scratch (device globals; no allocs allowed) ----------------
__device__ float g_qkv[(size_t)S_LEN * NQKV];
__device__ float g_bias[NQKV];

__device__ __align__(16) __nv_bfloat16 g_hsh[S_LEN * HID],  g_hsl[S_LEN * HID];
__device__ __align__(16) __half        g_ctxh[S_LEN * NQD], g_ctxl[S_LEN * NQD];
__device__ __align__(16) __nv_bfloat16 g_qh[S_LEN * NQD],   g_ql[S_LEN * NQD];
__device__ __align__(16) __nv_bfloat16 g_kh[S_LEN * NKD],   g_kl[S_LEN * NKD];
__device__ __align__(16) __nv_bfloat16 g_vh[S_LEN * NKD],   g_vl[S_LEN * NKD];
__device__ __align__(16) __nv_bfloat16 g_wh[(size_t)NQKV * HID], g_wl[(size_t)NQKV * HID];
__device__ __align__(16) __half        g_wo16[(size_t)HID * NQD];

// ---------------- helpers ----------------
__device__ __forceinline__ uint32_t smem_u32(const void* p) {
    uint32_t a;
    asm("{ .reg .u64 t; cvta.to.shared.u64 t, %1; cvt.u32.u64 %0, t; }" : "=r"(a) : "l"(p));
    return a;
}

__device__ __forceinline__ void cp_async16(uint32_t dst, const void* src) {
    asm volatile("cp.async.cg.shared.global [%0], [%1], 16;" :: "r"(dst), "l"(src) : "memory");
}

__device__ __forceinline__ void ldm_x4(uint32_t* r, uint32_t addr) {
    asm volatile("ldmatrix.sync.aligned.m8n8.x4.shared.b16 {%0,%1,%2,%3}, [%4];"
                 : "=r"(r[0]), "=r"(r[1]), "=r"(r[2]), "=r"(r[3]) : "r"(addr));
}

__device__ __forceinline__ void ldm_x4_t(uint32_t* r, uint32_t addr) {
    asm volatile("ldmatrix.sync.aligned.m8n8.x4.trans.shared.b16 {%0,%1,%2,%3}, [%4];"
                 : "=r"(r[0]), "=r"(r[1]), "=r"(r[2]), "=r"(r[3]) : "r"(addr));
}

__device__ __forceinline__ void mma_bf16(float* c, const uint32_t* a, const uint32_t* b) {
    asm volatile(
        "mma.sync.aligned.m16n8k16.row.col.f32.bf16.bf16.f32 "
        "{%0,%1,%2,%3}, {%4,%5,%6,%7}, {%8,%9}, {%0,%1,%2,%3};"
        : "+f"(c[0]), "+f"(c[1]), "+f"(c[2]), "+f"(c[3])
        : "r"(a[0]), "r"(a[1]), "r"(a[2]), "r"(a[3]), "r"(b[0]), "r"(b[1]));
}

__device__ __forceinline__ void mma_f16(float* c, const uint32_t* a, const uint32_t* b) {
    asm volatile(
        "mma.sync.aligned.m16n8k16.row.col.f32.f16.f16.f32 "
        "{%0,%1,%2,%3}, {%4,%5,%6,%7}, {%8,%9}, {%0,%1,%2,%3};"
        : "+f"(c[0]), "+f"(c[1]), "+f"(c[2]), "+f"(c[3])
        : "r"(a[0]), "r"(a[1]), "r"(a[2]), "r"(a[3]), "r"(b[0]), "r"(b[1]));
}

__device__ __forceinline__ uint32_t pack_bf2(float lo, float hi) {
    uint32_t r;
    asm("cvt.rn.bf16x2.f32 %0, %1, %2;" : "=r"(r) : "f"(hi), "f"(lo));
    return r;
}

// ---------------- split kernels ----------------
__global__ void split_kernel(const float4* __restrict__ X, __nv_bfloat162* __restrict__ H,
                             __nv_bfloat162* __restrict__ L, int n4) {
    int i = blockIdx.x * 256 + threadIdx.x;
    if (i >= n4) return;
    float4 x = X[i];
    __nv_bfloat16 h0 = __float2bfloat16(x.x), h1 = __float2bfloat16(x.y);
    __nv_bfloat16 h2 = __float2bfloat16(x.z), h3 = __float2bfloat16(x.w);
    H[2*i]   = __halves2bfloat162(h0, h1);
    H[2*i+1] = __halves2bfloat162(h2, h3);
    L[2*i]   = __halves2bfloat162(__float2bfloat16(x.x - __bfloat162float(h0)),
                                  __float2bfloat16(x.y - __bfloat162float(h1)));
    L[2*i+1] = __halves2bfloat162(__float2bfloat16(x.z - __bfloat162float(h2)),
                                  __float2bfloat16(x.w - __bfloat162float(h3)));
}

// W [K,N] fp32 row-major -> Th/Tl [N,K] bf16 hi/lo. Tile 32n x 64k, block (32,8).
__global__ void tsplit2_kernel(const float* __restrict__ W, __nv_bfloat16* __restrict__ Th,
                               __nv_bfloat16* __restrict__ Tl, int K, int N) {
    __shared__ float t[64][33];
    int n0 = blockIdx.x * 32, k0 = blockIdx.y * 64;
    int tx = threadIdx.x, ty = threadIdx.y;   // (32, 8)
#pragma unroll
    for (int i = 0; i < 8; i++) {
        int k = i * 8 + ty;
        t[k][tx] = W[(size_t)(k0 + k) * N + n0 + tx];
    }
    __syncthreads();
#pragma unroll
    for (int i = 0; i < 4; i++) {
        int n = i * 8 + ty;
        float v0 = t[2 * tx][n], v1 = t[2 * tx + 1][n];
        __nv_bfloat16 h0 = __float2bfloat16(v0), h1 = __float2bfloat16(v1);
        __nv_bfloat162 hp = __halves2bfloat162(h0, h1);
        __nv_bfloat162 lp = __halves2bfloat162(__float2bfloat16(v0 - __bfloat162float(h0)),
                                               __float2bfloat16(v1 - __bfloat162float(h1)));
        size_t o = (size_t)(n0 + n) * K + k0 + 2 * tx;
        *(__nv_bfloat162*)(Th + o) = hp;
        *(__nv_bfloat162*)(Tl + o) = lp;
    }
}

// W [K,N] fp32 row-major -> T [N,K] fp16 (single). Tile 32n x 64k, block (32,8).
__global__ void tsplit2h_kernel(const float* __restrict__ W, __half* __restrict__ T,
                                int K, int N) {
    __shared__ float t[64][33];
    int n0 = blockIdx.x * 32, k0 = blockIdx.y * 64;
    int tx = threadIdx.x, ty = threadIdx.y;
#pragma unroll
    for (int i = 0; i < 8; i++) {
        int k = i * 8 + ty;
        t[k][tx] = W[(size_t)(k0 + k) * N + n0 + tx];
    }
    __syncthreads();
#pragma unroll
    for (int i = 0; i < 4; i++) {
        int n = i * 8 + ty;
        __half2 hp = __floats2half2_rn(t[2 * tx][n], t[2 * tx + 1][n]);
        *(__half2*)(T + (size_t)(n0 + n) * K + k0 + 2 * tx) = hp;
    }
}

__global__ void concat_bias_kernel(const float* __restrict__ bq, const float* __restrict__ bk,
                                   const float* __restrict__ bv, float* __restrict__ b) {
    int i = blockIdx.x * 256 + threadIdx.x;
    if (i < NQD) b[i] = bq[i];
    else if (i < NQD + NKD) b[i] = bk[i - NQD];
    else if (i < NQKV) b[i] = bv[i - NQD - NKD];
}

// ---------------- mma.sync GEMM (bf16 3-term, QKV projection) ----------------
#define GBK 32
#define ROWP 40
#define STG_TILE (128*ROWP*2)          // 10240 B per operand tile
#define STG_BYTES (4*STG_TILE)         // 40960 B per stage
#define GEMM_SMEM (2*STG_BYTES)        // 81920 B

__global__ __launch_bounds__(256, 2)
void gemm_mma(const __nv_bfloat16* __restrict__ Ah, const __nv_bfloat16* __restrict__ Al,
              const __nv_bfloat16* __restrict__ Bh, const __nv_bfloat16* __restrict__ Bl,
              const float* __restrict__ bias, float* __restrict__ C, int K, int Ntot) {
    extern __shared__ char smem[];
    const uint32_t sb = smem_u32(smem);
    const int tid = threadIdx.x;
    const int lane = tid & 31;
    const int warp = tid >> 5;
    const int wm = (warp >> 2) * 64;
    const int wn = (warp & 3) * 32;
    const int row0 = blockIdx.y * 128;
    const int col0 = blockIdx.x * 128;
    const int NI = K / GBK;

    float acc[4][4][4];
#pragma unroll
    for (int mt = 0; mt < 4; mt++)
#pragma unroll
        for (int nt = 0; nt < 4; nt++)
#pragma unroll
            for (int i = 0; i < 4; i++) acc[mt][nt][i] = 0.f;

    auto issue_load = [&](int stage, int kb) {
        uint32_t sbase = sb + stage * STG_BYTES;
#pragma unroll
        for (int tile = 0; tile < 4; tile++) {
            const __nv_bfloat16* src =
                (tile == 0) ? Ah : (tile == 1) ? Al : (tile == 2) ? Bh : Bl;
            int gbase = (tile < 2) ? row0 : col0;
#pragma unroll
            for (int j = 0; j < 2; j++) {
                int s = j * 256 + tid;
                int row = s >> 2;
                int c = (s & 3) << 3;
                const void* g = src + (size_t)(gbase + row) * K + kb + c;
                uint32_t dst = sbase + tile * STG_TILE + (row * ROWP + c) * 2;
                cp_async16(dst, g);
            }
        }
        asm volatile("cp.async.commit_group;" ::: "memory");
    };

    issue_load(0, 0);

    for (int i = 0; i < NI; i++) {
        if (i + 1 < NI) {
            issue_load((i + 1) & 1, (i + 1) * GBK);
            asm volatile("cp.async.wait_group 1;" ::: "memory");
        } else {
            asm volatile("cp.async.wait_group 0;" ::: "memory");
        }
        __syncthreads();

        const uint32_t sa = sb + (i & 1) * STG_BYTES;
#pragma unroll
        for (int ks = 0; ks < 2; ks++) {
            uint32_t bh[4][2], bl[4][2];
#pragma unroll
            for (int np = 0; np < 2; np++) {
                uint32_t addr = sa + 2 * STG_TILE +
                    ((wn + np * 16 + ((lane >> 4) << 3) + (lane & 7)) * ROWP
                     + ks * 16 + (((lane >> 3) & 1) << 3)) * 2;
                ldm_x4(&bh[np * 2][0], addr);
                ldm_x4(&bl[np * 2][0], addr + STG_TILE);
            }
#pragma unroll
            for (int mt = 0; mt < 4; mt++) {
                uint32_t ah[4], al[4];
                uint32_t addr = sa +
                    ((wm + mt * 16 + (lane & 15)) * ROWP + ks * 16 + ((lane >> 4) << 3)) * 2;
                ldm_x4(ah, addr);
                ldm_x4(al, addr + STG_TILE);
#pragma unroll
                for (int nt = 0; nt < 4; nt++) {
                    mma_bf16(acc[mt][nt], ah, bh[nt]);
                    mma_bf16(acc[mt][nt], ah, bl[nt]);
                    mma_bf16(acc[mt][nt], al, bh[nt]);
                }
            }
        }
        __syncthreads();
    }

#pragma unroll
    for (int mt = 0; mt < 4; mt++) {
#pragma unroll
        for (int nt = 0; nt < 4; nt++) {
            int r = row0 + wm + mt * 16 + (lane >> 2);
            int cidx = col0 + wn + nt * 8 + ((lane & 3) << 1);
            float b0 = bias[cidx], b1 = bias[cidx + 1];
            float2* p0 = (float2*)(C + (size_t)r * Ntot + cidx);
            float2* p1 = (float2*)(C + (size_t)(r + 8) * Ntot + cidx);
            *p0 = make_float2(acc[mt][nt][0] + b0, acc[mt][nt][1] + b1);
            *p1 = make_float2(acc[mt][nt][2] + b0, acc[mt][nt][3] + b1);
        }
    }
}

// ---------------- mma.sync GEMM (fp16 2-term, O projection) ----------------
#define STG2_BYTES (3*STG_TILE)        // 30720 B per stage (Ah, Al, B)
#define GEMM2_SMEM (2*STG2_BYTES)      // 61440 B

__global__ __launch_bounds__(256, 2)
void gemm_f16_2t(const __half* __restrict__ Ah, const __half* __restrict__ Al,
                 const __half* __restrict__ B,
                 float* __restrict__ C, int K, int Ntot) {
    extern __shared__ char smem[];
    const uint32_t sb = smem_u32(smem);
    const int tid = threadIdx.x;
    const int lane = tid & 31;
    const int warp = tid >> 5;
    const int wm = (warp >> 2) * 64;
    const int wn = (warp & 3) * 32;
    const int row0 = blockIdx.y * 128;
    const int col0 = blockIdx.x * 128;
    const int NI = K / GBK;

    float acc[4][4][4];
#pragma unroll
    for (int mt = 0; mt < 4; mt++)
#pragma unroll
        for (int nt = 0; nt < 4; nt++)
#pragma unroll
            for (int i = 0; i < 4; i++) acc[mt][nt][i] = 0.f;

    auto issue_load = [&](int stage, int kb) {
        uint32_t sbase = sb + stage * STG2_BYTES;
#pragma unroll
        for (int tile = 0; tile < 3; tile++) {
            const __half* src = (tile == 0) ? Ah : (tile == 1) ? Al : B;
            int gbase = (tile < 2) ? row0 : col0;
#pragma unroll
            for (int j = 0; j < 2; j++) {
                int s = j * 256 + tid;
                int row = s >> 2;
                int c = (s & 3) << 3;
                const void* g = src + (size_t)(gbase + row) * K + kb + c;
                uint32_t dst = sbase + tile * STG_TILE + (row * ROWP + c) * 2;
                cp_async16(dst, g);
            }
        }
        asm volatile("cp.async.commit_group;" ::: "memory");
    };

    issue_load(0, 0);

    for (int i = 0; i < NI; i++) {
        if (i + 1 < NI) {
            issue_load((i + 1) & 1, (i + 1) * GBK);
            asm volatile("cp.async.wait_group 1;" ::: "memory");
        } else {
            asm volatile("cp.async.wait_group 0;" ::: "memory");
        }
        __syncthreads();

        const uint32_t sa = sb + (i & 1) * STG2_BYTES;
#pragma unroll
        for (int ks = 0; ks < 2; ks++) {
            uint32_t bh[4][2];
#pragma unroll
            for (int np = 0; np < 2; np++) {
                uint32_t addr = sa + 2 * STG_TILE +
                    ((wn + np * 16 + ((lane >> 4) << 3) + (lane & 7)) * ROWP
                     + ks * 16 + (((lane >> 3) & 1) << 3)) * 2;
                ldm_x4(&bh[np * 2][0], addr);
            }
#pragma unroll
            for (int mt = 0; mt < 4; mt++) {
                uint32_t ah[4], al[4];
                uint32_t addr = sa +
                    ((wm + mt * 16 + (lane & 15)) * ROWP + ks * 16 + ((lane >> 4) << 3)) * 2;
                ldm_x4(ah, addr);
                ldm_x4(al, addr + STG_TILE);
#pragma unroll
                for (int nt = 0; nt < 4; nt++) {
                    mma_f16(acc[mt][nt], ah, bh[nt]);
                    mma_f16(acc[mt][nt], al, bh[nt]);
                }
            }
        }
        __syncthreads();
    }

#pragma unroll
    for (int mt = 0; mt < 4; mt++) {
#pragma unroll
        for (int nt = 0; nt < 4; nt++) {
            int r = row0 + wm + mt * 16 + (lane >> 2);
            int cidx = col0 + wn + nt * 8 + ((lane & 3) << 1);
            float2* p0 = (float2*)(C + (size_t)r * Ntot + cidx);
            float2* p1 = (float2*)(C + (size_t)(r + 8) * Ntot + cidx);
            *p0 = make_float2(acc[mt][nt][0], acc[mt][nt][1]);
            *p1 = make_float2(acc[mt][nt][2], acc[mt][nt][3]);
        }
    }
}

// ---------------- fused mROPE + hi/lo split (vectorized stores) ----------------
__global__ __launch_bounds__(256)
void rope_split_kernel(const float* __restrict__ qkv,
                       const float* __restrict__ cosp, const float* __restrict__ sinp,
                       __nv_bfloat16* __restrict__ qh, __nv_bfloat16* __restrict__ ql,
                       __nv_bfloat16* __restrict__ kh, __nv_bfloat16* __restrict__ kl,
                       __nv_bfloat16* __restrict__ vh, __nv_bfloat16* __restrict__ vl) {
    const int s = blockIdx.x;
    const int lane = threadIdx.x & 31;    // d-pair index
    const int grp = threadIdx.x >> 5;     // 0..7
    const int da = 2 * lane;              // even, 0..62 (pairs don't cross sec boundaries 16/40)
    const int sec = (da < 16) ? 0 : ((da < 40) ? 1 : 2);
    const int SH = S_LEN * HD;
    const float scale = 0.08838834764831845f;   // 1/sqrt(128)

    const float2 c1 = *(const float2*)(cosp + sec * SH + s * HD + da);
    const float2 s1 = *(const float2*)(sinp + sec * SH + s * HD + da);
    const float2 c2 = *(const float2*)(cosp + sec * SH + s * HD + da + 64);
    const float2 s2 = *(const float2*)(sinp + sec * SH + s * HD + da + 64);

    const float* row = qkv + (size_t)s * NQKV;

    auto store2 = [](__nv_bfloat16* H, __nv_bfloat16* L, size_t o, float a, float b) {
        __nv_bfloat16 ha = __float2bfloat16(a), hb = __float2bfloat16(b);
        *(__nv_bfloat162*)(H + o) = __halves2bfloat162(ha, hb);
        *(__nv_bfloat162*)(L + o) = __halves2bfloat162(
            __float2bfloat16(a - __bfloat162float(ha)),
            __float2bfloat16(b - __bfloat162float(hb)));
    };

#pragma unroll 1
    for (int it = 0; it < 5; it++) {
        int hh = it * 8 + grp;    // 0..39, valid < 36
        if (hh >= NH + 2 * NKV) break;
        if (hh < NH) {
            const float* base = row + hh * HD;
            float2 x1 = *(const float2*)(base + da);
            float2 x2 = *(const float2*)(base + da + 64);
            size_t o = (size_t)s * NQD + hh * HD;
            store2(qh, ql, o + da,      (x1.x * c1.x - x2.x * s1.x) * scale,
                                        (x1.y * c1.y - x2.y * s1.y) * scale);
            store2(qh, ql, o + da + 64, (x2.x * c2.x + x1.x * s2.x) * scale,
                                        (x2.y * c2.y + x1.y * s2.y) * scale);
        } else if (hh < NH + NKV) {
            int kvi = hh - NH;
            const float* base = row + NQD + kvi * HD;
            float2 x1 = *(const float2*)(base + da);
            float2 x2 = *(const float2*)(base + da + 64);
            size_t o = (size_t)s * NKD + kvi * HD;
            store2(kh, kl, o + da,      x1.x * c1.x - x2.x * s1.x,
                                        x1.y * c1.y - x2.y * s1.y);
            store2(kh, kl, o + da + 64, x2.x * c2.x + x1.x * s2.x,
                                        x2.y * c2.y + x1.y * s2.y);
        } else {
            int kvi = hh - NH - NKV;
            const float* base = row + NQD + NKD + kvi * HD;
            float2 x1 = *(const float2*)(base + da);
            float2 x2 = *(const float2*)(base + da + 64);
            size_t o = (size_t)s * NKD + kvi * HD;
            store2(vh, vl, o + da,      x1.x, x1.y);
            store2(vh, vl, o + da + 64, x2.x, x2.y);
        }
    }
}

// ---------------- attention: mma.sync flash, 128 q-rows/CTA, pipelined KV ----------------
#define ATP 136
#define AT_ROWB (ATP*2)              // 272 B/row
#define AQ_TILE (128*AT_ROWB)        // 34816
#define KV_TILE (32*AT_ROWB)         // 8704
#define KV_STG  (4*KV_TILE)          // 34816 (Kh,Kl,Vh,Vl)
#define AQ_H 0
#define AQ_L AQ_TILE
#define AKV  (2*AQ_TILE)
#define ATTN_SMEM (AKV + 2*KV_STG)   // 139264 B

__global__ __launch_bounds__(256)
void attn_mma(const __nv_bfloat16* __restrict__ qh, const __nv_bfloat16* __restrict__ ql,
              const __nv_bfloat16* __restrict__ kh, const __nv_bfloat16* __restrict__ kl,
              const __nv_bfloat16* __restrict__ vh, const __nv_bfloat16* __restrict__ vl,
              __half* __restrict__ ctxh, __half* __restrict__ ctxl) {
    extern __shared__ char smem[];
    const uint32_t sb = smem_u32(smem);
    const int tid = threadIdx.x;
    const int lane = tid & 31;
    const int warp = tid >> 5;           // 0..7
    const int h = blockIdx.y;
    const int kvh = h / GRP;
    const int r0 = blockIdx.x * 128;

    // ---- Q tile (128 x 128) hi/lo ----
#pragma unroll
    for (int j = 0; j < 8; j++) {
        int idx = j * 256 + tid;          // 0..2047
        int row = idx >> 4, c = idx & 15;
        size_t g = (size_t)(r0 + row) * NQD + h * HD + c * 8;
        uint32_t so = row * AT_ROWB + c * 16;
        cp_async16(sb + AQ_H + so, qh + g);
        cp_async16(sb + AQ_L + so, ql + g);
    }
    asm volatile("cp.async.commit_group;" ::: "memory");

    auto issue_kv = [&](int stage, int kt) {
        uint32_t base = sb + AKV + stage * KV_STG;
#pragma unroll
        for (int j = 0; j < 2; j++) {
            int idx = j * 256 + tid;      // 0..511
            int row = idx >> 4, c = idx & 15;
            size_t g = (size_t)(kt + row) * NKD + kvh * HD + c * 8;
            uint32_t so = row * AT_ROWB + c * 16;
            cp_async16(base + 0 * KV_TILE + so, kh + g);
            cp_async16(base + 1 * KV_TILE + so, kl + g);
            cp_async16(base + 2 * KV_TILE + so, vh + g);
            cp_async16(base + 3 * KV_TILE + so, vl + g);
        }
        asm volatile("cp.async.commit_group;" ::: "memory");
    };

    issue_kv(0, 0);
    asm volatile("cp.async.wait_group 1;" ::: "memory");   // Q done (kv0 may pend)
    __syncthreads();

    // ---- Q fragments (warp owns rows [warp*16, warp*16+16)) ----
    uint32_t qfh[8][4], qfl[8][4];
#pragma unroll
    for (int kf = 0; kf < 8; kf++) {
        uint32_t off = ((warp * 16 + (lane & 15)) * ATP + kf * 16 + ((lane >> 4) << 3)) * 2;
        ldm_x4(qfh[kf], sb + AQ_H + off);
        ldm_x4(qfl[kf], sb + AQ_L + off);
    }

    float o[16][4];
#pragma unroll
    for (int nt = 0; nt < 16; nt++)
#pragma unroll
        for (int i = 0; i < 4; i++) o[nt][i] = 0.f;
    float m0 = -INFINITY, m1 = -INFINITY, l0 = 0.f, l1 = 0.f;

    const int NI = S_LEN / 32;            // 64

    for (int it = 0; it < NI; it++) {
        if (it + 1 < NI) {
            issue_kv((it + 1) & 1, (it + 1) * 32);
            asm volatile("cp.async.wait_group 1;" ::: "memory");
        } else {
            asm volatile("cp.async.wait_group 0;" ::: "memory");
        }
        __syncthreads();

        const uint32_t sk = sb + AKV + (it & 1) * KV_STG;

        // ---- S = Q K^T (3-term split); K frags via x4 (two n-tiles per load) ----
        float s[4][4];
#pragma unroll
        for (int nt = 0; nt < 4; nt++)
#pragma unroll
            for (int i = 0; i < 4; i++) s[nt][i] = 0.f;

#pragma unroll
        for (int kf = 0; kf < 8; kf++) {
            uint32_t kbh[4][2], kbl[4][2];
#pragma unroll
            for (int np = 0; np < 2; np++) {
                uint32_t addr = sk +
                    ((np * 16 + ((lane >> 4) << 3) + (lane & 7)) * ATP
                     + kf * 16 + (((lane >> 3) & 1) << 3)) * 2;
                ldm_x4(&kbh[np * 2][0], addr);
                ldm_x4(&kbl[np * 2][0], addr + KV_TILE);
            }
#pragma unroll
            for (int nt = 0; nt < 4; nt++) {
                mma_bf16(s[nt], qfh[kf], kbh[nt]);
                mma_bf16(s[nt], qfh[kf], kbl[nt]);
                mma_bf16(s[nt], qfl[kf], kbh[nt]);
            }
        }

        // ---- online softmax ----
        float mx0 = -INFINITY, mx1 = -INFINITY;
#pragma unroll
        for (int nt = 0; nt < 4; nt++) {
            mx0 = fmaxf(mx0, fmaxf(s[nt][0], s[nt][1]));
            mx1 = fmaxf(mx1, fmaxf(s[nt][2], s[nt][3]));
        }
        mx0 = fmaxf(mx0, __shfl_xor_sync(0xffffffffu, mx0, 1));
        mx0 = fmaxf(mx0, __shfl_xor_sync(0xffffffffu, mx0, 2));
        mx1 = fmaxf(mx1, __shfl_xor_sync(0xffffffffu, mx1, 1));
        mx1 = fmaxf(mx1, __shfl_xor_sync(0xffffffffu, mx1, 2));

        float nm0 = fmaxf(m0, mx0), nm1 = fmaxf(m1, mx1);
        float c0 = __expf(m0 - nm0), c1 = __expf(m1 - nm1);
        m0 = nm0; m1 = nm1;

        float sum0 = 0.f, sum1 = 0.f;
#pragma unroll
        for (int nt = 0; nt < 4; nt++) {
            s[nt][0] = __expf(s[nt][0] - nm0);
            s[nt][1] = __expf(s[nt][1] - nm0);
            s[nt][2] = __expf(s[nt][2] - nm1);
            s[nt][3] = __expf(s[nt][3] - nm1);
            sum0 += s[nt][0] + s[nt][1];
            sum1 += s[nt][2] + s[nt][3];
        }
        sum0 += __shfl_xor_sync(0xffffffffu, sum0, 1);
        sum0 += __shfl_xor_sync(0xffffffffu, sum0, 2);
        sum1 += __shfl_xor_sync(0xffffffffu, sum1, 1);
        sum1 += __shfl_xor_sync(0xffffffffu, sum1, 2);
        l0 = l0 * c0 + sum0;
        l1 = l1 * c1 + sum1;

#pragma unroll
        for (int nt = 0; nt < 16; nt++) {
            o[nt][0] *= c0; o[nt][1] *= c0;
            o[nt][2] *= c1; o[nt][3] *= c1;
        }

        // ---- O += P V (3-term split); V frags via x4.trans ----
#pragma unroll
        for (int kf = 0; kf < 2; kf++) {
            uint32_t ah[4], al[4];
#pragma unroll
            for (int half = 0; half < 2; half++) {
                int nt = 2 * kf + half;
                uint32_t p01 = pack_bf2(s[nt][0], s[nt][1]);
                uint32_t p23 = pack_bf2(s[nt][2], s[nt][3]);
                float h0 = __uint_as_float(p01 << 16);
                float h1 = __uint_as_float(p01 & 0xffff0000u);
                float h2 = __uint_as_float(p23 << 16);
                float h3 = __uint_as_float(p23 & 0xffff0000u);
                uint32_t q01 = pack_bf2(s[nt][0] - h0, s[nt][1] - h1);
                uint32_t q23 = pack_bf2(s[nt][2] - h2, s[nt][3] - h3);
                ah[2 * half]     = p01;
                ah[2 * half + 1] = p23;
                al[2 * half]     = q01;
                al[2 * half + 1] = q23;
            }
#pragma unroll
            for (int np = 0; np < 8; np++) {
                uint32_t vbh[4], vbl[4];
                uint32_t addr = sk + 2 * KV_TILE +
                    ((kf * 16 + (lane & 15)) * ATP + np * 16 + ((lane >> 4) << 3)) * 2;
                ldm_x4_t(vbh, addr);
                ldm_x4_t(vbl, addr + KV_TILE);
                mma_bf16(o[2 * np],     ah, &vbh[0]);
                mma_bf16(o[2 * np],     ah, &vbl[0]);
                mma_bf16(o[2 * np],     al, &vbh[0]);
                mma_bf16(o[2 * np + 1], ah, &vbh[2]);
                mma_bf16(o[2 * np + 1], ah, &vbl[2]);
                mma_bf16(o[2 * np + 1], al, &vbh[2]);
            }
        }
        __syncthreads();
    }

    // ---- epilogue: ctx as fp16 hi/lo (feeds fp16 2-term O projection) ----
    float inv0 = 1.f / l0, inv1 = 1.f / l1;
    int r_lo = r0 + warp * 16 + (lane >> 2);
    int r_hi = r_lo + 8;
#pragma unroll
    for (int nt = 0; nt < 16; nt++) {
        int col = h * HD + nt * 8 + ((lane & 3) << 1);
        {
            float x0 = o[nt][0] * inv0, x1 = o[nt][1] * inv0;
            __half2 ph = __floats2half2_rn(x0, x1);
            __half2 pl = __floats2half2_rn(x0 - __half2float(__low2half(ph)),
                                           x1 - __half2float(__high2half(ph)));
            *(__half2*)(ctxh + (size_t)r_lo * NQD + col) = ph;
            *(__half2*)(ctxl + (size_t)r_lo * NQD + col) = pl;
        }
        {
            float x0 = o[nt][2] * inv1, x1 = o[nt][3] * inv1;
            __half2 ph = __floats2half2_rn(x0, x1);
            __half2 pl = __floats2half2_rn(x0 - __half2float(__low2half(ph)),
                                           x1 - __half2float(__high2half(ph)));
            *(__half2*)(ctxh + (size_t)r_hi * NQD + col) = ph;
            *(__half2*)(ctxl + (size_t)r_hi * NQD + col) = pl;
        }
    }
}

// ---------------- launch ----------------
extern "C" void kernel_launch(void* const* d_in, const int* in_sizes, int n_in,
                              void* d_out, int out_size) {
    const float* hs   = (const float*)d_in[0];
    const float* cosp = (const float*)d_in[1];
    const float* sinp = (const float*)d_in[2];
    const float* Wq   = (const float*)d_in[3];
    const float* bq   = (const float*)d_in[4];
    const float* Wk   = (const float*)d_in[5];
    const float* bk   = (const float*)d_in[6];
    const float* Wv   = (const float*)d_in[7];
    const float* bv   = (const float*)d_in[8];
    const float* Wo   = (const float*)d_in[9];
    float* out = (float*)d_out;

    float *qkv_p, *bias_p;
    cudaGetSymbolAddress((void**)&qkv_p,  g_qkv);
    cudaGetSymbolAddress((void**)&bias_p, g_bias);

    __nv_bfloat16 *hsh, *hsl, *wh, *wl;
    __nv_bfloat16 *qh, *ql, *kh, *kl, *vh, *vl;
    __half *ctxh, *ctxl, *wo16;
    cudaGetSymbolAddress((void**)&hsh,  g_hsh);  cudaGetSymbolAddress((void**)&hsl,  g_hsl);
    cudaGetSymbolAddress((void**)&ctxh, g_ctxh); cudaGetSymbolAddress((void**)&ctxl, g_ctxl);
    cudaGetSymbolAddress((void**)&wh,   g_wh);   cudaGetSymbolAddress((void**)&wl,   g_wl);
    cudaGetSymbolAddress((void**)&wo16, g_wo16);
    cudaGetSymbolAddress((void**)&qh,   g_qh);   cudaGetSymbolAddress((void**)&ql,   g_ql);
    cudaGetSymbolAddress((void**)&kh,   g_kh);   cudaGetSymbolAddress((void**)&kl,   g_kl);
    cudaGetSymbolAddress((void**)&vh,   g_vh);   cudaGetSymbolAddress((void**)&vl,   g_vl);

    cudaFuncSetAttribute(gemm_mma,   cudaFuncAttributeMaxDynamicSharedMemorySize, GEMM_SMEM);
    cudaFuncSetAttribute(gemm_f16_2t, cudaFuncAttributeMaxDynamicSharedMemorySize, GEMM2_SMEM);
    cudaFuncSetAttribute(attn_mma,   cudaFuncAttributeMaxDynamicSharedMemorySize, ATTN_SMEM);

    // 1) input split + weight transposes/splits + bias concat
    {
        int n4 = S_LEN * HID / 4;
        split_kernel<<<(n4 + 255) / 256, 256>>>((const float4*)hs, (__nv_bfloat162*)hsh, (__nv_bfloat162*)hsl, n4);
    }
    {
        dim3 blk(32, 8);
        tsplit2_kernel<<<dim3(NQD / 32, HID / 64), blk>>>(Wq, wh, wl, HID, NQD);
        tsplit2_kernel<<<dim3(NKD / 32, HID / 64), blk>>>(Wk, wh + (size_t)NQD * HID, wl + (size_t)NQD * HID, HID, NKD);
        tsplit2_kernel<<<dim3(NKD / 32, HID / 64), blk>>>(Wv, wh + (size_t)(NQD + NKD) * HID, wl + (size_t)(NQD + NKD) * HID, HID, NKD);
        tsplit2h_kernel<<<dim3(HID / 32, NQD / 64), blk>>>(Wo, wo16, NQD, HID);
        concat_bias_kernel<<<(NQKV + 255) / 256, 256>>>(bq, bk, bv, bias_p);
    }

    // 2) fused QKV projection (bf16 3-term)
    gemm_mma<<<dim3(NQKV / 128, S_LEN / 128), 256, GEMM_SMEM>>>(hsh, hsl, wh, wl, bias_p, qkv_p, HID, NQKV);

    // 3) fused mROPE + hi/lo split (scale folded into q)
    rope_split_kernel<<<S_LEN, 256>>>(qkv_p, cosp, sinp, qh, ql, kh, kl, vh, vl);

    // 4) attention -> ctx (fp16 hi/lo directly)
    {
        dim3 grid(S_LEN / 128, NH);
        attn_mma<<<grid, 256, ATTN_SMEM>>>(qh, ql, kh, kl, vh, vl, ctxh, ctxl);
    }

    // 5) output projection (fp16 2-term)
    gemm_f16_2t<<<dim3(HID / 128, S_LEN / 128), 256, GEMM2_SMEM>>>(ctxh, ctxl, wo16, out, NQD, HID);
}

// round 10
// speedup vs baseline: 4.2813x; 1.0970x over previous
#include <cuda_runtime.h>
#include <cuda_bf16.h>
#include <cuda_fp16.h>
#include <math.h>
#include <stdint.h>

// ---------------- problem constants ----------------
#define S_LEN 2048
#define HID   3584
#define NH    28
#define NKV   4
#define HD    128
#define NQD   (NH*HD)    // 3584
#define NKD   (NKV*HD)   // 512
#define GRP   (NH/NKV)   // 7
#define NQKV  (NQD + 2*NKD)  // 4608

// ---------------- scratch (device globals; no allocs allowed) ----------------
__device__ float g_qkv[(size_t)S_LEN * NQKV];
__device__ float g_bias[NQKV];

__device__ __align__(16) __nv_bfloat16 g_hsh[S_LEN * HID],  g_hsl[S_LEN * HID];
__device__ __align__(16) __half        g_ctxh[S_LEN * NQD], g_ctxl[S_LEN * NQD];
__device__ __align__(16) __half        g_q16h[S_LEN * NQD], g_q16l[S_LEN * NQD];
__device__ __align__(16) __half        g_k16[S_LEN * NKD];
__device__ __align__(16) __half        g_v16h[S_LEN * NKD], g_v16l[S_LEN * NKD];
__device__ __align__(16) __nv_bfloat16 g_wh[(size_t)NQKV * HID], g_wl[(size_t)NQKV * HID];
__device__ __align__(16) __half        g_wo16[(size_t)HID * NQD];

// ---------------- helpers ----------------
__device__ __forceinline__ uint32_t smem_u32(const void* p) {
    uint32_t a;
    asm("{ .reg .u64 t; cvta.to.shared.u64 t, %1; cvt.u32.u64 %0, t; }" : "=r"(a) : "l"(p));
    return a;
}

__device__ __forceinline__ void cp_async16(uint32_t dst, const void* src) {
    asm volatile("cp.async.cg.shared.global [%0], [%1], 16;" :: "r"(dst), "l"(src) : "memory");
}

__device__ __forceinline__ void ldm_x4(uint32_t* r, uint32_t addr) {
    asm volatile("ldmatrix.sync.aligned.m8n8.x4.shared.b16 {%0,%1,%2,%3}, [%4];"
                 : "=r"(r[0]), "=r"(r[1]), "=r"(r[2]), "=r"(r[3]) : "r"(addr));
}

__device__ __forceinline__ void ldm_x4_t(uint32_t* r, uint32_t addr) {
    asm volatile("ldmatrix.sync.aligned.m8n8.x4.trans.shared.b16 {%0,%1,%2,%3}, [%4];"
                 : "=r"(r[0]), "=r"(r[1]), "=r"(r[2]), "=r"(r[3]) : "r"(addr));
}

__device__ __forceinline__ void mma_bf16(float* c, const uint32_t* a, const uint32_t* b) {
    asm volatile(
        "mma.sync.aligned.m16n8k16.row.col.f32.bf16.bf16.f32 "
        "{%0,%1,%2,%3}, {%4,%5,%6,%7}, {%8,%9}, {%0,%1,%2,%3};"
        : "+f"(c[0]), "+f"(c[1]), "+f"(c[2]), "+f"(c[3])
        : "r"(a[0]), "r"(a[1]), "r"(a[2]), "r"(a[3]), "r"(b[0]), "r"(b[1]));
}

__device__ __forceinline__ void mma_f16(float* c, const uint32_t* a, const uint32_t* b) {
    asm volatile(
        "mma.sync.aligned.m16n8k16.row.col.f32.f16.f16.f32 "
        "{%0,%1,%2,%3}, {%4,%5,%6,%7}, {%8,%9}, {%0,%1,%2,%3};"
        : "+f"(c[0]), "+f"(c[1]), "+f"(c[2]), "+f"(c[3])
        : "r"(a[0]), "r"(a[1]), "r"(a[2]), "r"(a[3]), "r"(b[0]), "r"(b[1]));
}

__device__ __forceinline__ uint32_t pack_h2(float a, float b) {
    __half2 h = __floats2half2_rn(a, b);
    return *(uint32_t*)&h;
}

// ---------------- split kernels ----------------
__global__ void split_kernel(const float4* __restrict__ X, __nv_bfloat162* __restrict__ H,
                             __nv_bfloat162* __restrict__ L, int n4) {
    int i = blockIdx.x * 256 + threadIdx.x;
    if (i >= n4) return;
    float4 x = X[i];
    __nv_bfloat16 h0 = __float2bfloat16(x.x), h1 = __float2bfloat16(x.y);
    __nv_bfloat16 h2 = __float2bfloat16(x.z), h3 = __float2bfloat16(x.w);
    H[2*i]   = __halves2bfloat162(h0, h1);
    H[2*i+1] = __halves2bfloat162(h2, h3);
    L[2*i]   = __halves2bfloat162(__float2bfloat16(x.x - __bfloat162float(h0)),
                                  __float2bfloat16(x.y - __bfloat162float(h1)));
    L[2*i+1] = __halves2bfloat162(__float2bfloat16(x.z - __bfloat162float(h2)),
                                  __float2bfloat16(x.w - __bfloat162float(h3)));
}

// W [K,N] fp32 row-major -> Th/Tl [N,K] bf16 hi/lo. Tile 32n x 64k, block (32,8).
__global__ void tsplit2_kernel(const float* __restrict__ W, __nv_bfloat16* __restrict__ Th,
                               __nv_bfloat16* __restrict__ Tl, int K, int N) {
    __shared__ float t[64][33];
    int n0 = blockIdx.x * 32, k0 = blockIdx.y * 64;
    int tx = threadIdx.x, ty = threadIdx.y;   // (32, 8)
#pragma unroll
    for (int i = 0; i < 8; i++) {
        int k = i * 8 + ty;
        t[k][tx] = W[(size_t)(k0 + k) * N + n0 + tx];
    }
    __syncthreads();
#pragma unroll
    for (int i = 0; i < 4; i++) {
        int n = i * 8 + ty;
        float v0 = t[2 * tx][n], v1 = t[2 * tx + 1][n];
        __nv_bfloat16 h0 = __float2bfloat16(v0), h1 = __float2bfloat16(v1);
        __nv_bfloat162 hp = __halves2bfloat162(h0, h1);
        __nv_bfloat162 lp = __halves2bfloat162(__float2bfloat16(v0 - __bfloat162float(h0)),
                                               __float2bfloat16(v1 - __bfloat162float(h1)));
        size_t o = (size_t)(n0 + n) * K + k0 + 2 * tx;
        *(__nv_bfloat162*)(Th + o) = hp;
        *(__nv_bfloat162*)(Tl + o) = lp;
    }
}

// W [K,N] fp32 row-major -> T [N,K] fp16 (single). Tile 32n x 64k, block (32,8).
__global__ void tsplit2h_kernel(const float* __restrict__ W, __half* __restrict__ T,
                                int K, int N) {
    __shared__ float t[64][33];
    int n0 = blockIdx.x * 32, k0 = blockIdx.y * 64;
    int tx = threadIdx.x, ty = threadIdx.y;
#pragma unroll
    for (int i = 0; i < 8; i++) {
        int k = i * 8 + ty;
        t[k][tx] = W[(size_t)(k0 + k) * N + n0 + tx];
    }
    __syncthreads();
#pragma unroll
    for (int i = 0; i < 4; i++) {
        int n = i * 8 + ty;
        __half2 hp = __floats2half2_rn(t[2 * tx][n], t[2 * tx + 1][n]);
        *(__half2*)(T + (size_t)(n0 + n) * K + k0 + 2 * tx) = hp;
    }
}

__global__ void concat_bias_kernel(const float* __restrict__ bq, const float* __restrict__ bk,
                                   const float* __restrict__ bv, float* __restrict__ b) {
    int i = blockIdx.x * 256 + threadIdx.x;
    if (i < NQD) b[i] = bq[i];
    else if (i < NQD + NKD) b[i] = bk[i - NQD];
    else if (i < NQKV) b[i] = bv[i - NQD - NKD];
}

// ---------------- mma.sync GEMM (bf16 3-term, QKV projection) ----------------
#define GBK 32
#define ROWP 40
#define STG_TILE (128*ROWP*2)          // 10240 B per operand tile
#define STG_BYTES (4*STG_TILE)         // 40960 B per stage
#define GEMM_SMEM (2*STG_BYTES)        // 81920 B

__global__ __launch_bounds__(256, 2)
void gemm_mma(const __nv_bfloat16* __restrict__ Ah, const __nv_bfloat16* __restrict__ Al,
              const __nv_bfloat16* __restrict__ Bh, const __nv_bfloat16* __restrict__ Bl,
              const float* __restrict__ bias, float* __restrict__ C, int K, int Ntot) {
    extern __shared__ char smem[];
    const uint32_t sb = smem_u32(smem);
    const int tid = threadIdx.x;
    const int lane = tid & 31;
    const int warp = tid >> 5;
    const int wm = (warp >> 2) * 64;
    const int wn = (warp & 3) * 32;
    const int row0 = blockIdx.y * 128;
    const int col0 = blockIdx.x * 128;
    const int NI = K / GBK;

    float acc[4][4][4];
#pragma unroll
    for (int mt = 0; mt < 4; mt++)
#pragma unroll
        for (int nt = 0; nt < 4; nt++)
#pragma unroll
            for (int i = 0; i < 4; i++) acc[mt][nt][i] = 0.f;

    auto issue_load = [&](int stage, int kb) {
        uint32_t sbase = sb + stage * STG_BYTES;
#pragma unroll
        for (int tile = 0; tile < 4; tile++) {
            const __nv_bfloat16* src =
                (tile == 0) ? Ah : (tile == 1) ? Al : (tile == 2) ? Bh : Bl;
            int gbase = (tile < 2) ? row0 : col0;
#pragma unroll
            for (int j = 0; j < 2; j++) {
                int s = j * 256 + tid;
                int row = s >> 2;
                int c = (s & 3) << 3;
                const void* g = src + (size_t)(gbase + row) * K + kb + c;
                uint32_t dst = sbase + tile * STG_TILE + (row * ROWP + c) * 2;
                cp_async16(dst, g);
            }
        }
        asm volatile("cp.async.commit_group;" ::: "memory");
    };

    issue_load(0, 0);

    for (int i = 0; i < NI; i++) {
        if (i + 1 < NI) {
            issue_load((i + 1) & 1, (i + 1) * GBK);
            asm volatile("cp.async.wait_group 1;" ::: "memory");
        } else {
            asm volatile("cp.async.wait_group 0;" ::: "memory");
        }
        __syncthreads();

        const uint32_t sa = sb + (i & 1) * STG_BYTES;
#pragma unroll
        for (int ks = 0; ks < 2; ks++) {
            uint32_t bh[4][2], bl[4][2];
#pragma unroll
            for (int np = 0; np < 2; np++) {
                uint32_t addr = sa + 2 * STG_TILE +
                    ((wn + np * 16 + ((lane >> 4) << 3) + (lane & 7)) * ROWP
                     + ks * 16 + (((lane >> 3) & 1) << 3)) * 2;
                ldm_x4(&bh[np * 2][0], addr);
                ldm_x4(&bl[np * 2][0], addr + STG_TILE);
            }
#pragma unroll
            for (int mt = 0; mt < 4; mt++) {
                uint32_t ah[4], al[4];
                uint32_t addr = sa +
                    ((wm + mt * 16 + (lane & 15)) * ROWP + ks * 16 + ((lane >> 4) << 3)) * 2;
                ldm_x4(ah, addr);
                ldm_x4(al, addr + STG_TILE);
#pragma unroll
                for (int nt = 0; nt < 4; nt++) {
                    mma_bf16(acc[mt][nt], ah, bh[nt]);
                    mma_bf16(acc[mt][nt], ah, bl[nt]);
                    mma_bf16(acc[mt][nt], al, bh[nt]);
                }
            }
        }
        __syncthreads();
    }

#pragma unroll
    for (int mt = 0; mt < 4; mt++) {
#pragma unroll
        for (int nt = 0; nt < 4; nt++) {
            int r = row0 + wm + mt * 16 + (lane >> 2);
            int cidx = col0 + wn + nt * 8 + ((lane & 3) << 1);
            float b0 = bias[cidx], b1 = bias[cidx + 1];
            float2* p0 = (float2*)(C + (size_t)r * Ntot + cidx);
            float2* p1 = (float2*)(C + (size_t)(r + 8) * Ntot + cidx);
            *p0 = make_float2(acc[mt][nt][0] + b0, acc[mt][nt][1] + b1);
            *p1 = make_float2(acc[mt][nt][2] + b0, acc[mt][nt][3] + b1);
        }
    }
}

// ---------------- mma.sync GEMM (fp16 2-term, O projection) ----------------
#define STG2_BYTES (3*STG_TILE)        // 30720 B per stage (Ah, Al, B)
#define GEMM2_SMEM (2*STG2_BYTES)      // 61440 B

__global__ __launch_bounds__(256, 2)
void gemm_f16_2t(const __half* __restrict__ Ah, const __half* __restrict__ Al,
                 const __half* __restrict__ B,
                 float* __restrict__ C, int K, int Ntot) {
    extern __shared__ char smem[];
    const uint32_t sb = smem_u32(smem);
    const int tid = threadIdx.x;
    const int lane = tid & 31;
    const int warp = tid >> 5;
    const int wm = (warp >> 2) * 64;
    const int wn = (warp & 3) * 32;
    const int row0 = blockIdx.y * 128;
    const int col0 = blockIdx.x * 128;
    const int NI = K / GBK;

    float acc[4][4][4];
#pragma unroll
    for (int mt = 0; mt < 4; mt++)
#pragma unroll
        for (int nt = 0; nt < 4; nt++)
#pragma unroll
            for (int i = 0; i < 4; i++) acc[mt][nt][i] = 0.f;

    auto issue_load = [&](int stage, int kb) {
        uint32_t sbase = sb + stage * STG2_BYTES;
#pragma unroll
        for (int tile = 0; tile < 3; tile++) {
            const __half* src = (tile == 0) ? Ah : (tile == 1) ? Al : B;
            int gbase = (tile < 2) ? row0 : col0;
#pragma unroll
            for (int j = 0; j < 2; j++) {
                int s = j * 256 + tid;
                int row = s >> 2;
                int c = (s & 3) << 3;
                const void* g = src + (size_t)(gbase + row) * K + kb + c;
                uint32_t dst = sbase + tile * STG_TILE + (row * ROWP + c) * 2;
                cp_async16(dst, g);
            }
        }
        asm volatile("cp.async.commit_group;" ::: "memory");
    };

    issue_load(0, 0);

    for (int i = 0; i < NI; i++) {
        if (i + 1 < NI) {
            issue_load((i + 1) & 1, (i + 1) * GBK);
            asm volatile("cp.async.wait_group 1;" ::: "memory");
        } else {
            asm volatile("cp.async.wait_group 0;" ::: "memory");
        }
        __syncthreads();

        const uint32_t sa = sb + (i & 1) * STG2_BYTES;
#pragma unroll
        for (int ks = 0; ks < 2; ks++) {
            uint32_t bh[4][2];
#pragma unroll
            for (int np = 0; np < 2; np++) {
                uint32_t addr = sa + 2 * STG_TILE +
                    ((wn + np * 16 + ((lane >> 4) << 3) + (lane & 7)) * ROWP
                     + ks * 16 + (((lane >> 3) & 1) << 3)) * 2;
                ldm_x4(&bh[np * 2][0], addr);
            }
#pragma unroll
            for (int mt = 0; mt < 4; mt++) {
                uint32_t ah[4], al[4];
                uint32_t addr = sa +
                    ((wm + mt * 16 + (lane & 15)) * ROWP + ks * 16 + ((lane >> 4) << 3)) * 2;
                ldm_x4(ah, addr);
                ldm_x4(al, addr + STG_TILE);
#pragma unroll
                for (int nt = 0; nt < 4; nt++) {
                    mma_f16(acc[mt][nt], ah, bh[nt]);
                    mma_f16(acc[mt][nt], al, bh[nt]);
                }
            }
        }
        __syncthreads();
    }

#pragma unroll
    for (int mt = 0; mt < 4; mt++) {
#pragma unroll
        for (int nt = 0; nt < 4; nt++) {
            int r = row0 + wm + mt * 16 + (lane >> 2);
            int cidx = col0 + wn + nt * 8 + ((lane & 3) << 1);
            float2* p0 = (float2*)(C + (size_t)r * Ntot + cidx);
            float2* p1 = (float2*)(C + (size_t)(r + 8) * Ntot + cidx);
            *p0 = make_float2(acc[mt][nt][0], acc[mt][nt][1]);
            *p1 = make_float2(acc[mt][nt][2], acc[mt][nt][3]);
        }
    }
}

// ---------------- fused mROPE + fp16 split ----------------
// q -> fp16 hi/lo (scaled), k -> fp16 single, v -> fp16 hi/lo
__global__ __launch_bounds__(256)
void rope_split_kernel(const float* __restrict__ qkv,
                       const float* __restrict__ cosp, const float* __restrict__ sinp,
                       __half* __restrict__ qh, __half* __restrict__ ql,
                       __half* __restrict__ k16,
                       __half* __restrict__ vh, __half* __restrict__ vl) {
    const int s = blockIdx.x;
    const int lane = threadIdx.x & 31;
    const int grp = threadIdx.x >> 5;     // 0..7
    const int da = 2 * lane;              // even, 0..62
    const int sec = (da < 16) ? 0 : ((da < 40) ? 1 : 2);
    const int SH = S_LEN * HD;
    const float scale = 0.08838834764831845f;   // 1/sqrt(128)

    const float2 c1 = *(const float2*)(cosp + sec * SH + s * HD + da);
    const float2 s1 = *(const float2*)(sinp + sec * SH + s * HD + da);
    const float2 c2 = *(const float2*)(cosp + sec * SH + s * HD + da + 64);
    const float2 s2 = *(const float2*)(sinp + sec * SH + s * HD + da + 64);

    const float* row = qkv + (size_t)s * NQKV;

    auto store2h = [](__half* H, __half* L, size_t o, float a, float b) {
        __half ha = __float2half_rn(a), hb = __float2half_rn(b);
        *(__half2*)(H + o) = __halves2half2(ha, hb);
        *(__half2*)(L + o) = __floats2half2_rn(a - __half2float(ha), b - __half2float(hb));
    };

#pragma unroll 1
    for (int it = 0; it < 5; it++) {
        int hh = it * 8 + grp;    // 0..39, valid < 36
        if (hh >= NH + 2 * NKV) break;
        if (hh < NH) {
            const float* base = row + hh * HD;
            float2 x1 = *(const float2*)(base + da);
            float2 x2 = *(const float2*)(base + da + 64);
            size_t o = (size_t)s * NQD + hh * HD;
            store2h(qh, ql, o + da,      (x1.x * c1.x - x2.x * s1.x) * scale,
                                         (x1.y * c1.y - x2.y * s1.y) * scale);
            store2h(qh, ql, o + da + 64, (x2.x * c2.x + x1.x * s2.x) * scale,
                                         (x2.y * c2.y + x1.y * s2.y) * scale);
        } else if (hh < NH + NKV) {
            int kvi = hh - NH;
            const float* base = row + NQD + kvi * HD;
            float2 x1 = *(const float2*)(base + da);
            float2 x2 = *(const float2*)(base + da + 64);
            size_t o = (size_t)s * NKD + kvi * HD;
            *(__half2*)(k16 + o + da)      = __floats2half2_rn(x1.x * c1.x - x2.x * s1.x,
                                                               x1.y * c1.y - x2.y * s1.y);
            *(__half2*)(k16 + o + da + 64) = __floats2half2_rn(x2.x * c2.x + x1.x * s2.x,
                                                               x2.y * c2.y + x1.y * s2.y);
        } else {
            int kvi = hh - NH - NKV;
            const float* base = row + NQD + NKD + kvi * HD;
            float2 x1 = *(const float2*)(base + da);
            float2 x2 = *(const float2*)(base + da + 64);
            size_t o = (size_t)s * NKD + kvi * HD;
            store2h(vh, vl, o + da,      x1.x, x1.y);
            store2h(vh, vl, o + da + 64, x2.x, x2.y);
        }
    }
}

// ---------------- attention: fp16 mma flash, QK 2-term / PV 2-term ----------------
#define ATP 136
#define AT_ROWB (ATP*2)              // 272 B/row
#define AQ_TILE (128*AT_ROWB)        // 34816
#define KV_TILE (32*AT_ROWB)         // 8704
#define KV_STG  (3*KV_TILE)          // 26112 (K, Vh, Vl)
#define AQ_H 0
#define AQ_L AQ_TILE
#define AKV  (2*AQ_TILE)
#define ATTN_SMEM (AKV + 2*KV_STG)   // 121856 B

__global__ __launch_bounds__(256)
void attn_mma(const __half* __restrict__ qh, const __half* __restrict__ ql,
              const __half* __restrict__ k16,
              const __half* __restrict__ vh, const __half* __restrict__ vl,
              __half* __restrict__ ctxh, __half* __restrict__ ctxl) {
    extern __shared__ char smem[];
    const uint32_t sb = smem_u32(smem);
    const int tid = threadIdx.x;
    const int lane = tid & 31;
    const int warp = tid >> 5;           // 0..7
    const int h = blockIdx.y;
    const int kvh = h / GRP;
    const int r0 = blockIdx.x * 128;

    // ---- Q tile (128 x 128) hi/lo ----
#pragma unroll
    for (int j = 0; j < 8; j++) {
        int idx = j * 256 + tid;          // 0..2047
        int row = idx >> 4, c = idx & 15;
        size_t g = (size_t)(r0 + row) * NQD + h * HD + c * 8;
        uint32_t so = row * AT_ROWB + c * 16;
        cp_async16(sb + AQ_H + so, qh + g);
        cp_async16(sb + AQ_L + so, ql + g);
    }
    asm volatile("cp.async.commit_group;" ::: "memory");

    auto issue_kv = [&](int stage, int kt) {
        uint32_t base = sb + AKV + stage * KV_STG;
#pragma unroll
        for (int j = 0; j < 2; j++) {
            int idx = j * 256 + tid;      // 0..511
            int row = idx >> 4, c = idx & 15;
            size_t g = (size_t)(kt + row) * NKD + kvh * HD + c * 8;
            uint32_t so = row * AT_ROWB + c * 16;
            cp_async16(base + 0 * KV_TILE + so, k16 + g);
            cp_async16(base + 1 * KV_TILE + so, vh + g);
            cp_async16(base + 2 * KV_TILE + so, vl + g);
        }
        asm volatile("cp.async.commit_group;" ::: "memory");
    };

    issue_kv(0, 0);
    asm volatile("cp.async.wait_group 1;" ::: "memory");   // Q done (kv0 may pend)
    __syncthreads();

    // ---- Q fragments (warp owns rows [warp*16, warp*16+16)) ----
    uint32_t qfh[8][4], qfl[8][4];
#pragma unroll
    for (int kf = 0; kf < 8; kf++) {
        uint32_t off = ((warp * 16 + (lane & 15)) * ATP + kf * 16 + ((lane >> 4) << 3)) * 2;
        ldm_x4(qfh[kf], sb + AQ_H + off);
        ldm_x4(qfl[kf], sb + AQ_L + off);
    }

    float o[16][4];
#pragma unroll
    for (int nt = 0; nt < 16; nt++)
#pragma unroll
        for (int i = 0; i < 4; i++) o[nt][i] = 0.f;
    float m0 = -INFINITY, m1 = -INFINITY, l0 = 0.f, l1 = 0.f;

    const int NI = S_LEN / 32;            // 64

    for (int it = 0; it < NI; it++) {
        if (it + 1 < NI) {
            issue_kv((it + 1) & 1, (it + 1) * 32);
            asm volatile("cp.async.wait_group 1;" ::: "memory");
        } else {
            asm volatile("cp.async.wait_group 0;" ::: "memory");
        }
        __syncthreads();

        const uint32_t sk = sb + AKV + (it & 1) * KV_STG;

        // ---- S = Q K^T (2-term: Qh*K + Ql*K) ----
        float s[4][4];
#pragma unroll
        for (int nt = 0; nt < 4; nt++)
#pragma unroll
            for (int i = 0; i < 4; i++) s[nt][i] = 0.f;

#pragma unroll
        for (int kf = 0; kf < 8; kf++) {
            uint32_t kb[4][2];
#pragma unroll
            for (int np = 0; np < 2; np++) {
                uint32_t addr = sk +
                    ((np * 16 + ((lane >> 4) << 3) + (lane & 7)) * ATP
                     + kf * 16 + (((lane >> 3) & 1) << 3)) * 2;
                ldm_x4(&kb[np * 2][0], addr);
            }
#pragma unroll
            for (int nt = 0; nt < 4; nt++) {
                mma_f16(s[nt], qfh[kf], kb[nt]);
                mma_f16(s[nt], qfl[kf], kb[nt]);
            }
        }

        // ---- online softmax ----
        float mx0 = -INFINITY, mx1 = -INFINITY;
#pragma unroll
        for (int nt = 0; nt < 4; nt++) {
            mx0 = fmaxf(mx0, fmaxf(s[nt][0], s[nt][1]));
            mx1 = fmaxf(mx1, fmaxf(s[nt][2], s[nt][3]));
        }
        mx0 = fmaxf(mx0, __shfl_xor_sync(0xffffffffu, mx0, 1));
        mx0 = fmaxf(mx0, __shfl_xor_sync(0xffffffffu, mx0, 2));
        mx1 = fmaxf(mx1, __shfl_xor_sync(0xffffffffu, mx1, 1));
        mx1 = fmaxf(mx1, __shfl_xor_sync(0xffffffffu, mx1, 2));

        float nm0 = fmaxf(m0, mx0), nm1 = fmaxf(m1, mx1);
        float c0 = __expf(m0 - nm0), c1 = __expf(m1 - nm1);
        m0 = nm0; m1 = nm1;

        float sum0 = 0.f, sum1 = 0.f;
#pragma unroll
        for (int nt = 0; nt < 4; nt++) {
            s[nt][0] = __expf(s[nt][0] - nm0);
            s[nt][1] = __expf(s[nt][1] - nm0);
            s[nt][2] = __expf(s[nt][2] - nm1);
            s[nt][3] = __expf(s[nt][3] - nm1);
            sum0 += s[nt][0] + s[nt][1];
            sum1 += s[nt][2] + s[nt][3];
        }
        sum0 += __shfl_xor_sync(0xffffffffu, sum0, 1);
        sum0 += __shfl_xor_sync(0xffffffffu, sum0, 2);
        sum1 += __shfl_xor_sync(0xffffffffu, sum1, 1);
        sum1 += __shfl_xor_sync(0xffffffffu, sum1, 2);
        l0 = l0 * c0 + sum0;
        l1 = l1 * c1 + sum1;

#pragma unroll
        for (int nt = 0; nt < 16; nt++) {
            o[nt][0] *= c0; o[nt][1] *= c0;
            o[nt][2] *= c1; o[nt][3] *= c1;
        }

        // ---- O += P V (2-term: P*Vh + P*Vl; P single fp16) ----
#pragma unroll
        for (int kf = 0; kf < 2; kf++) {
            uint32_t ah[4];
#pragma unroll
            for (int half = 0; half < 2; half++) {
                int nt = 2 * kf + half;
                ah[2 * half]     = pack_h2(s[nt][0], s[nt][1]);
                ah[2 * half + 1] = pack_h2(s[nt][2], s[nt][3]);
            }
#pragma unroll
            for (int np = 0; np < 8; np++) {
                uint32_t vbh[4], vbl[4];
                uint32_t addr = sk + 1 * KV_TILE +
                    ((kf * 16 + (lane & 15)) * ATP + np * 16 + ((lane >> 4) << 3)) * 2;
                ldm_x4_t(vbh, addr);
                ldm_x4_t(vbl, addr + KV_TILE);
                mma_f16(o[2 * np],     ah, &vbh[0]);
                mma_f16(o[2 * np],     ah, &vbl[0]);
                mma_f16(o[2 * np + 1], ah, &vbh[2]);
                mma_f16(o[2 * np + 1], ah, &vbl[2]);
            }
        }
        __syncthreads();
    }

    // ---- epilogue: ctx as fp16 hi/lo (feeds fp16 2-term O projection) ----
    float inv0 = 1.f / l0, inv1 = 1.f / l1;
    int r_lo = r0 + warp * 16 + (lane >> 2);
    int r_hi = r_lo + 8;
#pragma unroll
    for (int nt = 0; nt < 16; nt++) {
        int col = h * HD + nt * 8 + ((lane & 3) << 1);
        {
            float x0 = o[nt][0] * inv0, x1 = o[nt][1] * inv0;
            __half2 ph = __floats2half2_rn(x0, x1);
            __half2 pl = __floats2half2_rn(x0 - __half2float(__low2half(ph)),
                                           x1 - __half2float(__high2half(ph)));
            *(__half2*)(ctxh + (size_t)r_lo * NQD + col) = ph;
            *(__half2*)(ctxl + (size_t)r_lo * NQD + col) = pl;
        }
        {
            float x0 = o[nt][2] * inv1, x1 = o[nt][3] * inv1;
            __half2 ph = __floats2half2_rn(x0, x1);
            __half2 pl = __floats2half2_rn(x0 - __half2float(__low2half(ph)),
                                           x1 - __half2float(__high2half(ph)));
            *(__half2*)(ctxh + (size_t)r_hi * NQD + col) = ph;
            *(__half2*)(ctxl + (size_t)r_hi * NQD + col) = pl;
        }
    }
}

// ---------------- launch ----------------
extern "C" void kernel_launch(void* const* d_in, const int* in_sizes, int n_in,
                              void* d_out, int out_size) {
    const float* hs   = (const float*)d_in[0];
    const float* cosp = (const float*)d_in[1];
    const float* sinp = (const float*)d_in[2];
    const float* Wq   = (const float*)d_in[3];
    const float* bq   = (const float*)d_in[4];
    const float* Wk   = (const float*)d_in[5];
    const float* bk   = (const float*)d_in[6];
    const float* Wv   = (const float*)d_in[7];
    const float* bv   = (const float*)d_in[8];
    const float* Wo   = (const float*)d_in[9];
    float* out = (float*)d_out;

    float *qkv_p, *bias_p;
    cudaGetSymbolAddress((void**)&qkv_p,  g_qkv);
    cudaGetSymbolAddress((void**)&bias_p, g_bias);

    __nv_bfloat16 *hsh, *hsl, *wh, *wl;
    __half *ctxh, *ctxl, *wo16, *q16h, *q16l, *k16, *v16h, *v16l;
    cudaGetSymbolAddress((void**)&hsh,  g_hsh);  cudaGetSymbolAddress((void**)&hsl,  g_hsl);
    cudaGetSymbolAddress((void**)&ctxh, g_ctxh); cudaGetSymbolAddress((void**)&ctxl, g_ctxl);
    cudaGetSymbolAddress((void**)&wh,   g_wh);   cudaGetSymbolAddress((void**)&wl,   g_wl);
    cudaGetSymbolAddress((void**)&wo16, g_wo16);
    cudaGetSymbolAddress((void**)&q16h, g_q16h); cudaGetSymbolAddress((void**)&q16l, g_q16l);
    cudaGetSymbolAddress((void**)&k16,  g_k16);
    cudaGetSymbolAddress((void**)&v16h, g_v16h); cudaGetSymbolAddress((void**)&v16l, g_v16l);

    cudaFuncSetAttribute(gemm_mma,    cudaFuncAttributeMaxDynamicSharedMemorySize, GEMM_SMEM);
    cudaFuncSetAttribute(gemm_f16_2t, cudaFuncAttributeMaxDynamicSharedMemorySize, GEMM2_SMEM);
    cudaFuncSetAttribute(attn_mma,    cudaFuncAttributeMaxDynamicSharedMemorySize, ATTN_SMEM);

    // 1) input split + weight transposes/splits + bias concat
    {
        int n4 = S_LEN * HID / 4;
        split_kernel<<<(n4 + 255) / 256, 256>>>((const float4*)hs, (__nv_bfloat162*)hsh, (__nv_bfloat162*)hsl, n4);
    }
    {
        dim3 blk(32, 8);
        tsplit2_kernel<<<dim3(NQD / 32, HID / 64), blk>>>(Wq, wh, wl, HID, NQD);
        tsplit2_kernel<<<dim3(NKD / 32, HID / 64), blk>>>(Wk, wh + (size_t)NQD * HID, wl + (size_t)NQD * HID, HID, NKD);
        tsplit2_kernel<<<dim3(NKD / 32, HID / 64), blk>>>(Wv, wh + (size_t)(NQD + NKD) * HID, wl + (size_t)(NQD + NKD) * HID, HID, NKD);
        tsplit2h_kernel<<<dim3(HID / 32, NQD / 64), blk>>>(Wo, wo16, NQD, HID);
        concat_bias_kernel<<<(NQKV + 255) / 256, 256>>>(bq, bk, bv, bias_p);
    }

    // 2) fused QKV projection (bf16 3-term)
    gemm_mma<<<dim3(NQKV / 128, S_LEN / 128), 256, GEMM_SMEM>>>(hsh, hsl, wh, wl, bias_p, qkv_p, HID, NQKV);

    // 3) fused mROPE + fp16 split (scale folded into q; k single fp16)
    rope_split_kernel<<<S_LEN, 256>>>(qkv_p, cosp, sinp, q16h, q16l, k16, v16h, v16l);

    // 4) attention -> ctx (fp16 hi/lo)
    {
        dim3 grid(S_LEN / 128, NH);
        attn_mma<<<grid, 256, ATTN_SMEM>>>(q16h, q16l, k16, v16h, v16l, ctxh, ctxl);
    }

    // 5) output projection (fp16 2-term)
    gemm_f16_2t<<<dim3(HID / 128, S_LEN / 128), 256, GEMM2_SMEM>>>(ctxh, ctxl, wo16, out, NQD, HID);
}

// round 11
// speedup vs baseline: 4.9813x; 1.1635x over previous
#include <cuda_runtime.h>
#include <cuda_fp16.h>
#include <math.h>
#include <stdint.h>

// ---------------- problem constants ----------------
#define S_LEN 2048
#define HID   3584
#define NH    28
#define NKV   4
#define HD    128
#define NQD   (NH*HD)    // 3584
#define NKD   (NKV*HD)   // 512
#define GRP   (NH/NKV)   // 7
#define NQKV  (NQD + 2*NKD)  // 4608

// ---------------- scratch (device globals; no allocs allowed) ----------------
__device__ float g_qkv[(size_t)S_LEN * NQKV];
__device__ float g_bias[NQKV];

__device__ __align__(16) __half g_hsh[S_LEN * HID],  g_hsl[S_LEN * HID];
__device__ __align__(16) __half g_ctxh[S_LEN * NQD], g_ctxl[S_LEN * NQD];
__device__ __align__(16) __half g_q16h[S_LEN * NQD], g_q16l[S_LEN * NQD];
__device__ __align__(16) __half g_k16[S_LEN * NKD];
__device__ __align__(16) __half g_v16h[S_LEN * NKD], g_v16l[S_LEN * NKD];
__device__ __align__(16) __half g_w16[(size_t)NQKV * HID];
__device__ __align__(16) __half g_wo16[(size_t)HID * NQD];

// ---------------- helpers ----------------
__device__ __forceinline__ uint32_t smem_u32(const void* p) {
    uint32_t a;
    asm("{ .reg .u64 t; cvta.to.shared.u64 t, %1; cvt.u32.u64 %0, t; }" : "=r"(a) : "l"(p));
    return a;
}

__device__ __forceinline__ void cp_async16(uint32_t dst, const void* src) {
    asm volatile("cp.async.cg.shared.global [%0], [%1], 16;" :: "r"(dst), "l"(src) : "memory");
}

__device__ __forceinline__ void ldm_x4(uint32_t* r, uint32_t addr) {
    asm volatile("ldmatrix.sync.aligned.m8n8.x4.shared.b16 {%0,%1,%2,%3}, [%4];"
                 : "=r"(r[0]), "=r"(r[1]), "=r"(r[2]), "=r"(r[3]) : "r"(addr));
}

__device__ __forceinline__ void ldm_x4_t(uint32_t* r, uint32_t addr) {
    asm volatile("ldmatrix.sync.aligned.m8n8.x4.trans.shared.b16 {%0,%1,%2,%3}, [%4];"
                 : "=r"(r[0]), "=r"(r[1]), "=r"(r[2]), "=r"(r[3]) : "r"(addr));
}

__device__ __forceinline__ void mma_f16(float* c, const uint32_t* a, const uint32_t* b) {
    asm volatile(
        "mma.sync.aligned.m16n8k16.row.col.f32.f16.f16.f32 "
        "{%0,%1,%2,%3}, {%4,%5,%6,%7}, {%8,%9}, {%0,%1,%2,%3};"
        : "+f"(c[0]), "+f"(c[1]), "+f"(c[2]), "+f"(c[3])
        : "r"(a[0]), "r"(a[1]), "r"(a[2]), "r"(a[3]), "r"(b[0]), "r"(b[1]));
}

__device__ __forceinline__ uint32_t pack_h2(float a, float b) {
    __half2 h = __floats2half2_rn(a, b);
    return *(uint32_t*)&h;
}

// ---------------- split kernels ----------------
// fp32 -> fp16 hi/lo (hi+lo reconstructs fp32 to ~2^-22)
__global__ void split_h_kernel(const float4* __restrict__ X, __half2* __restrict__ H,
                               __half2* __restrict__ L, int n4) {
    int i = blockIdx.x * 256 + threadIdx.x;
    if (i >= n4) return;
    float4 x = X[i];
    __half h0 = __float2half_rn(x.x), h1 = __float2half_rn(x.y);
    __half h2 = __float2half_rn(x.z), h3 = __float2half_rn(x.w);
    H[2*i]   = __halves2half2(h0, h1);
    H[2*i+1] = __halves2half2(h2, h3);
    L[2*i]   = __floats2half2_rn(x.x - __half2float(h0), x.y - __half2float(h1));
    L[2*i+1] = __floats2half2_rn(x.z - __half2float(h2), x.w - __half2float(h3));
}

// W [K,N] fp32 row-major -> T [N,K] fp16 (single). Tile 32n x 64k, block (32,8).
__global__ void tsplit2h_kernel(const float* __restrict__ W, __half* __restrict__ T,
                                int K, int N) {
    __shared__ float t[64][33];
    int n0 = blockIdx.x * 32, k0 = blockIdx.y * 64;
    int tx = threadIdx.x, ty = threadIdx.y;
#pragma unroll
    for (int i = 0; i < 8; i++) {
        int k = i * 8 + ty;
        t[k][tx] = W[(size_t)(k0 + k) * N + n0 + tx];
    }
    __syncthreads();
#pragma unroll
    for (int i = 0; i < 4; i++) {
        int n = i * 8 + ty;
        __half2 hp = __floats2half2_rn(t[2 * tx][n], t[2 * tx + 1][n]);
        *(__half2*)(T + (size_t)(n0 + n) * K + k0 + 2 * tx) = hp;
    }
}

__global__ void concat_bias_kernel(const float* __restrict__ bq, const float* __restrict__ bk,
                                   const float* __restrict__ bv, float* __restrict__ b) {
    int i = blockIdx.x * 256 + threadIdx.x;
    if (i < NQD) b[i] = bq[i];
    else if (i < NQD + NKD) b[i] = bk[i - NQD];
    else if (i < NQKV) b[i] = bv[i - NQD - NKD];
}

// ---------------- unified mma.sync GEMM (fp16 2-term: (Ah+Al) x B) ----------------
// CTA tile 128x128, BK=32, 8 warps (2m x 4n), 3-stage cp.async pipeline, 1 sync/iter.
#define GBK 32
#define ROWP 40
#define STG_TILE (128*ROWP*2)          // 10240 B per operand tile
#define STG2_BYTES (3*STG_TILE)        // 30720 B per stage (Ah, Al, B)
#define GEMM2_SMEM (3*STG2_BYTES)      // 92160 B (3 stages)

__global__ __launch_bounds__(256, 2)
void gemm_f16_2t(const __half* __restrict__ Ah, const __half* __restrict__ Al,
                 const __half* __restrict__ B, const float* __restrict__ bias,
                 float* __restrict__ C, int K, int Ntot) {
    extern __shared__ char smem[];
    const uint32_t sb = smem_u32(smem);
    const int tid = threadIdx.x;
    const int lane = tid & 31;
    const int warp = tid >> 5;
    const int wm = (warp >> 2) * 64;
    const int wn = (warp & 3) * 32;
    const int row0 = blockIdx.y * 128;
    const int col0 = blockIdx.x * 128;
    const int NI = K / GBK;

    float acc[4][4][4];
#pragma unroll
    for (int mt = 0; mt < 4; mt++)
#pragma unroll
        for (int nt = 0; nt < 4; nt++)
#pragma unroll
            for (int i = 0; i < 4; i++) acc[mt][nt][i] = 0.f;

    auto issue_load = [&](int stage, int kb) {
        uint32_t sbase = sb + stage * STG2_BYTES;
#pragma unroll
        for (int tile = 0; tile < 3; tile++) {
            const __half* src = (tile == 0) ? Ah : (tile == 1) ? Al : B;
            int gbase = (tile < 2) ? row0 : col0;
#pragma unroll
            for (int j = 0; j < 2; j++) {
                int s = j * 256 + tid;
                int row = s >> 2;
                int c = (s & 3) << 3;
                const void* g = src + (size_t)(gbase + row) * K + kb + c;
                uint32_t dst = sbase + tile * STG_TILE + (row * ROWP + c) * 2;
                cp_async16(dst, g);
            }
        }
        asm volatile("cp.async.commit_group;" ::: "memory");
    };

    issue_load(0, 0);
    issue_load(1, GBK);

    int stage = 0;
    for (int i = 0; i < NI; i++) {
        if (i + 1 < NI) {
            asm volatile("cp.async.wait_group 1;" ::: "memory");
        } else {
            asm volatile("cp.async.wait_group 0;" ::: "memory");
        }
        __syncthreads();   // (a) stage i visible block-wide; (b) compute(i-1) done block-wide
        if (i + 2 < NI) {
            int nstage = stage + 2; if (nstage >= 3) nstage -= 3;
            issue_load(nstage, (i + 2) * GBK);
        }

        const uint32_t sa = sb + stage * STG2_BYTES;
#pragma unroll
        for (int ks = 0; ks < 2; ks++) {
            uint32_t bh[4][2];
#pragma unroll
            for (int np = 0; np < 2; np++) {
                uint32_t addr = sa + 2 * STG_TILE +
                    ((wn + np * 16 + ((lane >> 4) << 3) + (lane & 7)) * ROWP
                     + ks * 16 + (((lane >> 3) & 1) << 3)) * 2;
                ldm_x4(&bh[np * 2][0], addr);
            }
#pragma unroll
            for (int mt = 0; mt < 4; mt++) {
                uint32_t ah[4], al[4];
                uint32_t addr = sa +
                    ((wm + mt * 16 + (lane & 15)) * ROWP + ks * 16 + ((lane >> 4) << 3)) * 2;
                ldm_x4(ah, addr);
                ldm_x4(al, addr + STG_TILE);
#pragma unroll
                for (int nt = 0; nt < 4; nt++) {
                    mma_f16(acc[mt][nt], ah, bh[nt]);
                    mma_f16(acc[mt][nt], al, bh[nt]);
                }
            }
        }
        if (++stage == 3) stage = 0;
    }

#pragma unroll
    for (int mt = 0; mt < 4; mt++) {
#pragma unroll
        for (int nt = 0; nt < 4; nt++) {
            int r = row0 + wm + mt * 16 + (lane >> 2);
            int cidx = col0 + wn + nt * 8 + ((lane & 3) << 1);
            float b0 = 0.f, b1 = 0.f;
            if (bias) { b0 = bias[cidx]; b1 = bias[cidx + 1]; }
            float2* p0 = (float2*)(C + (size_t)r * Ntot + cidx);
            float2* p1 = (float2*)(C + (size_t)(r + 8) * Ntot + cidx);
            *p0 = make_float2(acc[mt][nt][0] + b0, acc[mt][nt][1] + b1);
            *p1 = make_float2(acc[mt][nt][2] + b0, acc[mt][nt][3] + b1);
        }
    }
}

// ---------------- fused mROPE + fp16 split ----------------
// q -> fp16 hi/lo (scaled), k -> fp16 single, v -> fp16 hi/lo
__global__ __launch_bounds__(256)
void rope_split_kernel(const float* __restrict__ qkv,
                       const float* __restrict__ cosp, const float* __restrict__ sinp,
                       __half* __restrict__ qh, __half* __restrict__ ql,
                       __half* __restrict__ k16,
                       __half* __restrict__ vh, __half* __restrict__ vl) {
    const int s = blockIdx.x;
    const int lane = threadIdx.x & 31;
    const int grp = threadIdx.x >> 5;     // 0..7
    const int da = 2 * lane;              // even, 0..62
    const int sec = (da < 16) ? 0 : ((da < 40) ? 1 : 2);
    const int SH = S_LEN * HD;
    const float scale = 0.08838834764831845f;   // 1/sqrt(128)

    const float2 c1 = *(const float2*)(cosp + sec * SH + s * HD + da);
    const float2 s1 = *(const float2*)(sinp + sec * SH + s * HD + da);
    const float2 c2 = *(const float2*)(cosp + sec * SH + s * HD + da + 64);
    const float2 s2 = *(const float2*)(sinp + sec * SH + s * HD + da + 64);

    const float* row = qkv + (size_t)s * NQKV;

    auto store2h = [](__half* H, __half* L, size_t o, float a, float b) {
        __half ha = __float2half_rn(a), hb = __float2half_rn(b);
        *(__half2*)(H + o) = __halves2half2(ha, hb);
        *(__half2*)(L + o) = __floats2half2_rn(a - __half2float(ha), b - __half2float(hb));
    };

#pragma unroll 1
    for (int it = 0; it < 5; it++) {
        int hh = it * 8 + grp;    // 0..39, valid < 36
        if (hh >= NH + 2 * NKV) break;
        if (hh < NH) {
            const float* base = row + hh * HD;
            float2 x1 = *(const float2*)(base + da);
            float2 x2 = *(const float2*)(base + da + 64);
            size_t o = (size_t)s * NQD + hh * HD;
            store2h(qh, ql, o + da,      (x1.x * c1.x - x2.x * s1.x) * scale,
                                         (x1.y * c1.y - x2.y * s1.y) * scale);
            store2h(qh, ql, o + da + 64, (x2.x * c2.x + x1.x * s2.x) * scale,
                                         (x2.y * c2.y + x1.y * s2.y) * scale);
        } else if (hh < NH + NKV) {
            int kvi = hh - NH;
            const float* base = row + NQD + kvi * HD;
            float2 x1 = *(const float2*)(base + da);
            float2 x2 = *(const float2*)(base + da + 64);
            size_t o = (size_t)s * NKD + kvi * HD;
            *(__half2*)(k16 + o + da)      = __floats2half2_rn(x1.x * c1.x - x2.x * s1.x,
                                                               x1.y * c1.y - x2.y * s1.y);
            *(__half2*)(k16 + o + da + 64) = __floats2half2_rn(x2.x * c2.x + x1.x * s2.x,
                                                               x2.y * c2.y + x1.y * s2.y);
        } else {
            int kvi = hh - NH - NKV;
            const float* base = row + NQD + NKD + kvi * HD;
            float2 x1 = *(const float2*)(base + da);
            float2 x2 = *(const float2*)(base + da + 64);
            size_t o = (size_t)s * NKD + kvi * HD;
            store2h(vh, vl, o + da,      x1.x, x1.y);
            store2h(vh, vl, o + da + 64, x2.x, x2.y);
        }
    }
}

// ---------------- attention: fp16 mma flash, QK 2-term / PV 2-term ----------------
#define ATP 136
#define AT_ROWB (ATP*2)              // 272 B/row
#define AQ_TILE (128*AT_ROWB)        // 34816
#define KV_TILE (32*AT_ROWB)         // 8704
#define KV_STG  (3*KV_TILE)          // 26112 (K, Vh, Vl)
#define AQ_H 0
#define AQ_L AQ_TILE
#define AKV  (2*AQ_TILE)
#define ATTN_SMEM (AKV + 2*KV_STG)   // 121856 B

__global__ __launch_bounds__(256)
void attn_mma(const __half* __restrict__ qh, const __half* __restrict__ ql,
              const __half* __restrict__ k16,
              const __half* __restrict__ vh, const __half* __restrict__ vl,
              __half* __restrict__ ctxh, __half* __restrict__ ctxl) {
    extern __shared__ char smem[];
    const uint32_t sb = smem_u32(smem);
    const int tid = threadIdx.x;
    const int lane = tid & 31;
    const int warp = tid >> 5;           // 0..7
    const int h = blockIdx.y;
    const int kvh = h / GRP;
    const int r0 = blockIdx.x * 128;

    // ---- Q tile (128 x 128) hi/lo ----
#pragma unroll
    for (int j = 0; j < 8; j++) {
        int idx = j * 256 + tid;          // 0..2047
        int row = idx >> 4, c = idx & 15;
        size_t g = (size_t)(r0 + row) * NQD + h * HD + c * 8;
        uint32_t so = row * AT_ROWB + c * 16;
        cp_async16(sb + AQ_H + so, qh + g);
        cp_async16(sb + AQ_L + so, ql + g);
    }
    asm volatile("cp.async.commit_group;" ::: "memory");

    auto issue_kv = [&](int stage, int kt) {
        uint32_t base = sb + AKV + stage * KV_STG;
#pragma unroll
        for (int j = 0; j < 2; j++) {
            int idx = j * 256 + tid;      // 0..511
            int row = idx >> 4, c = idx & 15;
            size_t g = (size_t)(kt + row) * NKD + kvh * HD + c * 8;
            uint32_t so = row * AT_ROWB + c * 16;
            cp_async16(base + 0 * KV_TILE + so, k16 + g);
            cp_async16(base + 1 * KV_TILE + so, vh + g);
            cp_async16(base + 2 * KV_TILE + so, vl + g);
        }
        asm volatile("cp.async.commit_group;" ::: "memory");
    };

    issue_kv(0, 0);
    asm volatile("cp.async.wait_group 1;" ::: "memory");   // Q done (kv0 may pend)
    __syncthreads();

    // ---- Q fragments (warp owns rows [warp*16, warp*16+16)) ----
    uint32_t qfh[8][4], qfl[8][4];
#pragma unroll
    for (int kf = 0; kf < 8; kf++) {
        uint32_t off = ((warp * 16 + (lane & 15)) * ATP + kf * 16 + ((lane >> 4) << 3)) * 2;
        ldm_x4(qfh[kf], sb + AQ_H + off);
        ldm_x4(qfl[kf], sb + AQ_L + off);
    }

    float o[16][4];
#pragma unroll
    for (int nt = 0; nt < 16; nt++)
#pragma unroll
        for (int i = 0; i < 4; i++) o[nt][i] = 0.f;
    float m0 = -INFINITY, m1 = -INFINITY, l0 = 0.f, l1 = 0.f;

    const int NI = S_LEN / 32;            // 64

    for (int it = 0; it < NI; it++) {
        asm volatile("cp.async.wait_group 0;" ::: "memory");  // kv stage `it` landed
        __syncthreads();   // (a) stage visible; (b) compute(it-1) done block-wide
        if (it + 1 < NI) issue_kv((it + 1) & 1, (it + 1) * 32);

        const uint32_t sk = sb + AKV + (it & 1) * KV_STG;

        // ---- S = Q K^T (2-term: Qh*K + Ql*K) ----
        float s[4][4];
#pragma unroll
        for (int nt = 0; nt < 4; nt++)
#pragma unroll
            for (int i = 0; i < 4; i++) s[nt][i] = 0.f;

#pragma unroll
        for (int kf = 0; kf < 8; kf++) {
            uint32_t kb[4][2];
#pragma unroll
            for (int np = 0; np < 2; np++) {
                uint32_t addr = sk +
                    ((np * 16 + ((lane >> 4) << 3) + (lane & 7)) * ATP
                     + kf * 16 + (((lane >> 3) & 1) << 3)) * 2;
                ldm_x4(&kb[np * 2][0], addr);
            }
#pragma unroll
            for (int nt = 0; nt < 4; nt++) {
                mma_f16(s[nt], qfh[kf], kb[nt]);
                mma_f16(s[nt], qfl[kf], kb[nt]);
            }
        }

        // ---- online softmax ----
        float mx0 = -INFINITY, mx1 = -INFINITY;
#pragma unroll
        for (int nt = 0; nt < 4; nt++) {
            mx0 = fmaxf(mx0, fmaxf(s[nt][0], s[nt][1]));
            mx1 = fmaxf(mx1, fmaxf(s[nt][2], s[nt][3]));
        }
        mx0 = fmaxf(mx0, __shfl_xor_sync(0xffffffffu, mx0, 1));
        mx0 = fmaxf(mx0, __shfl_xor_sync(0xffffffffu, mx0, 2));
        mx1 = fmaxf(mx1, __shfl_xor_sync(0xffffffffu, mx1, 1));
        mx1 = fmaxf(mx1, __shfl_xor_sync(0xffffffffu, mx1, 2));

        float nm0 = fmaxf(m0, mx0), nm1 = fmaxf(m1, mx1);
        float c0 = __expf(m0 - nm0), c1 = __expf(m1 - nm1);
        m0 = nm0; m1 = nm1;

        float sum0 = 0.f, sum1 = 0.f;
#pragma unroll
        for (int nt = 0; nt < 4; nt++) {
            s[nt][0] = __expf(s[nt][0] - nm0);
            s[nt][1] = __expf(s[nt][1] - nm0);
            s[nt][2] = __expf(s[nt][2] - nm1);
            s[nt][3] = __expf(s[nt][3] - nm1);
            sum0 += s[nt][0] + s[nt][1];
            sum1 += s[nt][2] + s[nt][3];
        }
        sum0 += __shfl_xor_sync(0xffffffffu, sum0, 1);
        sum0 += __shfl_xor_sync(0xffffffffu, sum0, 2);
        sum1 += __shfl_xor_sync(0xffffffffu, sum1, 1);
        sum1 += __shfl_xor_sync(0xffffffffu, sum1, 2);
        l0 = l0 * c0 + sum0;
        l1 = l1 * c1 + sum1;

#pragma unroll
        for (int nt = 0; nt < 16; nt++) {
            o[nt][0] *= c0; o[nt][1] *= c0;
            o[nt][2] *= c1; o[nt][3] *= c1;
        }

        // ---- O += P V (2-term: P*Vh + P*Vl; P single fp16) ----
#pragma unroll
        for (int kf = 0; kf < 2; kf++) {
            uint32_t ah[4];
#pragma unroll
            for (int half = 0; half < 2; half++) {
                int nt = 2 * kf + half;
                ah[2 * half]     = pack_h2(s[nt][0], s[nt][1]);
                ah[2 * half + 1] = pack_h2(s[nt][2], s[nt][3]);
            }
#pragma unroll
            for (int np = 0; np < 8; np++) {
                uint32_t vbh[4], vbl[4];
                uint32_t addr = sk + 1 * KV_TILE +
                    ((kf * 16 + (lane & 15)) * ATP + np * 16 + ((lane >> 4) << 3)) * 2;
                ldm_x4_t(vbh, addr);
                ldm_x4_t(vbl, addr + KV_TILE);
                mma_f16(o[2 * np],     ah, &vbh[0]);
                mma_f16(o[2 * np],     ah, &vbl[0]);
                mma_f16(o[2 * np + 1], ah, &vbh[2]);
                mma_f16(o[2 * np + 1], ah, &vbl[2]);
            }
        }
    }

    // ---- epilogue: ctx as fp16 hi/lo (feeds fp16 2-term O projection) ----
    float inv0 = 1.f / l0, inv1 = 1.f / l1;
    int r_lo = r0 + warp * 16 + (lane >> 2);
    int r_hi = r_lo + 8;
#pragma unroll
    for (int nt = 0; nt < 16; nt++) {
        int col = h * HD + nt * 8 + ((lane & 3) << 1);
        {
            float x0 = o[nt][0] * inv0, x1 = o[nt][1] * inv0;
            __half2 ph = __floats2half2_rn(x0, x1);
            __half2 pl = __floats2half2_rn(x0 - __half2float(__low2half(ph)),
                                           x1 - __half2float(__high2half(ph)));
            *(__half2*)(ctxh + (size_t)r_lo * NQD + col) = ph;
            *(__half2*)(ctxl + (size_t)r_lo * NQD + col) = pl;
        }
        {
            float x0 = o[nt][2] * inv1, x1 = o[nt][3] * inv1;
            __half2 ph = __floats2half2_rn(x0, x1);
            __half2 pl = __floats2half2_rn(x0 - __half2float(__low2half(ph)),
                                           x1 - __half2float(__high2half(ph)));
            *(__half2*)(ctxh + (size_t)r_hi * NQD + col) = ph;
            *(__half2*)(ctxl + (size_t)r_hi * NQD + col) = pl;
        }
    }
}

// ---------------- launch ----------------
extern "C" void kernel_launch(void* const* d_in, const int* in_sizes, int n_in,
                              void* d_out, int out_size) {
    const float* hs   = (const float*)d_in[0];
    const float* cosp = (const float*)d_in[1];
    const float* sinp = (const float*)d_in[2];
    const float* Wq   = (const float*)d_in[3];
    const float* bq   = (const float*)d_in[4];
    const float* Wk   = (const float*)d_in[5];
    const float* bk   = (const float*)d_in[6];
    const float* Wv   = (const float*)d_in[7];
    const float* bv   = (const float*)d_in[8];
    const float* Wo   = (const float*)d_in[9];
    float* out = (float*)d_out;

    float *qkv_p, *bias_p;
    cudaGetSymbolAddress((void**)&qkv_p,  g_qkv);
    cudaGetSymbolAddress((void**)&bias_p, g_bias);

    __half *hsh, *hsl, *w16, *wo16;
    __half *ctxh, *ctxl, *q16h, *q16l, *k16, *v16h, *v16l;
    cudaGetSymbolAddress((void**)&hsh,  g_hsh);  cudaGetSymbolAddress((void**)&hsl,  g_hsl);
    cudaGetSymbolAddress((void**)&ctxh, g_ctxh); cudaGetSymbolAddress((void**)&ctxl, g_ctxl);
    cudaGetSymbolAddress((void**)&w16,  g_w16);  cudaGetSymbolAddress((void**)&wo16, g_wo16);
    cudaGetSymbolAddress((void**)&q16h, g_q16h); cudaGetSymbolAddress((void**)&q16l, g_q16l);
    cudaGetSymbolAddress((void**)&k16,  g_k16);
    cudaGetSymbolAddress((void**)&v16h, g_v16h); cudaGetSymbolAddress((void**)&v16l, g_v16l);

    cudaFuncSetAttribute(gemm_f16_2t, cudaFuncAttributeMaxDynamicSharedMemorySize, GEMM2_SMEM);
    cudaFuncSetAttribute(attn_mma,    cudaFuncAttributeMaxDynamicSharedMemorySize, ATTN_SMEM);

    // 1) input split + weight transposes (all fp16) + bias concat
    {
        int n4 = S_LEN * HID / 4;
        split_h_kernel<<<(n4 + 255) / 256, 256>>>((const float4*)hs, (__half2*)hsh, (__half2*)hsl, n4);
    }
    {
        dim3 blk(32, 8);
        tsplit2h_kernel<<<dim3(NQD / 32, HID / 64), blk>>>(Wq, w16, HID, NQD);
        tsplit2h_kernel<<<dim3(NKD / 32, HID / 64), blk>>>(Wk, w16 + (size_t)NQD * HID, HID, NKD);
        tsplit2h_kernel<<<dim3(NKD / 32, HID / 64), blk>>>(Wv, w16 + (size_t)(NQD + NKD) * HID, HID, NKD);
        tsplit2h_kernel<<<dim3(HID / 32, NQD / 64), blk>>>(Wo, wo16, NQD, HID);
        concat_bias_kernel<<<(NQKV + 255) / 256, 256>>>(bq, bk, bv, bias_p);
    }

    // 2) fused QKV projection (fp16 2-term)
    gemm_f16_2t<<<dim3(NQKV / 128, S_LEN / 128), 256, GEMM2_SMEM>>>(hsh, hsl, w16, bias_p, qkv_p, HID, NQKV);

    // 3) fused mROPE + fp16 split (scale folded into q; k single fp16)
    rope_split_kernel<<<S_LEN, 256>>>(qkv_p, cosp, sinp, q16h, q16l, k16, v16h, v16l);

    // 4) attention -> ctx (fp16 hi/lo)
    {
        dim3 grid(S_LEN / 128, NH);
        attn_mma<<<grid, 256, ATTN_SMEM>>>(q16h, q16l, k16, v16h, v16l, ctxh, ctxl);
    }

    // 5) output projection (fp16 2-term)
    gemm_f16_2t<<<dim3(HID / 128, S_LEN / 128), 256, GEMM2_SMEM>>>(ctxh, ctxl, wo16, nullptr, out, NQD, HID);
}

// round 12
// speedup vs baseline: 7.5944x; 1.5246x over previous
#include <cuda_runtime.h>
#include <cuda_fp16.h>
#include <math.h>
#include <stdint.h>

// ---------------- problem constants ----------------
#define S_LEN 2048
#define HID   3584
#define NH    28
#define NKV   4
#define HD    128
#define NQD   (NH*HD)    // 3584
#define NKD   (NKV*HD)   // 512
#define GRP   (NH/NKV)   // 7
#define NQKV  (NQD + 2*NKD)  // 4608

// ---------------- scratch (device globals; no allocs allowed) ----------------
__device__ float g_qkv[(size_t)S_LEN * NQKV];
__device__ float g_bias[NQKV];

__device__ __align__(16) __half g_hs16[S_LEN * HID];
__device__ __align__(16) __half g_ctx16[S_LEN * NQD];
__device__ __align__(16) __half g_q16h[S_LEN * NQD], g_q16l[S_LEN * NQD];
__device__ __align__(16) __half g_k16[S_LEN * NKD];
__device__ __align__(16) __half g_v16[S_LEN * NKD];
__device__ __align__(16) __half g_w16[(size_t)NQKV * HID];
__device__ __align__(16) __half g_wo16[(size_t)HID * NQD];

// ---------------- helpers ----------------
__device__ __forceinline__ uint32_t smem_u32(const void* p) {
    uint32_t a;
    asm("{ .reg .u64 t; cvta.to.shared.u64 t, %1; cvt.u32.u64 %0, t; }" : "=r"(a) : "l"(p));
    return a;
}

__device__ __forceinline__ void cp_async16(uint32_t dst, const void* src) {
    asm volatile("cp.async.cg.shared.global [%0], [%1], 16;" :: "r"(dst), "l"(src) : "memory");
}

__device__ __forceinline__ void ldm_x4(uint32_t* r, uint32_t addr) {
    asm volatile("ldmatrix.sync.aligned.m8n8.x4.shared.b16 {%0,%1,%2,%3}, [%4];"
                 : "=r"(r[0]), "=r"(r[1]), "=r"(r[2]), "=r"(r[3]) : "r"(addr));
}

__device__ __forceinline__ void ldm_x4_t(uint32_t* r, uint32_t addr) {
    asm volatile("ldmatrix.sync.aligned.m8n8.x4.trans.shared.b16 {%0,%1,%2,%3}, [%4];"
                 : "=r"(r[0]), "=r"(r[1]), "=r"(r[2]), "=r"(r[3]) : "r"(addr));
}

__device__ __forceinline__ void mma_f16(float* c, const uint32_t* a, const uint32_t* b) {
    asm volatile(
        "mma.sync.aligned.m16n8k16.row.col.f32.f16.f16.f32 "
        "{%0,%1,%2,%3}, {%4,%5,%6,%7}, {%8,%9}, {%0,%1,%2,%3};"
        : "+f"(c[0]), "+f"(c[1]), "+f"(c[2]), "+f"(c[3])
        : "r"(a[0]), "r"(a[1]), "r"(a[2]), "r"(a[3]), "r"(b[0]), "r"(b[1]));
}

__device__ __forceinline__ uint32_t pack_h2(float a, float b) {
    __half2 h = __floats2half2_rn(a, b);
    return *(uint32_t*)&h;
}

// ---------------- convert kernels ----------------
// fp32 -> fp16 single
__global__ void conv_h_kernel(const float4* __restrict__ X, __half2* __restrict__ H, int n4) {
    int i = blockIdx.x * 256 + threadIdx.x;
    if (i >= n4) return;
    float4 x = X[i];
    H[2*i]   = __floats2half2_rn(x.x, x.y);
    H[2*i+1] = __floats2half2_rn(x.z, x.w);
}

// W [K,N] fp32 row-major -> T [N,K] fp16 (single). Tile 32n x 64k, block (32,8).
__global__ void tsplit2h_kernel(const float* __restrict__ W, __half* __restrict__ T,
                                int K, int N) {
    __shared__ float t[64][33];
    int n0 = blockIdx.x * 32, k0 = blockIdx.y * 64;
    int tx = threadIdx.x, ty = threadIdx.y;
#pragma unroll
    for (int i = 0; i < 8; i++) {
        int k = i * 8 + ty;
        t[k][tx] = W[(size_t)(k0 + k) * N + n0 + tx];
    }
    __syncthreads();
#pragma unroll
    for (int i = 0; i < 4; i++) {
        int n = i * 8 + ty;
        __half2 hp = __floats2half2_rn(t[2 * tx][n], t[2 * tx + 1][n]);
        *(__half2*)(T + (size_t)(n0 + n) * K + k0 + 2 * tx) = hp;
    }
}

__global__ void concat_bias_kernel(const float* __restrict__ bq, const float* __restrict__ bk,
                                   const float* __restrict__ bv, float* __restrict__ b) {
    int i = blockIdx.x * 256 + threadIdx.x;
    if (i < NQD) b[i] = bq[i];
    else if (i < NQD + NKD) b[i] = bk[i - NQD];
    else if (i < NQKV) b[i] = bv[i - NQD - NKD];
}

// ---------------- mma.sync GEMM (fp16 1-term: A x B) ----------------
// CTA tile 128x128, BK=32, 8 warps (2m x 4n), 3-stage cp.async pipeline, 1 sync/iter.
#define GBK 32
#define ROWP 40
#define STG_TILE (128*ROWP*2)          // 10240 B per operand tile
#define STG1_BYTES (2*STG_TILE)        // 20480 B per stage (A, B)
#define GEMM1_SMEM (3*STG1_BYTES)      // 61440 B (3 stages)

__global__ __launch_bounds__(256, 2)
void gemm_f16_1t(const __half* __restrict__ A, const __half* __restrict__ B,
                 const float* __restrict__ bias,
                 float* __restrict__ C, int K, int Ntot) {
    extern __shared__ char smem[];
    const uint32_t sb = smem_u32(smem);
    const int tid = threadIdx.x;
    const int lane = tid & 31;
    const int warp = tid >> 5;
    const int wm = (warp >> 2) * 64;
    const int wn = (warp & 3) * 32;
    const int row0 = blockIdx.y * 128;
    const int col0 = blockIdx.x * 128;
    const int NI = K / GBK;

    float acc[4][4][4];
#pragma unroll
    for (int mt = 0; mt < 4; mt++)
#pragma unroll
        for (int nt = 0; nt < 4; nt++)
#pragma unroll
            for (int i = 0; i < 4; i++) acc[mt][nt][i] = 0.f;

    auto issue_load = [&](int stage, int kb) {
        uint32_t sbase = sb + stage * STG1_BYTES;
#pragma unroll
        for (int tile = 0; tile < 2; tile++) {
            const __half* src = (tile == 0) ? A : B;
            int gbase = (tile == 0) ? row0 : col0;
#pragma unroll
            for (int j = 0; j < 2; j++) {
                int s = j * 256 + tid;
                int row = s >> 2;
                int c = (s & 3) << 3;
                const void* g = src + (size_t)(gbase + row) * K + kb + c;
                uint32_t dst = sbase + tile * STG_TILE + (row * ROWP + c) * 2;
                cp_async16(dst, g);
            }
        }
        asm volatile("cp.async.commit_group;" ::: "memory");
    };

    issue_load(0, 0);
    issue_load(1, GBK);

    int stage = 0;
    for (int i = 0; i < NI; i++) {
        if (i + 1 < NI) {
            asm volatile("cp.async.wait_group 1;" ::: "memory");
        } else {
            asm volatile("cp.async.wait_group 0;" ::: "memory");
        }
        __syncthreads();   // stage i visible; compute(i-1) finished block-wide
        if (i + 2 < NI) {
            int nstage = stage + 2; if (nstage >= 3) nstage -= 3;
            issue_load(nstage, (i + 2) * GBK);
        }

        const uint32_t sa = sb + stage * STG1_BYTES;
#pragma unroll
        for (int ks = 0; ks < 2; ks++) {
            uint32_t bh[4][2];
#pragma unroll
            for (int np = 0; np < 2; np++) {
                uint32_t addr = sa + STG_TILE +
                    ((wn + np * 16 + ((lane >> 4) << 3) + (lane & 7)) * ROWP
                     + ks * 16 + (((lane >> 3) & 1) << 3)) * 2;
                ldm_x4(&bh[np * 2][0], addr);
            }
#pragma unroll
            for (int mt = 0; mt < 4; mt++) {
                uint32_t ah[4];
                uint32_t addr = sa +
                    ((wm + mt * 16 + (lane & 15)) * ROWP + ks * 16 + ((lane >> 4) << 3)) * 2;
                ldm_x4(ah, addr);
#pragma unroll
                for (int nt = 0; nt < 4; nt++) {
                    mma_f16(acc[mt][nt], ah, bh[nt]);
                }
            }
        }
        if (++stage == 3) stage = 0;
    }

#pragma unroll
    for (int mt = 0; mt < 4; mt++) {
#pragma unroll
        for (int nt = 0; nt < 4; nt++) {
            int r = row0 + wm + mt * 16 + (lane >> 2);
            int cidx = col0 + wn + nt * 8 + ((lane & 3) << 1);
            float b0 = 0.f, b1 = 0.f;
            if (bias) { b0 = bias[cidx]; b1 = bias[cidx + 1]; }
            float2* p0 = (float2*)(C + (size_t)r * Ntot + cidx);
            float2* p1 = (float2*)(C + (size_t)(r + 8) * Ntot + cidx);
            *p0 = make_float2(acc[mt][nt][0] + b0, acc[mt][nt][1] + b1);
            *p1 = make_float2(acc[mt][nt][2] + b0, acc[mt][nt][3] + b1);
        }
    }
}

// ---------------- fused mROPE + fp16 split ----------------
// q -> fp16 hi/lo (scaled), k -> fp16 single, v -> fp16 single
__global__ __launch_bounds__(256)
void rope_split_kernel(const float* __restrict__ qkv,
                       const float* __restrict__ cosp, const float* __restrict__ sinp,
                       __half* __restrict__ qh, __half* __restrict__ ql,
                       __half* __restrict__ k16, __half* __restrict__ v16) {
    const int s = blockIdx.x;
    const int lane = threadIdx.x & 31;
    const int grp = threadIdx.x >> 5;     // 0..7
    const int da = 2 * lane;              // even, 0..62
    const int sec = (da < 16) ? 0 : ((da < 40) ? 1 : 2);
    const int SH = S_LEN * HD;
    const float scale = 0.08838834764831845f;   // 1/sqrt(128)

    const float2 c1 = *(const float2*)(cosp + sec * SH + s * HD + da);
    const float2 s1 = *(const float2*)(sinp + sec * SH + s * HD + da);
    const float2 c2 = *(const float2*)(cosp + sec * SH + s * HD + da + 64);
    const float2 s2 = *(const float2*)(sinp + sec * SH + s * HD + da + 64);

    const float* row = qkv + (size_t)s * NQKV;

    auto store2h = [](__half* H, __half* L, size_t o, float a, float b) {
        __half ha = __float2half_rn(a), hb = __float2half_rn(b);
        *(__half2*)(H + o) = __halves2half2(ha, hb);
        *(__half2*)(L + o) = __floats2half2_rn(a - __half2float(ha), b - __half2float(hb));
    };

#pragma unroll 1
    for (int it = 0; it < 5; it++) {
        int hh = it * 8 + grp;    // 0..39, valid < 36
        if (hh >= NH + 2 * NKV) break;
        if (hh < NH) {
            const float* base = row + hh * HD;
            float2 x1 = *(const float2*)(base + da);
            float2 x2 = *(const float2*)(base + da + 64);
            size_t o = (size_t)s * NQD + hh * HD;
            store2h(qh, ql, o + da,      (x1.x * c1.x - x2.x * s1.x) * scale,
                                         (x1.y * c1.y - x2.y * s1.y) * scale);
            store2h(qh, ql, o + da + 64, (x2.x * c2.x + x1.x * s2.x) * scale,
                                         (x2.y * c2.y + x1.y * s2.y) * scale);
        } else if (hh < NH + NKV) {
            int kvi = hh - NH;
            const float* base = row + NQD + kvi * HD;
            float2 x1 = *(const float2*)(base + da);
            float2 x2 = *(const float2*)(base + da + 64);
            size_t o = (size_t)s * NKD + kvi * HD;
            *(__half2*)(k16 + o + da)      = __floats2half2_rn(x1.x * c1.x - x2.x * s1.x,
                                                               x1.y * c1.y - x2.y * s1.y);
            *(__half2*)(k16 + o + da + 64) = __floats2half2_rn(x2.x * c2.x + x1.x * s2.x,
                                                               x2.y * c2.y + x1.y * s2.y);
        } else {
            int kvi = hh - NH - NKV;
            const float* base = row + NQD + NKD + kvi * HD;
            float2 x1 = *(const float2*)(base + da);
            float2 x2 = *(const float2*)(base + da + 64);
            size_t o = (size_t)s * NKD + kvi * HD;
            *(__half2*)(v16 + o + da)      = __floats2half2_rn(x1.x, x1.y);
            *(__half2*)(v16 + o + da + 64) = __floats2half2_rn(x2.x, x2.y);
        }
    }
}

// ---------------- attention: fp16 mma flash, QK 2-term / PV 1-term ----------------
#define ATP 136
#define AT_ROWB (ATP*2)              // 272 B/row
#define AQ_TILE (128*AT_ROWB)        // 34816
#define KV_TILE (32*AT_ROWB)         // 8704
#define KV_STG  (2*KV_TILE)          // 17408 (K, V)
#define AQ_H 0
#define AQ_L AQ_TILE
#define AKV  (2*AQ_TILE)
#define ATTN_SMEM (AKV + 2*KV_STG)   // 104448 B

__global__ __launch_bounds__(256)
void attn_mma(const __half* __restrict__ qh, const __half* __restrict__ ql,
              const __half* __restrict__ k16, const __half* __restrict__ v16,
              __half* __restrict__ ctx16) {
    extern __shared__ char smem[];
    const uint32_t sb = smem_u32(smem);
    const int tid = threadIdx.x;
    const int lane = tid & 31;
    const int warp = tid >> 5;           // 0..7
    const int h = blockIdx.y;
    const int kvh = h / GRP;
    const int r0 = blockIdx.x * 128;

    // ---- Q tile (128 x 128) hi/lo ----
#pragma unroll
    for (int j = 0; j < 8; j++) {
        int idx = j * 256 + tid;          // 0..2047
        int row = idx >> 4, c = idx & 15;
        size_t g = (size_t)(r0 + row) * NQD + h * HD + c * 8;
        uint32_t so = row * AT_ROWB + c * 16;
        cp_async16(sb + AQ_H + so, qh + g);
        cp_async16(sb + AQ_L + so, ql + g);
    }
    asm volatile("cp.async.commit_group;" ::: "memory");

    auto issue_kv = [&](int stage, int kt) {
        uint32_t base = sb + AKV + stage * KV_STG;
#pragma unroll
        for (int j = 0; j < 2; j++) {
            int idx = j * 256 + tid;      // 0..511
            int row = idx >> 4, c = idx & 15;
            size_t g = (size_t)(kt + row) * NKD + kvh * HD + c * 8;
            uint32_t so = row * AT_ROWB + c * 16;
            cp_async16(base + 0 * KV_TILE + so, k16 + g);
            cp_async16(base + 1 * KV_TILE + so, v16 + g);
        }
        asm volatile("cp.async.commit_group;" ::: "memory");
    };

    issue_kv(0, 0);
    asm volatile("cp.async.wait_group 1;" ::: "memory");   // Q done (kv0 may pend)
    __syncthreads();

    // ---- Q fragments (warp owns rows [warp*16, warp*16+16)) ----
    uint32_t qfh[8][4], qfl[8][4];
#pragma unroll
    for (int kf = 0; kf < 8; kf++) {
        uint32_t off = ((warp * 16 + (lane & 15)) * ATP + kf * 16 + ((lane >> 4) << 3)) * 2;
        ldm_x4(qfh[kf], sb + AQ_H + off);
        ldm_x4(qfl[kf], sb + AQ_L + off);
    }

    float o[16][4];
#pragma unroll
    for (int nt = 0; nt < 16; nt++)
#pragma unroll
        for (int i = 0; i < 4; i++) o[nt][i] = 0.f;
    float m0 = -INFINITY, m1 = -INFINITY, l0 = 0.f, l1 = 0.f;

    const int NI = S_LEN / 32;            // 64

    for (int it = 0; it < NI; it++) {
        asm volatile("cp.async.wait_group 0;" ::: "memory");  // kv stage `it` landed
        __syncthreads();   // stage visible; compute(it-1) done block-wide
        if (it + 1 < NI) issue_kv((it + 1) & 1, (it + 1) * 32);

        const uint32_t sk = sb + AKV + (it & 1) * KV_STG;

        // ---- S = Q K^T (2-term: Qh*K + Ql*K) ----
        float s[4][4];
#pragma unroll
        for (int nt = 0; nt < 4; nt++)
#pragma unroll
            for (int i = 0; i < 4; i++) s[nt][i] = 0.f;

#pragma unroll
        for (int kf = 0; kf < 8; kf++) {
            uint32_t kb[4][2];
#pragma unroll
            for (int np = 0; np < 2; np++) {
                uint32_t addr = sk +
                    ((np * 16 + ((lane >> 4) << 3) + (lane & 7)) * ATP
                     + kf * 16 + (((lane >> 3) & 1) << 3)) * 2;
                ldm_x4(&kb[np * 2][0], addr);
            }
#pragma unroll
            for (int nt = 0; nt < 4; nt++) {
                mma_f16(s[nt], qfh[kf], kb[nt]);
                mma_f16(s[nt], qfl[kf], kb[nt]);
            }
        }

        // ---- online softmax ----
        float mx0 = -INFINITY, mx1 = -INFINITY;
#pragma unroll
        for (int nt = 0; nt < 4; nt++) {
            mx0 = fmaxf(mx0, fmaxf(s[nt][0], s[nt][1]));
            mx1 = fmaxf(mx1, fmaxf(s[nt][2], s[nt][3]));
        }
        mx0 = fmaxf(mx0, __shfl_xor_sync(0xffffffffu, mx0, 1));
        mx0 = fmaxf(mx0, __shfl_xor_sync(0xffffffffu, mx0, 2));
        mx1 = fmaxf(mx1, __shfl_xor_sync(0xffffffffu, mx1, 1));
        mx1 = fmaxf(mx1, __shfl_xor_sync(0xffffffffu, mx1, 2));

        float nm0 = fmaxf(m0, mx0), nm1 = fmaxf(m1, mx1);
        float c0 = __expf(m0 - nm0), c1 = __expf(m1 - nm1);
        m0 = nm0; m1 = nm1;

        float sum0 = 0.f, sum1 = 0.f;
#pragma unroll
        for (int nt = 0; nt < 4; nt++) {
            s[nt][0] = __expf(s[nt][0] - nm0);
            s[nt][1] = __expf(s[nt][1] - nm0);
            s[nt][2] = __expf(s[nt][2] - nm1);
            s[nt][3] = __expf(s[nt][3] - nm1);
            sum0 += s[nt][0] + s[nt][1];
            sum1 += s[nt][2] + s[nt][3];
        }
        sum0 += __shfl_xor_sync(0xffffffffu, sum0, 1);
        sum0 += __shfl_xor_sync(0xffffffffu, sum0, 2);
        sum1 += __shfl_xor_sync(0xffffffffu, sum1, 1);
        sum1 += __shfl_xor_sync(0xffffffffu, sum1, 2);
        l0 = l0 * c0 + sum0;
        l1 = l1 * c1 + sum1;

#pragma unroll
        for (int nt = 0; nt < 16; nt++) {
            o[nt][0] *= c0; o[nt][1] *= c0;
            o[nt][2] *= c1; o[nt][3] *= c1;
        }

        // ---- O += P V (1-term: P single fp16 x V single fp16) ----
#pragma unroll
        for (int kf = 0; kf < 2; kf++) {
            uint32_t ah[4];
#pragma unroll
            for (int half = 0; half < 2; half++) {
                int nt = 2 * kf + half;
                ah[2 * half]     = pack_h2(s[nt][0], s[nt][1]);
                ah[2 * half + 1] = pack_h2(s[nt][2], s[nt][3]);
            }
#pragma unroll
            for (int np = 0; np < 8; np++) {
                uint32_t vb[4];
                uint32_t addr = sk + KV_TILE +
                    ((kf * 16 + (lane & 15)) * ATP + np * 16 + ((lane >> 4) << 3)) * 2;
                ldm_x4_t(vb, addr);
                mma_f16(o[2 * np],     ah, &vb[0]);
                mma_f16(o[2 * np + 1], ah, &vb[2]);
            }
        }
    }

    // ---- epilogue: ctx as single fp16 (feeds fp16 1-term O projection) ----
    float inv0 = 1.f / l0, inv1 = 1.f / l1;
    int r_lo = r0 + warp * 16 + (lane >> 2);
    int r_hi = r_lo + 8;
#pragma unroll
    for (int nt = 0; nt < 16; nt++) {
        int col = h * HD + nt * 8 + ((lane & 3) << 1);
        *(__half2*)(ctx16 + (size_t)r_lo * NQD + col) =
            __floats2half2_rn(o[nt][0] * inv0, o[nt][1] * inv0);
        *(__half2*)(ctx16 + (size_t)r_hi * NQD + col) =
            __floats2half2_rn(o[nt][2] * inv1, o[nt][3] * inv1);
    }
}

// ---------------- launch ----------------
extern "C" void kernel_launch(void* const* d_in, const int* in_sizes, int n_in,
                              void* d_out, int out_size) {
    const float* hs   = (const float*)d_in[0];
    const float* cosp = (const float*)d_in[1];
    const float* sinp = (const float*)d_in[2];
    const float* Wq   = (const float*)d_in[3];
    const float* bq   = (const float*)d_in[4];
    const float* Wk   = (const float*)d_in[5];
    const float* bk   = (const float*)d_in[6];
    const float* Wv   = (const float*)d_in[7];
    const float* bv   = (const float*)d_in[8];
    const float* Wo   = (const float*)d_in[9];
    float* out = (float*)d_out;

    float *qkv_p, *bias_p;
    cudaGetSymbolAddress((void**)&qkv_p,  g_qkv);
    cudaGetSymbolAddress((void**)&bias_p, g_bias);

    __half *hs16, *w16, *wo16, *ctx16, *q16h, *q16l, *k16, *v16;
    cudaGetSymbolAddress((void**)&hs16,  g_hs16);
    cudaGetSymbolAddress((void**)&ctx16, g_ctx16);
    cudaGetSymbolAddress((void**)&w16,   g_w16);  cudaGetSymbolAddress((void**)&wo16, g_wo16);
    cudaGetSymbolAddress((void**)&q16h,  g_q16h); cudaGetSymbolAddress((void**)&q16l, g_q16l);
    cudaGetSymbolAddress((void**)&k16,   g_k16);  cudaGetSymbolAddress((void**)&v16,  g_v16);

    cudaFuncSetAttribute(gemm_f16_1t, cudaFuncAttributeMaxDynamicSharedMemorySize, GEMM1_SMEM);
    cudaFuncSetAttribute(attn_mma,    cudaFuncAttributeMaxDynamicSharedMemorySize, ATTN_SMEM);

    // 1) input convert + weight transposes (all fp16) + bias concat
    {
        int n4 = S_LEN * HID / 4;
        conv_h_kernel<<<(n4 + 255) / 256, 256>>>((const float4*)hs, (__half2*)hs16, n4);
    }
    {
        dim3 blk(32, 8);
        tsplit2h_kernel<<<dim3(NQD / 32, HID / 64), blk>>>(Wq, w16, HID, NQD);
        tsplit2h_kernel<<<dim3(NKD / 32, HID / 64), blk>>>(Wk, w16 + (size_t)NQD * HID, HID, NKD);
        tsplit2h_kernel<<<dim3(NKD / 32, HID / 64), blk>>>(Wv, w16 + (size_t)(NQD + NKD) * HID, HID, NKD);
        tsplit2h_kernel<<<dim3(HID / 32, NQD / 64), blk>>>(Wo, wo16, NQD, HID);
        concat_bias_kernel<<<(NQKV + 255) / 256, 256>>>(bq, bk, bv, bias_p);
    }

    // 2) fused QKV projection (fp16 1-term)
    gemm_f16_1t<<<dim3(NQKV / 128, S_LEN / 128), 256, GEMM1_SMEM>>>(hs16, w16, bias_p, qkv_p, HID, NQKV);

    // 3) fused mROPE + fp16 split (q hi/lo scaled; k,v single)
    rope_split_kernel<<<S_LEN, 256>>>(qkv_p, cosp, sinp, q16h, q16l, k16, v16);

    // 4) attention -> ctx (single fp16)
    {
        dim3 grid(S_LEN / 128, NH);
        attn_mma<<<grid, 256, ATTN_SMEM>>>(q16h, q16l, k16, v16, ctx16);
    }

    // 5) output projection (fp16 1-term)
    gemm_f16_1t<<<dim3(HID / 128, S_LEN / 128), 256, GEMM1_SMEM>>>(ctx16, wo16, nullptr, out, NQD, HID);
}

// round 13
// speedup vs baseline: 8.0127x; 1.0551x over previous
#include <cuda_runtime.h>
#include <cuda_fp16.h>
#include <math.h>
#include <stdint.h>

// ---------------- problem constants ----------------
#define S_LEN 2048
#define HID   3584
#define NH    28
#define NKV   4
#define HD    128
#define NQD   (NH*HD)    // 3584
#define NKD   (NKV*HD)   // 512
#define GRP   (NH/NKV)   // 7
#define NQKV  (NQD + 2*NKD)  // 4608

// ---------------- scratch (device globals; no allocs allowed) ----------------
__device__ float g_qkv[(size_t)S_LEN * NQKV];
__device__ float g_bias[NQKV];

__device__ __align__(16) __half g_hs16[S_LEN * HID];
__device__ __align__(16) __half g_ctx16[S_LEN * NQD];
__device__ __align__(16) __half g_q16h[S_LEN * NQD], g_q16l[S_LEN * NQD];
__device__ __align__(16) __half g_k16[S_LEN * NKD];
__device__ __align__(16) __half g_v16[S_LEN * NKD];
__device__ __align__(16) __half g_w16[(size_t)NQKV * HID];
__device__ __align__(16) __half g_wo16[(size_t)HID * NQD];

// ---------------- helpers ----------------
__device__ __forceinline__ uint32_t smem_u32(const void* p) {
    uint32_t a;
    asm("{ .reg .u64 t; cvta.to.shared.u64 t, %1; cvt.u32.u64 %0, t; }" : "=r"(a) : "l"(p));
    return a;
}

__device__ __forceinline__ void cp_async16(uint32_t dst, const void* src) {
    asm volatile("cp.async.cg.shared.global [%0], [%1], 16;" :: "r"(dst), "l"(src) : "memory");
}

__device__ __forceinline__ void ldm_x4(uint32_t* r, uint32_t addr) {
    asm volatile("ldmatrix.sync.aligned.m8n8.x4.shared.b16 {%0,%1,%2,%3}, [%4];"
                 : "=r"(r[0]), "=r"(r[1]), "=r"(r[2]), "=r"(r[3]) : "r"(addr));
}

__device__ __forceinline__ void ldm_x4_t(uint32_t* r, uint32_t addr) {
    asm volatile("ldmatrix.sync.aligned.m8n8.x4.trans.shared.b16 {%0,%1,%2,%3}, [%4];"
                 : "=r"(r[0]), "=r"(r[1]), "=r"(r[2]), "=r"(r[3]) : "r"(addr));
}

__device__ __forceinline__ void mma_f16(float* c, const uint32_t* a, const uint32_t* b) {
    asm volatile(
        "mma.sync.aligned.m16n8k16.row.col.f32.f16.f16.f32 "
        "{%0,%1,%2,%3}, {%4,%5,%6,%7}, {%8,%9}, {%0,%1,%2,%3};"
        : "+f"(c[0]), "+f"(c[1]), "+f"(c[2]), "+f"(c[3])
        : "r"(a[0]), "r"(a[1]), "r"(a[2]), "r"(a[3]), "r"(b[0]), "r"(b[1]));
}

__device__ __forceinline__ uint32_t pack_h2(float a, float b) {
    __half2 h = __floats2half2_rn(a, b);
    return *(uint32_t*)&h;
}

__device__ __forceinline__ float fexp2(float x) {
    float r;
    asm("ex2.approx.f32 %0, %1;" : "=f"(r) : "f"(x));
    return r;
}

// ---------------- convert kernels ----------------
__global__ void conv_h_kernel(const float4* __restrict__ X, __half2* __restrict__ H, int n4) {
    int i = blockIdx.x * 256 + threadIdx.x;
    if (i >= n4) return;
    float4 x = X[i];
    H[2*i]   = __floats2half2_rn(x.x, x.y);
    H[2*i+1] = __floats2half2_rn(x.z, x.w);
}

// W [K,N] fp32 row-major -> T [N,K] fp16 (single). Tile 32n x 64k, block (32,8).
__global__ void tsplit2h_kernel(const float* __restrict__ W, __half* __restrict__ T,
                                int K, int N) {
    __shared__ float t[64][33];
    int n0 = blockIdx.x * 32, k0 = blockIdx.y * 64;
    int tx = threadIdx.x, ty = threadIdx.y;
#pragma unroll
    for (int i = 0; i < 8; i++) {
        int k = i * 8 + ty;
        t[k][tx] = W[(size_t)(k0 + k) * N + n0 + tx];
    }
    __syncthreads();
#pragma unroll
    for (int i = 0; i < 4; i++) {
        int n = i * 8 + ty;
        __half2 hp = __floats2half2_rn(t[2 * tx][n], t[2 * tx + 1][n]);
        *(__half2*)(T + (size_t)(n0 + n) * K + k0 + 2 * tx) = hp;
    }
}

__global__ void concat_bias_kernel(const float* __restrict__ bq, const float* __restrict__ bk,
                                   const float* __restrict__ bv, float* __restrict__ b) {
    int i = blockIdx.x * 256 + threadIdx.x;
    if (i < NQD) b[i] = bq[i];
    else if (i < NQD + NKD) b[i] = bk[i - NQD];
    else if (i < NQKV) b[i] = bv[i - NQD - NKD];
}

// ---------------- mma.sync GEMM (fp16 1-term: A x B) ----------------
#define GBK 32
#define ROWP 40
#define STG_TILE (128*ROWP*2)          // 10240 B per operand tile
#define STG1_BYTES (2*STG_TILE)        // 20480 B per stage (A, B)
#define GEMM1_SMEM (3*STG1_BYTES)      // 61440 B (3 stages)

__global__ __launch_bounds__(256, 2)
void gemm_f16_1t(const __half* __restrict__ A, const __half* __restrict__ B,
                 const float* __restrict__ bias,
                 float* __restrict__ C, int K, int Ntot) {
    extern __shared__ char smem[];
    const uint32_t sb = smem_u32(smem);
    const int tid = threadIdx.x;
    const int lane = tid & 31;
    const int warp = tid >> 5;
    const int wm = (warp >> 2) * 64;
    const int wn = (warp & 3) * 32;
    const int row0 = blockIdx.y * 128;
    const int col0 = blockIdx.x * 128;
    const int NI = K / GBK;

    float acc[4][4][4];
#pragma unroll
    for (int mt = 0; mt < 4; mt++)
#pragma unroll
        for (int nt = 0; nt < 4; nt++)
#pragma unroll
            for (int i = 0; i < 4; i++) acc[mt][nt][i] = 0.f;

    auto issue_load = [&](int stage, int kb) {
        uint32_t sbase = sb + stage * STG1_BYTES;
#pragma unroll
        for (int tile = 0; tile < 2; tile++) {
            const __half* src = (tile == 0) ? A : B;
            int gbase = (tile == 0) ? row0 : col0;
#pragma unroll
            for (int j = 0; j < 2; j++) {
                int s = j * 256 + tid;
                int row = s >> 2;
                int c = (s & 3) << 3;
                const void* g = src + (size_t)(gbase + row) * K + kb + c;
                uint32_t dst = sbase + tile * STG_TILE + (row * ROWP + c) * 2;
                cp_async16(dst, g);
            }
        }
        asm volatile("cp.async.commit_group;" ::: "memory");
    };

    issue_load(0, 0);
    issue_load(1, GBK);

    int stage = 0;
    for (int i = 0; i < NI; i++) {
        if (i + 1 < NI) {
            asm volatile("cp.async.wait_group 1;" ::: "memory");
        } else {
            asm volatile("cp.async.wait_group 0;" ::: "memory");
        }
        __syncthreads();
        if (i + 2 < NI) {
            int nstage = stage + 2; if (nstage >= 3) nstage -= 3;
            issue_load(nstage, (i + 2) * GBK);
        }

        const uint32_t sa = sb + stage * STG1_BYTES;
#pragma unroll
        for (int ks = 0; ks < 2; ks++) {
            uint32_t bh[4][2];
#pragma unroll
            for (int np = 0; np < 2; np++) {
                uint32_t addr = sa + STG_TILE +
                    ((wn + np * 16 + ((lane >> 4) << 3) + (lane & 7)) * ROWP
                     + ks * 16 + (((lane >> 3) & 1) << 3)) * 2;
                ldm_x4(&bh[np * 2][0], addr);
            }
#pragma unroll
            for (int mt = 0; mt < 4; mt++) {
                uint32_t ah[4];
                uint32_t addr = sa +
                    ((wm + mt * 16 + (lane & 15)) * ROWP + ks * 16 + ((lane >> 4) << 3)) * 2;
                ldm_x4(ah, addr);
#pragma unroll
                for (int nt = 0; nt < 4; nt++) {
                    mma_f16(acc[mt][nt], ah, bh[nt]);
                }
            }
        }
        if (++stage == 3) stage = 0;
    }

#pragma unroll
    for (int mt = 0; mt < 4; mt++) {
#pragma unroll
        for (int nt = 0; nt < 4; nt++) {
            int r = row0 + wm + mt * 16 + (lane >> 2);
            int cidx = col0 + wn + nt * 8 + ((lane & 3) << 1);
            float b0 = 0.f, b1 = 0.f;
            if (bias) { b0 = bias[cidx]; b1 = bias[cidx + 1]; }
            float2* p0 = (float2*)(C + (size_t)r * Ntot + cidx);
            float2* p1 = (float2*)(C + (size_t)(r + 8) * Ntot + cidx);
            *p0 = make_float2(acc[mt][nt][0] + b0, acc[mt][nt][1] + b1);
            *p1 = make_float2(acc[mt][nt][2] + b0, acc[mt][nt][3] + b1);
        }
    }
}

// ---------------- fused mROPE + fp16 split ----------------
// q -> fp16 hi/lo (scaled by 1/sqrt(HD) * log2(e)), k -> fp16 single, v -> fp16 single
__global__ __launch_bounds__(256)
void rope_split_kernel(const float* __restrict__ qkv,
                       const float* __restrict__ cosp, const float* __restrict__ sinp,
                       __half* __restrict__ qh, __half* __restrict__ ql,
                       __half* __restrict__ k16, __half* __restrict__ v16) {
    const int s = blockIdx.x;
    const int lane = threadIdx.x & 31;
    const int grp = threadIdx.x >> 5;     // 0..7
    const int da = 2 * lane;              // even, 0..62
    const int sec = (da < 16) ? 0 : ((da < 40) ? 1 : 2);
    const int SH = S_LEN * HD;
    // 1/sqrt(128) * log2(e): exp folded to exp2
    const float scale = 0.08838834764831845f * 1.4426950408889634f;

    const float2 c1 = *(const float2*)(cosp + sec * SH + s * HD + da);
    const float2 s1 = *(const float2*)(sinp + sec * SH + s * HD + da);
    const float2 c2 = *(const float2*)(cosp + sec * SH + s * HD + da + 64);
    const float2 s2 = *(const float2*)(sinp + sec * SH + s * HD + da + 64);

    const float* row = qkv + (size_t)s * NQKV;

    auto store2h = [](__half* H, __half* L, size_t o, float a, float b) {
        __half ha = __float2half_rn(a), hb = __float2half_rn(b);
        *(__half2*)(H + o) = __halves2half2(ha, hb);
        *(__half2*)(L + o) = __floats2half2_rn(a - __half2float(ha), b - __half2float(hb));
    };

#pragma unroll 1
    for (int it = 0; it < 5; it++) {
        int hh = it * 8 + grp;    // 0..39, valid < 36
        if (hh >= NH + 2 * NKV) break;
        if (hh < NH) {
            const float* base = row + hh * HD;
            float2 x1 = *(const float2*)(base + da);
            float2 x2 = *(const float2*)(base + da + 64);
            size_t o = (size_t)s * NQD + hh * HD;
            store2h(qh, ql, o + da,      (x1.x * c1.x - x2.x * s1.x) * scale,
                                         (x1.y * c1.y - x2.y * s1.y) * scale);
            store2h(qh, ql, o + da + 64, (x2.x * c2.x + x1.x * s2.x) * scale,
                                         (x2.y * c2.y + x1.y * s2.y) * scale);
        } else if (hh < NH + NKV) {
            int kvi = hh - NH;
            const float* base = row + NQD + kvi * HD;
            float2 x1 = *(const float2*)(base + da);
            float2 x2 = *(const float2*)(base + da + 64);
            size_t o = (size_t)s * NKD + kvi * HD;
            *(__half2*)(k16 + o + da)      = __floats2half2_rn(x1.x * c1.x - x2.x * s1.x,
                                                               x1.y * c1.y - x2.y * s1.y);
            *(__half2*)(k16 + o + da + 64) = __floats2half2_rn(x2.x * c2.x + x1.x * s2.x,
                                                               x2.y * c2.y + x1.y * s2.y);
        } else {
            int kvi = hh - NH - NKV;
            const float* base = row + NQD + NKD + kvi * HD;
            float2 x1 = *(const float2*)(base + da);
            float2 x2 = *(const float2*)(base + da + 64);
            size_t o = (size_t)s * NKD + kvi * HD;
            *(__half2*)(v16 + o + da)      = __floats2half2_rn(x1.x, x1.y);
            *(__half2*)(v16 + o + da + 64) = __floats2half2_rn(x2.x, x2.y);
        }
    }
}

// ---------------- attention: fp16 mma flash, BN=64, QK 2-term / PV 1-term ----------------
#define ATP 136
#define AT_ROWB (ATP*2)              // 272 B/row
#define AQ_TILE (128*AT_ROWB)        // 34816
#define KV_TILE (64*AT_ROWB)         // 17408 (64 keys x 128 dims)
#define KV_STG  (2*KV_TILE)          // 34816 (K, V)
#define AQ_H 0
#define AQ_L AQ_TILE
#define AKV  (2*AQ_TILE)
#define ATTN_SMEM (AKV + 2*KV_STG)   // 139264 B

__global__ __launch_bounds__(256)
void attn_mma(const __half* __restrict__ qh, const __half* __restrict__ ql,
              const __half* __restrict__ k16, const __half* __restrict__ v16,
              __half* __restrict__ ctx16) {
    extern __shared__ char smem[];
    const uint32_t sb = smem_u32(smem);
    const int tid = threadIdx.x;
    const int lane = tid & 31;
    const int warp = tid >> 5;           // 0..7
    const int h = blockIdx.y;
    const int kvh = h / GRP;
    const int r0 = blockIdx.x * 128;

    // ---- Q tile (128 x 128) hi/lo ----
#pragma unroll
    for (int j = 0; j < 8; j++) {
        int idx = j * 256 + tid;          // 0..2047
        int row = idx >> 4, c = idx & 15;
        size_t g = (size_t)(r0 + row) * NQD + h * HD + c * 8;
        uint32_t so = row * AT_ROWB + c * 16;
        cp_async16(sb + AQ_H + so, qh + g);
        cp_async16(sb + AQ_L + so, ql + g);
    }
    asm volatile("cp.async.commit_group;" ::: "memory");

    auto issue_kv = [&](int stage, int kt) {
        uint32_t base = sb + AKV + stage * KV_STG;
#pragma unroll
        for (int j = 0; j < 4; j++) {
            int idx = j * 256 + tid;      // 0..1023
            int row = idx >> 4, c = idx & 15;
            size_t g = (size_t)(kt + row) * NKD + kvh * HD + c * 8;
            uint32_t so = row * AT_ROWB + c * 16;
            cp_async16(base + 0 * KV_TILE + so, k16 + g);
            cp_async16(base + 1 * KV_TILE + so, v16 + g);
        }
        asm volatile("cp.async.commit_group;" ::: "memory");
    };

    issue_kv(0, 0);
    asm volatile("cp.async.wait_group 1;" ::: "memory");   // Q done (kv0 may pend)
    __syncthreads();

    // ---- Q fragments (warp owns rows [warp*16, warp*16+16)) ----
    uint32_t qfh[8][4], qfl[8][4];
#pragma unroll
    for (int kf = 0; kf < 8; kf++) {
        uint32_t off = ((warp * 16 + (lane & 15)) * ATP + kf * 16 + ((lane >> 4) << 3)) * 2;
        ldm_x4(qfh[kf], sb + AQ_H + off);
        ldm_x4(qfl[kf], sb + AQ_L + off);
    }

    float o[16][4];
#pragma unroll
    for (int nt = 0; nt < 16; nt++)
#pragma unroll
        for (int i = 0; i < 4; i++) o[nt][i] = 0.f;
    float m0 = -INFINITY, m1 = -INFINITY, l0 = 0.f, l1 = 0.f;

    const int NI = S_LEN / 64;            // 32

    for (int it = 0; it < NI; it++) {
        asm volatile("cp.async.wait_group 0;" ::: "memory");  // kv stage `it` landed
        __syncthreads();   // stage visible; compute(it-1) done block-wide
        if (it + 1 < NI) issue_kv((it + 1) & 1, (it + 1) * 64);

        const uint32_t sk = sb + AKV + (it & 1) * KV_STG;

        // ---- S = Q K^T (2-term: Qh*K + Ql*K), 64 keys = 8 n-tiles ----
        float s[8][4];
#pragma unroll
        for (int nt = 0; nt < 8; nt++)
#pragma unroll
            for (int i = 0; i < 4; i++) s[nt][i] = 0.f;

#pragma unroll
        for (int kf = 0; kf < 8; kf++) {
            uint32_t kb[8][2];
#pragma unroll
            for (int np = 0; np < 4; np++) {
                uint32_t addr = sk +
                    ((np * 16 + ((lane >> 4) << 3) + (lane & 7)) * ATP
                     + kf * 16 + (((lane >> 3) & 1) << 3)) * 2;
                ldm_x4(&kb[np * 2][0], addr);
            }
#pragma unroll
            for (int nt = 0; nt < 8; nt++) {
                mma_f16(s[nt], qfh[kf], kb[nt]);
                mma_f16(s[nt], qfl[kf], kb[nt]);
            }
        }

        // ---- online softmax (base-2; log2e folded into q scale) ----
        float mx0 = -INFINITY, mx1 = -INFINITY;
#pragma unroll
        for (int nt = 0; nt < 8; nt++) {
            mx0 = fmaxf(mx0, fmaxf(s[nt][0], s[nt][1]));
            mx1 = fmaxf(mx1, fmaxf(s[nt][2], s[nt][3]));
        }
        mx0 = fmaxf(mx0, __shfl_xor_sync(0xffffffffu, mx0, 1));
        mx0 = fmaxf(mx0, __shfl_xor_sync(0xffffffffu, mx0, 2));
        mx1 = fmaxf(mx1, __shfl_xor_sync(0xffffffffu, mx1, 1));
        mx1 = fmaxf(mx1, __shfl_xor_sync(0xffffffffu, mx1, 2));

        float nm0 = fmaxf(m0, mx0), nm1 = fmaxf(m1, mx1);
        float c0 = fexp2(m0 - nm0), c1 = fexp2(m1 - nm1);
        m0 = nm0; m1 = nm1;

        float sum0 = 0.f, sum1 = 0.f;
#pragma unroll
        for (int nt = 0; nt < 8; nt++) {
            s[nt][0] = fexp2(s[nt][0] - nm0);
            s[nt][1] = fexp2(s[nt][1] - nm0);
            s[nt][2] = fexp2(s[nt][2] - nm1);
            s[nt][3] = fexp2(s[nt][3] - nm1);
            sum0 += s[nt][0] + s[nt][1];
            sum1 += s[nt][2] + s[nt][3];
        }
        sum0 += __shfl_xor_sync(0xffffffffu, sum0, 1);
        sum0 += __shfl_xor_sync(0xffffffffu, sum0, 2);
        sum1 += __shfl_xor_sync(0xffffffffu, sum1, 1);
        sum1 += __shfl_xor_sync(0xffffffffu, sum1, 2);
        l0 = l0 * c0 + sum0;
        l1 = l1 * c1 + sum1;

#pragma unroll
        for (int nt = 0; nt < 16; nt++) {
            o[nt][0] *= c0; o[nt][1] *= c0;
            o[nt][2] *= c1; o[nt][3] *= c1;
        }

        // ---- O += P V (1-term; P single fp16), 64 keys = kf 0..3 ----
#pragma unroll
        for (int kf = 0; kf < 4; kf++) {
            uint32_t ah[4];
#pragma unroll
            for (int half = 0; half < 2; half++) {
                int nt = 2 * kf + half;
                ah[2 * half]     = pack_h2(s[nt][0], s[nt][1]);
                ah[2 * half + 1] = pack_h2(s[nt][2], s[nt][3]);
            }
#pragma unroll
            for (int np = 0; np < 8; np++) {
                uint32_t vb[4];
                uint32_t addr = sk + KV_TILE +
                    ((kf * 16 + (lane & 15)) * ATP + np * 16 + ((lane >> 4) << 3)) * 2;
                ldm_x4_t(vb, addr);
                mma_f16(o[2 * np],     ah, &vb[0]);
                mma_f16(o[2 * np + 1], ah, &vb[2]);
            }
        }
    }

    // ---- epilogue: ctx as single fp16 ----
    float inv0 = 1.f / l0, inv1 = 1.f / l1;
    int r_lo = r0 + warp * 16 + (lane >> 2);
    int r_hi = r_lo + 8;
#pragma unroll
    for (int nt = 0; nt < 16; nt++) {
        int col = h * HD + nt * 8 + ((lane & 3) << 1);
        *(__half2*)(ctx16 + (size_t)r_lo * NQD + col) =
            __floats2half2_rn(o[nt][0] * inv0, o[nt][1] * inv0);
        *(__half2*)(ctx16 + (size_t)r_hi * NQD + col) =
            __floats2half2_rn(o[nt][2] * inv1, o[nt][3] * inv1);
    }
}

// ---------------- launch ----------------
extern "C" void kernel_launch(void* const* d_in, const int* in_sizes, int n_in,
                              void* d_out, int out_size) {
    const float* hs   = (const float*)d_in[0];
    const float* cosp = (const float*)d_in[1];
    const float* sinp = (const float*)d_in[2];
    const float* Wq   = (const float*)d_in[3];
    const float* bq   = (const float*)d_in[4];
    const float* Wk   = (const float*)d_in[5];
    const float* bk   = (const float*)d_in[6];
    const float* Wv   = (const float*)d_in[7];
    const float* bv   = (const float*)d_in[8];
    const float* Wo   = (const float*)d_in[9];
    float* out = (float*)d_out;

    float *qkv_p, *bias_p;
    cudaGetSymbolAddress((void**)&qkv_p,  g_qkv);
    cudaGetSymbolAddress((void**)&bias_p, g_bias);

    __half *hs16, *w16, *wo16, *ctx16, *q16h, *q16l, *k16, *v16;
    cudaGetSymbolAddress((void**)&hs16,  g_hs16);
    cudaGetSymbolAddress((void**)&ctx16, g_ctx16);
    cudaGetSymbolAddress((void**)&w16,   g_w16);  cudaGetSymbolAddress((void**)&wo16, g_wo16);
    cudaGetSymbolAddress((void**)&q16h,  g_q16h); cudaGetSymbolAddress((void**)&q16l, g_q16l);
    cudaGetSymbolAddress((void**)&k16,   g_k16);  cudaGetSymbolAddress((void**)&v16,  g_v16);

    cudaFuncSetAttribute(gemm_f16_1t, cudaFuncAttributeMaxDynamicSharedMemorySize, GEMM1_SMEM);
    cudaFuncSetAttribute(attn_mma,    cudaFuncAttributeMaxDynamicSharedMemorySize, ATTN_SMEM);

    // 1) input convert + weight transposes (all fp16) + bias concat
    {
        int n4 = S_LEN * HID / 4;
        conv_h_kernel<<<(n4 + 255) / 256, 256>>>((const float4*)hs, (__half2*)hs16, n4);
    }
    {
        dim3 blk(32, 8);
        tsplit2h_kernel<<<dim3(NQD / 32, HID / 64), blk>>>(Wq, w16, HID, NQD);
        tsplit2h_kernel<<<dim3(NKD / 32, HID / 64), blk>>>(Wk, w16 + (size_t)NQD * HID, HID, NKD);
        tsplit2h_kernel<<<dim3(NKD / 32, HID / 64), blk>>>(Wv, w16 + (size_t)(NQD + NKD) * HID, HID, NKD);
        tsplit2h_kernel<<<dim3(HID / 32, NQD / 64), blk>>>(Wo, wo16, NQD, HID);
        concat_bias_kernel<<<(NQKV + 255) / 256, 256>>>(bq, bk, bv, bias_p);
    }

    // 2) fused QKV projection (fp16 1-term)
    gemm_f16_1t<<<dim3(NQKV / 128, S_LEN / 128), 256, GEMM1_SMEM>>>(hs16, w16, bias_p, qkv_p, HID, NQKV);

    // 3) fused mROPE + fp16 split (q hi/lo scaled with log2e folded; k,v single)
    rope_split_kernel<<<S_LEN, 256>>>(qkv_p, cosp, sinp, q16h, q16l, k16, v16);

    // 4) attention -> ctx (single fp16)
    {
        dim3 grid(S_LEN / 128, NH);
        attn_mma<<<grid, 256, ATTN_SMEM>>>(q16h, q16l, k16, v16, ctx16);
    }

    // 5) output projection (fp16 1-term)
    gemm_f16_1t<<<dim3(HID / 128, S_LEN / 128), 256, GEMM1_SMEM>>>(ctx16, wo16, nullptr, out, NQD, HID);
}